// round 1
// baseline (speedup 1.0000x reference)
#include <cuda_runtime.h>
#include <cuda_bf16.h>
#include <math.h>

// ---------------- problem constants ----------------
#define BATCH 32
#define EPS 1e-5f

// ---------------- scratch (device globals; no allocs allowed) ----------------
__device__ float g_buf1[BATCH*32*160*160];   // conv1 out
__device__ float g_buf2[BATCH*32*80*80];     // region+relu+pool+bn out
__device__ float g_buf3[BATCH*16*73*73];     // conv2 out
__device__ float g_buf4[BATCH*16*66*66];     // conv3 out
__device__ float g_buf5[BATCH*16*31*31];     // conv4 out
__device__ float g_buf6[BATCH*16*27*27];     // conv5 out (== fc1 input, flattened)
__device__ float g_part[8*32*4096];          // fc partial sums (max: fc1, 8 ktiles)
__device__ float g_fc1[BATCH*4096];
__device__ float g_fc2[BATCH*2048];

// =====================================================================
// conv1: [32,3,170,170] -> [32,32,160,160], 11x11, pad 0, stride 1
// block (16,8): each thread does 2 output rows (ty, ty+8) x all 32 oc
// =====================================================================
__global__ void __launch_bounds__(128) conv1_kernel(
    const float* __restrict__ x, const float* __restrict__ w,
    const float* __restrict__ bias, float* __restrict__ out)
{
    __shared__ float ws[363*32];     // [c*121+kh*11+kw][oc]
    __shared__ float bs[32];
    const int tx = threadIdx.x, ty = threadIdx.y;
    const int tid = ty*16 + tx;
    for (int i = tid; i < 363*32; i += 128) {
        int ckk = i >> 5, oc = i & 31;
        ws[i] = w[oc*363 + ckk];
    }
    if (tid < 32) bs[tid] = bias[tid];
    __syncthreads();

    const int b   = blockIdx.z;
    const int ox  = blockIdx.x*16 + tx;
    const int oy0 = blockIdx.y*16 + ty;        // rows oy0 and oy0+8

    float acc0[32], acc1[32];
#pragma unroll
    for (int oc = 0; oc < 32; oc++) { acc0[oc] = bs[oc]; acc1[oc] = bs[oc]; }

    const float* xb = x + (size_t)b*3*170*170;
    for (int c = 0; c < 3; c++) {
        for (int kh = 0; kh < 11; kh++) {
            const float* xr0 = xb + ((size_t)c*170 + oy0 + kh)*170 + ox;
            const float* xr1 = xr0 + 8*170;
            const float* wrow = &ws[(c*121 + kh*11)*32];
#pragma unroll
            for (int kw = 0; kw < 11; kw++) {
                float v0 = __ldg(xr0 + kw);
                float v1 = __ldg(xr1 + kw);
                const float4* wp = (const float4*)(wrow + kw*32);
#pragma unroll
                for (int q = 0; q < 8; q++) {
                    float4 wv = wp[q];
                    acc0[q*4+0] = fmaf(wv.x, v0, acc0[q*4+0]);
                    acc0[q*4+1] = fmaf(wv.y, v0, acc0[q*4+1]);
                    acc0[q*4+2] = fmaf(wv.z, v0, acc0[q*4+2]);
                    acc0[q*4+3] = fmaf(wv.w, v0, acc0[q*4+3]);
                    acc1[q*4+0] = fmaf(wv.x, v1, acc1[q*4+0]);
                    acc1[q*4+1] = fmaf(wv.y, v1, acc1[q*4+1]);
                    acc1[q*4+2] = fmaf(wv.z, v1, acc1[q*4+2]);
                    acc1[q*4+3] = fmaf(wv.w, v1, acc1[q*4+3]);
                }
            }
        }
    }
#pragma unroll
    for (int oc = 0; oc < 32; oc++) {
        out[(((size_t)b*32 + oc)*160 + oy0    )*160 + ox] = acc0[oc];
        out[(((size_t)b*32 + oc)*160 + oy0 + 8)*160 + ox] = acc1[oc];
    }
}

// =====================================================================
// Region layer fused: per (batch, patch 20x20):
//   act = relu(bn_k(x)); conv3x3(act)+x; relu; maxpool2x2; bn2 -> [b,32,80,80]
//   k = gj*(gi+1)  (faithful to reference's i*j+j indexing)
// dyn smem: act[32][22][22] (zero-padded) + ws[32][32*9]
// =====================================================================
__global__ void __launch_bounds__(256) region_kernel(
    const float* __restrict__ in,      // g_buf1
    const float* __restrict__ rl_gamma, const float* __restrict__ rl_beta,
    const float* __restrict__ rl_mean,  const float* __restrict__ rl_var,
    const float* __restrict__ rl_cw,    const float* __restrict__ rl_cb,
    const float* __restrict__ bn_g, const float* __restrict__ bn_b,
    const float* __restrict__ bn_m, const float* __restrict__ bn_v,
    float* __restrict__ out)           // g_buf2
{
    extern __shared__ float sm[];
    float* act = sm;                   // 32*484 = 15488
    float* ws  = sm + 15488;           // 32*288 = 9216
    __shared__ float sc[32], sh[32], s2[32], t2[32], cb[32];

    const int blk = blockIdx.x;
    const int b = blk >> 6;
    const int patch = blk & 63;
    const int gi = patch >> 3, gj = patch & 7;
    const int k = gj*(gi+1);
    const int tid = threadIdx.x;

    if (tid < 32) {
        float g = rl_gamma[k*32+tid];
        float v = rl_var[k*32+tid];
        float s = g * rsqrtf(v + EPS);
        sc[tid] = s;
        sh[tid] = rl_beta[k*32+tid] - rl_mean[k*32+tid]*s;
        float gg = bn_g[tid];
        float ss = gg * rsqrtf(bn_v[tid] + EPS);
        s2[tid] = ss;
        t2[tid] = bn_b[tid] - bn_m[tid]*ss;
        cb[tid] = rl_cb[k*32+tid];
    }
    for (int i = tid; i < 15488; i += 256) act[i] = 0.f;
    __syncthreads();

    // fill interior: act[ic][y+1][x+1] = relu(bn(x))
    const float* inb = in + (size_t)b*32*160*160;
    for (int i = tid; i < 32*400; i += 256) {
        int ic = i / 400, r = i - ic*400;
        int y = r / 20, xx = r - y*20;
        float v = inb[((size_t)ic*160 + gi*20 + y)*160 + gj*20 + xx];
        float a = fmaf(v, sc[ic], sh[ic]);
        act[ic*484 + (y+1)*22 + (xx+1)] = fmaxf(a, 0.f);
    }
    for (int i = tid; i < 9216; i += 256) ws[i] = rl_cw[(size_t)k*9216 + i];
    __syncthreads();

    // 1600 items = 16 oc-pairs x 100 pooled positions
    for (int item = tid; item < 1600; item += 256) {
        int p = item / 100, pos = item - p*100;
        int oc0 = p*2;
        int py = pos / 10, px = pos - py*10;
        int yb = 2*py, xb = 2*px;

        float a0[4] = {cb[oc0],cb[oc0],cb[oc0],cb[oc0]};
        float a1[4] = {cb[oc0+1],cb[oc0+1],cb[oc0+1],cb[oc0+1]};

        for (int ic = 0; ic < 32; ic++) {
            float a[4][4];
#pragma unroll
            for (int dy = 0; dy < 4; dy++) {
                const float2* rp = (const float2*)&act[ic*484 + (yb+dy)*22 + xb];
                float2 v0 = rp[0], v1 = rp[1];
                a[dy][0]=v0.x; a[dy][1]=v0.y; a[dy][2]=v1.x; a[dy][3]=v1.y;
            }
            const float* w0 = &ws[oc0*288 + ic*9];
            const float* w1 = w0 + 288;
#pragma unroll
            for (int ky = 0; ky < 3; ky++) {
#pragma unroll
                for (int kx = 0; kx < 3; kx++) {
                    float wv0 = w0[ky*3+kx], wv1 = w1[ky*3+kx];
                    float e00 = a[ky][kx],   e01 = a[ky][kx+1];
                    float e10 = a[ky+1][kx], e11 = a[ky+1][kx+1];
                    a0[0]=fmaf(wv0,e00,a0[0]); a0[1]=fmaf(wv0,e01,a0[1]);
                    a0[2]=fmaf(wv0,e10,a0[2]); a0[3]=fmaf(wv0,e11,a0[3]);
                    a1[0]=fmaf(wv1,e00,a1[0]); a1[1]=fmaf(wv1,e01,a1[1]);
                    a1[2]=fmaf(wv1,e10,a1[2]); a1[3]=fmaf(wv1,e11,a1[3]);
                }
            }
        }
        // residual + relu + pool + bn2
#pragma unroll
        for (int o = 0; o < 2; o++) {
            int oc = oc0 + o;
            const float* xrb = inb + ((size_t)oc*160 + gi*20)*160 + gj*20;
            float* accp = o ? a1 : a0;
            float mx = -3.4e38f;
#pragma unroll
            for (int q = 0; q < 4; q++) {
                int oy = yb + (q>>1), ox = xb + (q&1);
                float raw = xrb[(size_t)oy*160 + ox];
                float v = fmaxf(accp[q] + raw, 0.f);
                mx = fmaxf(mx, v);
            }
            float r = fmaf(mx, s2[oc], t2[oc]);
            out[(((size_t)b*32 + oc)*80 + gi*10 + py)*80 + gj*10 + px] = r;
        }
    }
}

// =====================================================================
// generic direct conv (conv2..conv5): relu epilogue
// block (16,8): 2 rows per thread, all COUT channels
// =====================================================================
template<int CIN, int COUT, int KS, int STRIDE, int HIN, int WIN,
         int HOUT, int WOUT, int ICC>
__global__ void __launch_bounds__(128) conv_kernel(
    const float* __restrict__ in, const float* __restrict__ w,
    const float* __restrict__ bias, float* __restrict__ out)
{
    constexpr int TIN = 15*STRIDE + KS;
    __shared__ float xs[ICC*TIN*TIN];
    __shared__ float ws[ICC*KS*KS*COUT];
    __shared__ float bs[COUT];

    const int tx = threadIdx.x, ty = threadIdx.y;
    const int tid = ty*16 + tx;
    const int b = blockIdx.z;
    const int oy0 = blockIdx.y*16 + ty;
    const int ox  = blockIdx.x*16 + tx;
    const int iy0 = blockIdx.y*16*STRIDE;
    const int ix0 = blockIdx.x*16*STRIDE;

    if (tid < COUT) bs[tid] = bias[tid];
    __syncthreads();

    float acc0[COUT], acc1[COUT];
#pragma unroll
    for (int oc = 0; oc < COUT; oc++) { acc0[oc] = bs[oc]; acc1[oc] = bs[oc]; }

    for (int cc = 0; cc < CIN; cc += ICC) {
        __syncthreads();
        for (int i = tid; i < ICC*TIN*TIN; i += 128) {
            int icl = i / (TIN*TIN), r = i - icl*(TIN*TIN);
            int yy = r / TIN, xx = r - yy*TIN;
            int gy = iy0 + yy, gx = ix0 + xx;
            float v = 0.f;
            if (gy < HIN && gx < WIN)
                v = in[(((size_t)b*CIN + cc + icl)*HIN + gy)*WIN + gx];
            xs[i] = v;
        }
        for (int i = tid; i < ICC*KS*KS*COUT; i += 128) {
            int oc = i % COUT; int r = i / COUT;
            int icl = r / (KS*KS); int kk = r - icl*(KS*KS);
            ws[i] = w[((size_t)oc*CIN + cc + icl)*KS*KS + kk];
        }
        __syncthreads();
#pragma unroll 1
        for (int icl = 0; icl < ICC; icl++) {
            for (int kh = 0; kh < KS; kh++) {
                const float* x0 = &xs[icl*TIN*TIN + (ty*STRIDE + kh)*TIN + tx*STRIDE];
                const float* x1 = &xs[icl*TIN*TIN + ((ty+8)*STRIDE + kh)*TIN + tx*STRIDE];
                const float* wrow = &ws[(icl*KS*KS + kh*KS)*COUT];
#pragma unroll
                for (int kw = 0; kw < KS; kw++) {
                    float v0 = x0[kw];
                    float v1 = x1[kw];
                    const float4* wp = (const float4*)(wrow + kw*COUT);
#pragma unroll
                    for (int q = 0; q < COUT/4; q++) {
                        float4 wv = wp[q];
                        acc0[q*4+0]=fmaf(wv.x,v0,acc0[q*4+0]);
                        acc0[q*4+1]=fmaf(wv.y,v0,acc0[q*4+1]);
                        acc0[q*4+2]=fmaf(wv.z,v0,acc0[q*4+2]);
                        acc0[q*4+3]=fmaf(wv.w,v0,acc0[q*4+3]);
                        acc1[q*4+0]=fmaf(wv.x,v1,acc1[q*4+0]);
                        acc1[q*4+1]=fmaf(wv.y,v1,acc1[q*4+1]);
                        acc1[q*4+2]=fmaf(wv.z,v1,acc1[q*4+2]);
                        acc1[q*4+3]=fmaf(wv.w,v1,acc1[q*4+3]);
                    }
                }
            }
        }
    }
    if (ox < WOUT) {
#pragma unroll
        for (int oc = 0; oc < COUT; oc++) {
            if (oy0 < HOUT)
                out[(((size_t)b*COUT + oc)*HOUT + oy0)*WOUT + ox] = fmaxf(acc0[oc], 0.f);
            if (oy0 + 8 < HOUT)
                out[(((size_t)b*COUT + oc)*HOUT + oy0 + 8)*WOUT + ox] = fmaxf(acc1[oc], 0.f);
        }
    }
}

// =====================================================================
// fc partial: out[m][n] partial over K-tile. grid(N/256, KT), block 128,
// each thread owns 2 n-columns, all 32 m rows.
// =====================================================================
#define FC_CHUNK 160
__global__ void __launch_bounds__(128) fc_partial(
    const float* __restrict__ x, const float* __restrict__ w,
    float* __restrict__ part, int N, int K, int ktlen)
{
    __shared__ float xs[32*FC_CHUNK];
    const int tid = threadIdx.x;
    const int n0 = blockIdx.x*256 + tid;
    const int n1 = n0 + 128;
    const int k0 = blockIdx.y*ktlen;

    float acc0[32], acc1[32];
#pragma unroll
    for (int m = 0; m < 32; m++) { acc0[m]=0.f; acc1[m]=0.f; }

    for (int kc = 0; kc < ktlen; kc += FC_CHUNK) {
        int cl = min(FC_CHUNK, ktlen - kc);
        __syncthreads();
        for (int i = tid; i < 32*cl; i += 128) {
            int m = i / cl, kk = i - m*cl;
            xs[m*FC_CHUNK + kk] = x[(size_t)m*K + k0 + kc + kk];
        }
        __syncthreads();
        const float* w0 = w + (size_t)n0*K + k0 + kc;
        const float* w1 = w + (size_t)n1*K + k0 + kc;
        for (int kk = 0; kk < cl; kk += 2) {
            float2 a0 = *(const float2*)(w0 + kk);
            float2 a1 = *(const float2*)(w1 + kk);
#pragma unroll
            for (int m = 0; m < 32; m++) {
                float2 xv = *(const float2*)&xs[m*FC_CHUNK + kk];
                acc0[m] = fmaf(a0.x, xv.x, fmaf(a0.y, xv.y, acc0[m]));
                acc1[m] = fmaf(a1.x, xv.x, fmaf(a1.y, xv.y, acc1[m]));
            }
        }
    }
    float* pr = part + (size_t)blockIdx.y*32*N;
#pragma unroll
    for (int m = 0; m < 32; m++) {
        pr[(size_t)m*N + n0] = acc0[m];
        pr[(size_t)m*N + n1] = acc1[m];
    }
}

__global__ void fc_reduce(const float* __restrict__ part,
                          const float* __restrict__ bias,
                          float* __restrict__ out, int N, int KT, int do_relu)
{
    int i = blockIdx.x*256 + threadIdx.x;
    if (i >= 32*N) return;
    int n = i % N;
    float s = bias[n];
    for (int kt = 0; kt < KT; kt++) s += part[(size_t)kt*32*N + i];
    out[i] = do_relu ? fmaxf(s, 0.f) : s;
}

// =====================================================================
// fc3 (2048 -> 24) + log_softmax over the 2-way axis. 1 block per batch,
// 24 warps = 24 logits.
// =====================================================================
__global__ void __launch_bounds__(768) fc3_softmax(
    const float* __restrict__ x, const float* __restrict__ w,
    const float* __restrict__ bias, float* __restrict__ out)
{
    __shared__ float lg[24];
    const int b = blockIdx.x;
    const int tid = threadIdx.x;
    const int wo = tid >> 5, lane = tid & 31;

    const float* xr = x + (size_t)b*2048;
    const float* wr = w + (size_t)wo*2048;
    float s = 0.f;
    for (int k = lane; k < 2048; k += 32) s = fmaf(wr[k], xr[k], s);
#pragma unroll
    for (int off = 16; off; off >>= 1) s += __shfl_xor_sync(0xffffffffu, s, off);
    if (lane == 0) lg[wo] = s + bias[wo];
    __syncthreads();

    if (tid < 24) {
        int a = tid % 12;
        float z0 = lg[a], z1 = lg[12 + a];
        float m = fmaxf(z0, z1);
        float lse = m + logf(expf(z0 - m) + expf(z1 - m));
        out[b*24 + tid] = lg[tid] - lse;
    }
}

// =====================================================================
// launch
// =====================================================================
extern "C" void kernel_launch(void* const* d_in, const int* in_sizes, int n_in,
                              void* d_out, int out_size)
{
    const float* x        = (const float*)d_in[0];
    const float* conv1_w  = (const float*)d_in[1];
    const float* conv1_b  = (const float*)d_in[2];
    const float* rl_gamma = (const float*)d_in[3];
    const float* rl_beta  = (const float*)d_in[4];
    const float* rl_mean  = (const float*)d_in[5];
    const float* rl_var   = (const float*)d_in[6];
    const float* rl_cw    = (const float*)d_in[7];
    const float* rl_cb    = (const float*)d_in[8];
    const float* bn_gamma = (const float*)d_in[9];
    const float* bn_beta  = (const float*)d_in[10];
    const float* bn_mean  = (const float*)d_in[11];
    const float* bn_var   = (const float*)d_in[12];
    const float* conv2_w  = (const float*)d_in[13];
    const float* conv2_b  = (const float*)d_in[14];
    const float* conv3_w  = (const float*)d_in[15];
    const float* conv3_b  = (const float*)d_in[16];
    const float* conv4_w  = (const float*)d_in[17];
    const float* conv4_b  = (const float*)d_in[18];
    const float* conv5_w  = (const float*)d_in[19];
    const float* conv5_b  = (const float*)d_in[20];
    const float* fc1_w    = (const float*)d_in[21];
    const float* fc1_b    = (const float*)d_in[22];
    const float* fc2_w    = (const float*)d_in[23];
    const float* fc2_b    = (const float*)d_in[24];
    const float* fc3_w    = (const float*)d_in[25];
    const float* fc3_b    = (const float*)d_in[26];
    float* out = (float*)d_out;

    float *b1,*b2,*b3,*b4,*b5,*b6,*pt,*f1,*f2;
    cudaGetSymbolAddress((void**)&b1, g_buf1);
    cudaGetSymbolAddress((void**)&b2, g_buf2);
    cudaGetSymbolAddress((void**)&b3, g_buf3);
    cudaGetSymbolAddress((void**)&b4, g_buf4);
    cudaGetSymbolAddress((void**)&b5, g_buf5);
    cudaGetSymbolAddress((void**)&b6, g_buf6);
    cudaGetSymbolAddress((void**)&pt, g_part);
    cudaGetSymbolAddress((void**)&f1, g_fc1);
    cudaGetSymbolAddress((void**)&f2, g_fc2);

    // region kernel needs ~99 KB dynamic smem
    const int region_smem = (15488 + 9216) * 4;
    cudaFuncSetAttribute(region_kernel,
                         cudaFuncAttributeMaxDynamicSharedMemorySize, region_smem);

    // 1. conv1
    conv1_kernel<<<dim3(10,10,BATCH), dim3(16,8)>>>(x, conv1_w, conv1_b, b1);

    // 2. region + relu + maxpool + bn
    region_kernel<<<BATCH*64, 256, region_smem>>>(
        b1, rl_gamma, rl_beta, rl_mean, rl_var, rl_cw, rl_cb,
        bn_gamma, bn_beta, bn_mean, bn_var, b2);

    // 3. conv2: 32->16, 8x8, 80->73
    conv_kernel<32,16,8,1,80,80,73,73,4><<<dim3(5,5,BATCH), dim3(16,8)>>>(
        b2, conv2_w, conv2_b, b3);

    // 4. conv3: 16->16, 8x8, 73->66
    conv_kernel<16,16,8,1,73,73,66,66,4><<<dim3(5,5,BATCH), dim3(16,8)>>>(
        b3, conv3_w, conv3_b, b4);

    // 5. conv4: 16->16, 6x6 stride 2, 66->31
    conv_kernel<16,16,6,2,66,66,31,31,4><<<dim3(2,2,BATCH), dim3(16,8)>>>(
        b4, conv4_w, conv4_b, b5);

    // 6. conv5: 16->16, 5x5, 31->27
    conv_kernel<16,16,5,1,31,31,27,27,8><<<dim3(2,2,BATCH), dim3(16,8)>>>(
        b5, conv5_w, conv5_b, b6);

    // 7. fc1: 11664 -> 4096 (+relu), K split into 8 tiles
    fc_partial<<<dim3(16,8), 128>>>(b6, fc1_w, pt, 4096, 11664, 1458);
    fc_reduce<<<512, 256>>>(pt, fc1_b, f1, 4096, 8, 1);

    // 8. fc2: 4096 -> 2048 (+relu)
    fc_partial<<<dim3(8,8), 128>>>(f1, fc2_w, pt, 2048, 4096, 512);
    fc_reduce<<<256, 256>>>(pt, fc2_b, f2, 2048, 8, 1);

    // 9. fc3 + log_softmax
    fc3_softmax<<<BATCH, 768>>>(f2, fc3_w, fc3_b, out);
}

// round 2
// speedup vs baseline: 1.1673x; 1.1673x over previous
#include <cuda_runtime.h>
#include <cuda_bf16.h>
#include <math.h>

#define BATCH 32
#define EPS 1e-5f

// ---------------- scratch ----------------
__device__ float g_buf1[BATCH*32*160*160];
__device__ float g_buf2[BATCH*32*80*80];
__device__ float g_buf3[BATCH*16*73*73];
__device__ float g_buf4[BATCH*16*66*66];
__device__ float g_buf5[BATCH*16*31*31];
__device__ float g_buf6[BATCH*16*27*27];
__device__ float g_part[8*32*4096];
__device__ float g_fc1[BATCH*4096];
__device__ float g_fc2[BATCH*2048];

// =====================================================================
// conv1: [32,3,170,170] -> [32,32,160,160], 11x11
// block (16,8); out tile 32x16; each thread: 2x2 pixels x 16 oc
// grid z = batch*2 (oc half)
// =====================================================================
__global__ void __launch_bounds__(128) conv1_kernel(
    const float* __restrict__ x, const float* __restrict__ w,
    const float* __restrict__ bias, float* __restrict__ out)
{
    __shared__ float xs[3*26*42];      // [c][26][42]
    __shared__ float ws[363*16];       // [ckk][oc16]
    __shared__ float bs[16];
    const int tx = threadIdx.x, ty = threadIdx.y;
    const int tid = ty*16 + tx;
    const int z = blockIdx.z;
    const int b = z >> 1, half = z & 1;

    for (int i = tid; i < 363*16; i += 128) {
        int ckk = i >> 4, oc = i & 15;
        ws[i] = w[(half*16 + oc)*363 + ckk];
    }
    if (tid < 16) bs[tid] = bias[half*16 + tid];

    const int ix0 = blockIdx.x*32;
    const int iy0 = blockIdx.y*16;
    const float* xb = x + (size_t)b*3*170*170;
    for (int i = tid; i < 3*26*42; i += 128) {
        int c = i / (26*42), r = i - c*(26*42);
        int yy = r / 42, xx = r - yy*42;
        xs[i] = xb[((size_t)c*170 + iy0 + yy)*170 + ix0 + xx];
    }
    __syncthreads();

    float a00[16], a01[16], a10[16], a11[16];
#pragma unroll
    for (int q = 0; q < 16; q++) { a00[q]=bs[q]; a01[q]=bs[q]; a10[q]=bs[q]; a11[q]=bs[q]; }

    for (int c = 0; c < 3; c++) {
        for (int kh = 0; kh < 11; kh++) {
            const float* x0 = &xs[c*26*42 + (ty+kh)*42 + tx];
            const float* x1 = x0 + 8*42;
            const float* wrow = &ws[(c*121 + kh*11)*16];
#pragma unroll
            for (int kw = 0; kw < 11; kw++) {
                float v00 = x0[kw], v01 = x0[16+kw];
                float v10 = x1[kw], v11 = x1[16+kw];
                const float4* wp = (const float4*)(wrow + kw*16);
#pragma unroll
                for (int q = 0; q < 4; q++) {
                    float4 wv = wp[q];
                    a00[q*4+0]=fmaf(wv.x,v00,a00[q*4+0]); a00[q*4+1]=fmaf(wv.y,v00,a00[q*4+1]);
                    a00[q*4+2]=fmaf(wv.z,v00,a00[q*4+2]); a00[q*4+3]=fmaf(wv.w,v00,a00[q*4+3]);
                    a01[q*4+0]=fmaf(wv.x,v01,a01[q*4+0]); a01[q*4+1]=fmaf(wv.y,v01,a01[q*4+1]);
                    a01[q*4+2]=fmaf(wv.z,v01,a01[q*4+2]); a01[q*4+3]=fmaf(wv.w,v01,a01[q*4+3]);
                    a10[q*4+0]=fmaf(wv.x,v10,a10[q*4+0]); a10[q*4+1]=fmaf(wv.y,v10,a10[q*4+1]);
                    a10[q*4+2]=fmaf(wv.z,v10,a10[q*4+2]); a10[q*4+3]=fmaf(wv.w,v10,a10[q*4+3]);
                    a11[q*4+0]=fmaf(wv.x,v11,a11[q*4+0]); a11[q*4+1]=fmaf(wv.y,v11,a11[q*4+1]);
                    a11[q*4+2]=fmaf(wv.z,v11,a11[q*4+2]); a11[q*4+3]=fmaf(wv.w,v11,a11[q*4+3]);
                }
            }
        }
    }
    const int ox = ix0 + tx, oy = iy0 + ty;
#pragma unroll
    for (int q = 0; q < 16; q++) {
        int oc = half*16 + q;
        float* op = out + (((size_t)b*32 + oc)*160 + oy)*160 + ox;
        op[0] = a00[q]; op[16] = a01[q];
        op[8*160] = a10[q]; op[8*160+16] = a11[q];
    }
}

// =====================================================================
// Region layer fused (BN1+relu+3x3conv+res+relu+pool+BN2)
// item = 4-oc group x pooled pos; weights transposed [ic*9+k][oc] pad 36
// =====================================================================
__global__ void __launch_bounds__(256) region_kernel(
    const float* __restrict__ in,
    const float* __restrict__ rl_gamma, const float* __restrict__ rl_beta,
    const float* __restrict__ rl_mean,  const float* __restrict__ rl_var,
    const float* __restrict__ rl_cw,    const float* __restrict__ rl_cb,
    const float* __restrict__ bn_g, const float* __restrict__ bn_b,
    const float* __restrict__ bn_m, const float* __restrict__ bn_v,
    float* __restrict__ out)
{
    extern __shared__ float sm[];
    float* act = sm;                   // 32*484 = 15488
    float* wsT = sm + 15488;           // 288*36 = 10368
    __shared__ float sc[32], sh[32], s2[32], t2[32], cb[32];

    const int blk = blockIdx.x;
    const int b = blk >> 6;
    const int patch = blk & 63;
    const int gi = patch >> 3, gj = patch & 7;
    const int k = gj*(gi+1);
    const int tid = threadIdx.x;

    if (tid < 32) {
        float g = rl_gamma[k*32+tid];
        float s = g * rsqrtf(rl_var[k*32+tid] + EPS);
        sc[tid] = s;
        sh[tid] = rl_beta[k*32+tid] - rl_mean[k*32+tid]*s;
        float ss = bn_g[tid] * rsqrtf(bn_v[tid] + EPS);
        s2[tid] = ss;
        t2[tid] = bn_b[tid] - bn_m[tid]*ss;
        cb[tid] = rl_cb[k*32+tid];
    }
    for (int i = tid; i < 15488; i += 256) act[i] = 0.f;
    __syncthreads();

    const float* inb = in + (size_t)b*32*160*160;
    for (int i = tid; i < 32*400; i += 256) {
        int ic = i / 400, r = i - ic*400;
        int y = r / 20, xx = r - y*20;
        float v = inb[((size_t)ic*160 + gi*20 + y)*160 + gj*20 + xx];
        act[ic*484 + (y+1)*22 + (xx+1)] = fmaxf(fmaf(v, sc[ic], sh[ic]), 0.f);
    }
    // transposed weight fill: wsT[(ic*9+kk)*36 + oc]
    for (int i = tid; i < 9216; i += 256) {
        int oc = i / 288, r = i - oc*288;
        wsT[r*36 + oc] = rl_cw[(size_t)k*9216 + i];
    }
    __syncthreads();

    // 800 items = 8 oc-quads x 100 pooled positions
    for (int item = tid; item < 800; item += 256) {
        int ocq = item / 100, pos = item - ocq*100;
        int oc0 = ocq*4;
        int py = pos / 10, px = pos - py*10;
        int yb = 2*py, xb = 2*px;

        float acc[4][4];
#pragma unroll
        for (int o = 0; o < 4; o++) {
            float bv = cb[oc0+o];
            acc[o][0]=bv; acc[o][1]=bv; acc[o][2]=bv; acc[o][3]=bv;
        }

        for (int ic = 0; ic < 32; ic++) {
            float a[4][4];
#pragma unroll
            for (int dy = 0; dy < 4; dy++) {
                const float2* rp = (const float2*)&act[ic*484 + (yb+dy)*22 + xb];
                float2 v0 = rp[0], v1 = rp[1];
                a[dy][0]=v0.x; a[dy][1]=v0.y; a[dy][2]=v1.x; a[dy][3]=v1.y;
            }
            const float* wr = &wsT[(ic*9)*36 + oc0];
#pragma unroll
            for (int kk = 0; kk < 9; kk++) {
                int ky = kk/3, kx = kk - ky*3;
                float4 wv = *(const float4*)(wr + kk*36);
                float e00 = a[ky][kx],   e01 = a[ky][kx+1];
                float e10 = a[ky+1][kx], e11 = a[ky+1][kx+1];
                acc[0][0]=fmaf(wv.x,e00,acc[0][0]); acc[0][1]=fmaf(wv.x,e01,acc[0][1]);
                acc[0][2]=fmaf(wv.x,e10,acc[0][2]); acc[0][3]=fmaf(wv.x,e11,acc[0][3]);
                acc[1][0]=fmaf(wv.y,e00,acc[1][0]); acc[1][1]=fmaf(wv.y,e01,acc[1][1]);
                acc[1][2]=fmaf(wv.y,e10,acc[1][2]); acc[1][3]=fmaf(wv.y,e11,acc[1][3]);
                acc[2][0]=fmaf(wv.z,e00,acc[2][0]); acc[2][1]=fmaf(wv.z,e01,acc[2][1]);
                acc[2][2]=fmaf(wv.z,e10,acc[2][2]); acc[2][3]=fmaf(wv.z,e11,acc[2][3]);
                acc[3][0]=fmaf(wv.w,e00,acc[3][0]); acc[3][1]=fmaf(wv.w,e01,acc[3][1]);
                acc[3][2]=fmaf(wv.w,e10,acc[3][2]); acc[3][3]=fmaf(wv.w,e11,acc[3][3]);
            }
        }
#pragma unroll
        for (int o = 0; o < 4; o++) {
            int oc = oc0 + o;
            const float* xrb = inb + ((size_t)oc*160 + gi*20 + yb)*160 + gj*20 + xb;
            float v0 = fmaxf(acc[o][0] + xrb[0], 0.f);
            float v1 = fmaxf(acc[o][1] + xrb[1], 0.f);
            float v2 = fmaxf(acc[o][2] + xrb[160], 0.f);
            float v3 = fmaxf(acc[o][3] + xrb[161], 0.f);
            float mx = fmaxf(fmaxf(v0, v1), fmaxf(v2, v3));
            out[(((size_t)b*32 + oc)*80 + gi*10 + py)*80 + gj*10 + px] =
                fmaf(mx, s2[oc], t2[oc]);
        }
    }
}

// =====================================================================
// conv2/conv3: 2x2 pixels per thread, 32x16 output tile, COUT=16
// =====================================================================
template<int CIN, int KS, int HIN, int WIN, int HOUT, int WOUT, int ICC>
__global__ void __launch_bounds__(128) conv_kernel2(
    const float* __restrict__ in, const float* __restrict__ w,
    const float* __restrict__ bias, float* __restrict__ out)
{
    constexpr int TIW = 32 + KS - 1;
    constexpr int TIH = 16 + KS - 1;
    __shared__ float xs[ICC*TIH*TIW];
    __shared__ float ws[ICC*KS*KS*16];
    __shared__ float bs[16];

    const int tx = threadIdx.x, ty = threadIdx.y;
    const int tid = ty*16 + tx;
    const int b = blockIdx.z;
    const int ix0 = blockIdx.x*32, iy0 = blockIdx.y*16;

    if (tid < 16) bs[tid] = bias[tid];
    __syncthreads();

    float a00[16], a01[16], a10[16], a11[16];
#pragma unroll
    for (int q = 0; q < 16; q++) { a00[q]=bs[q]; a01[q]=bs[q]; a10[q]=bs[q]; a11[q]=bs[q]; }

    for (int cc = 0; cc < CIN; cc += ICC) {
        __syncthreads();
        for (int i = tid; i < ICC*TIH*TIW; i += 128) {
            int icl = i / (TIH*TIW), r = i - icl*(TIH*TIW);
            int yy = r / TIW, xx = r - yy*TIW;
            int gy = iy0 + yy, gx = ix0 + xx;
            float v = 0.f;
            if (gy < HIN && gx < WIN)
                v = in[(((size_t)b*CIN + cc + icl)*HIN + gy)*WIN + gx];
            xs[i] = v;
        }
        for (int i = tid; i < ICC*KS*KS*16; i += 128) {
            int oc = i & 15, r = i >> 4;
            int icl = r / (KS*KS), kk = r - icl*(KS*KS);
            ws[i] = w[((size_t)oc*CIN + cc + icl)*KS*KS + kk];
        }
        __syncthreads();
#pragma unroll 1
        for (int icl = 0; icl < ICC; icl++) {
            for (int kh = 0; kh < KS; kh++) {
                const float* x0 = &xs[icl*TIH*TIW + (ty+kh)*TIW + tx];
                const float* x1 = x0 + 8*TIW;
                const float* wrow = &ws[(icl*KS*KS + kh*KS)*16];
#pragma unroll
                for (int kw = 0; kw < KS; kw++) {
                    float v00 = x0[kw], v01 = x0[16+kw];
                    float v10 = x1[kw], v11 = x1[16+kw];
                    const float4* wp = (const float4*)(wrow + kw*16);
#pragma unroll
                    for (int q = 0; q < 4; q++) {
                        float4 wv = wp[q];
                        a00[q*4+0]=fmaf(wv.x,v00,a00[q*4+0]); a00[q*4+1]=fmaf(wv.y,v00,a00[q*4+1]);
                        a00[q*4+2]=fmaf(wv.z,v00,a00[q*4+2]); a00[q*4+3]=fmaf(wv.w,v00,a00[q*4+3]);
                        a01[q*4+0]=fmaf(wv.x,v01,a01[q*4+0]); a01[q*4+1]=fmaf(wv.y,v01,a01[q*4+1]);
                        a01[q*4+2]=fmaf(wv.z,v01,a01[q*4+2]); a01[q*4+3]=fmaf(wv.w,v01,a01[q*4+3]);
                        a10[q*4+0]=fmaf(wv.x,v10,a10[q*4+0]); a10[q*4+1]=fmaf(wv.y,v10,a10[q*4+1]);
                        a10[q*4+2]=fmaf(wv.z,v10,a10[q*4+2]); a10[q*4+3]=fmaf(wv.w,v10,a10[q*4+3]);
                        a11[q*4+0]=fmaf(wv.x,v11,a11[q*4+0]); a11[q*4+1]=fmaf(wv.y,v11,a11[q*4+1]);
                        a11[q*4+2]=fmaf(wv.z,v11,a11[q*4+2]); a11[q*4+3]=fmaf(wv.w,v11,a11[q*4+3]);
                    }
                }
            }
        }
    }
    const int ox0 = ix0 + tx, oy0 = iy0 + ty;
#pragma unroll
    for (int q = 0; q < 16; q++) {
        float* op = out + (((size_t)b*16 + q)*HOUT + oy0)*WOUT + ox0;
        if (oy0 < HOUT) {
            if (ox0      < WOUT) op[0]  = fmaxf(a00[q], 0.f);
            if (ox0 + 16 < WOUT) op[16] = fmaxf(a01[q], 0.f);
        }
        if (oy0 + 8 < HOUT) {
            if (ox0      < WOUT) op[8*(size_t)WOUT]      = fmaxf(a10[q], 0.f);
            if (ox0 + 16 < WOUT) op[8*(size_t)WOUT + 16] = fmaxf(a11[q], 0.f);
        }
    }
}

// =====================================================================
// conv4/conv5 (small): 16-wide tile, 2 rows per thread
// =====================================================================
template<int CIN, int COUT, int KS, int STRIDE, int HIN, int WIN,
         int HOUT, int WOUT, int ICC>
__global__ void __launch_bounds__(128) conv_kernel(
    const float* __restrict__ in, const float* __restrict__ w,
    const float* __restrict__ bias, float* __restrict__ out)
{
    constexpr int TIN = 15*STRIDE + KS;
    __shared__ float xs[ICC*TIN*TIN];
    __shared__ float ws[ICC*KS*KS*COUT];
    __shared__ float bs[COUT];

    const int tx = threadIdx.x, ty = threadIdx.y;
    const int tid = ty*16 + tx;
    const int b = blockIdx.z;
    const int oy0 = blockIdx.y*16 + ty;
    const int ox  = blockIdx.x*16 + tx;
    const int iy0 = blockIdx.y*16*STRIDE;
    const int ix0 = blockIdx.x*16*STRIDE;

    if (tid < COUT) bs[tid] = bias[tid];
    __syncthreads();

    float acc0[COUT], acc1[COUT];
#pragma unroll
    for (int oc = 0; oc < COUT; oc++) { acc0[oc] = bs[oc]; acc1[oc] = bs[oc]; }

    for (int cc = 0; cc < CIN; cc += ICC) {
        __syncthreads();
        for (int i = tid; i < ICC*TIN*TIN; i += 128) {
            int icl = i / (TIN*TIN), r = i - icl*(TIN*TIN);
            int yy = r / TIN, xx = r - yy*TIN;
            int gy = iy0 + yy, gx = ix0 + xx;
            float v = 0.f;
            if (gy < HIN && gx < WIN)
                v = in[(((size_t)b*CIN + cc + icl)*HIN + gy)*WIN + gx];
            xs[i] = v;
        }
        for (int i = tid; i < ICC*KS*KS*COUT; i += 128) {
            int oc = i % COUT; int r = i / COUT;
            int icl = r / (KS*KS); int kk = r - icl*(KS*KS);
            ws[i] = w[((size_t)oc*CIN + cc + icl)*KS*KS + kk];
        }
        __syncthreads();
#pragma unroll 1
        for (int icl = 0; icl < ICC; icl++) {
            for (int kh = 0; kh < KS; kh++) {
                const float* x0 = &xs[icl*TIN*TIN + (ty*STRIDE + kh)*TIN + tx*STRIDE];
                const float* x1 = &xs[icl*TIN*TIN + ((ty+8)*STRIDE + kh)*TIN + tx*STRIDE];
                const float* wrow = &ws[(icl*KS*KS + kh*KS)*COUT];
#pragma unroll
                for (int kw = 0; kw < KS; kw++) {
                    float v0 = x0[kw];
                    float v1 = x1[kw];
                    const float4* wp = (const float4*)(wrow + kw*COUT);
#pragma unroll
                    for (int q = 0; q < COUT/4; q++) {
                        float4 wv = wp[q];
                        acc0[q*4+0]=fmaf(wv.x,v0,acc0[q*4+0]);
                        acc0[q*4+1]=fmaf(wv.y,v0,acc0[q*4+1]);
                        acc0[q*4+2]=fmaf(wv.z,v0,acc0[q*4+2]);
                        acc0[q*4+3]=fmaf(wv.w,v0,acc0[q*4+3]);
                        acc1[q*4+0]=fmaf(wv.x,v1,acc1[q*4+0]);
                        acc1[q*4+1]=fmaf(wv.y,v1,acc1[q*4+1]);
                        acc1[q*4+2]=fmaf(wv.z,v1,acc1[q*4+2]);
                        acc1[q*4+3]=fmaf(wv.w,v1,acc1[q*4+3]);
                    }
                }
            }
        }
    }
    if (ox < WOUT) {
#pragma unroll
        for (int oc = 0; oc < COUT; oc++) {
            if (oy0 < HOUT)
                out[(((size_t)b*COUT + oc)*HOUT + oy0)*WOUT + ox] = fmaxf(acc0[oc], 0.f);
            if (oy0 + 8 < HOUT)
                out[(((size_t)b*COUT + oc)*HOUT + oy0 + 8)*WOUT + ox] = fmaxf(acc1[oc], 0.f);
        }
    }
}

// =====================================================================
// fc partial / reduce / fc3 (unchanged)
// =====================================================================
#define FC_CHUNK 160
__global__ void __launch_bounds__(128) fc_partial(
    const float* __restrict__ x, const float* __restrict__ w,
    float* __restrict__ part, int N, int K, int ktlen)
{
    __shared__ float xs[32*FC_CHUNK];
    const int tid = threadIdx.x;
    const int n0 = blockIdx.x*256 + tid;
    const int n1 = n0 + 128;
    const int k0 = blockIdx.y*ktlen;

    float acc0[32], acc1[32];
#pragma unroll
    for (int m = 0; m < 32; m++) { acc0[m]=0.f; acc1[m]=0.f; }

    for (int kc = 0; kc < ktlen; kc += FC_CHUNK) {
        int cl = min(FC_CHUNK, ktlen - kc);
        __syncthreads();
        for (int i = tid; i < 32*cl; i += 128) {
            int m = i / cl, kk = i - m*cl;
            xs[m*FC_CHUNK + kk] = x[(size_t)m*K + k0 + kc + kk];
        }
        __syncthreads();
        const float* w0 = w + (size_t)n0*K + k0 + kc;
        const float* w1 = w + (size_t)n1*K + k0 + kc;
        for (int kk = 0; kk < cl; kk += 2) {
            float2 a0 = *(const float2*)(w0 + kk);
            float2 a1 = *(const float2*)(w1 + kk);
#pragma unroll
            for (int m = 0; m < 32; m++) {
                float2 xv = *(const float2*)&xs[m*FC_CHUNK + kk];
                acc0[m] = fmaf(a0.x, xv.x, fmaf(a0.y, xv.y, acc0[m]));
                acc1[m] = fmaf(a1.x, xv.x, fmaf(a1.y, xv.y, acc1[m]));
            }
        }
    }
    float* pr = part + (size_t)blockIdx.y*32*N;
#pragma unroll
    for (int m = 0; m < 32; m++) {
        pr[(size_t)m*N + n0] = acc0[m];
        pr[(size_t)m*N + n1] = acc1[m];
    }
}

__global__ void fc_reduce(const float* __restrict__ part,
                          const float* __restrict__ bias,
                          float* __restrict__ out, int N, int KT, int do_relu)
{
    int i = blockIdx.x*256 + threadIdx.x;
    if (i >= 32*N) return;
    int n = i % N;
    float s = bias[n];
    for (int kt = 0; kt < KT; kt++) s += part[(size_t)kt*32*N + i];
    out[i] = do_relu ? fmaxf(s, 0.f) : s;
}

__global__ void __launch_bounds__(768) fc3_softmax(
    const float* __restrict__ x, const float* __restrict__ w,
    const float* __restrict__ bias, float* __restrict__ out)
{
    __shared__ float lg[24];
    const int b = blockIdx.x;
    const int tid = threadIdx.x;
    const int wo = tid >> 5, lane = tid & 31;

    const float* xr = x + (size_t)b*2048;
    const float* wr = w + (size_t)wo*2048;
    float s = 0.f;
    for (int k = lane; k < 2048; k += 32) s = fmaf(wr[k], xr[k], s);
#pragma unroll
    for (int off = 16; off; off >>= 1) s += __shfl_xor_sync(0xffffffffu, s, off);
    if (lane == 0) lg[wo] = s + bias[wo];
    __syncthreads();

    if (tid < 24) {
        int a = tid % 12;
        float z0 = lg[a], z1 = lg[12 + a];
        float m = fmaxf(z0, z1);
        float lse = m + logf(expf(z0 - m) + expf(z1 - m));
        out[b*24 + tid] = lg[tid] - lse;
    }
}

// =====================================================================
// launch
// =====================================================================
extern "C" void kernel_launch(void* const* d_in, const int* in_sizes, int n_in,
                              void* d_out, int out_size)
{
    const float* x        = (const float*)d_in[0];
    const float* conv1_w  = (const float*)d_in[1];
    const float* conv1_b  = (const float*)d_in[2];
    const float* rl_gamma = (const float*)d_in[3];
    const float* rl_beta  = (const float*)d_in[4];
    const float* rl_mean  = (const float*)d_in[5];
    const float* rl_var   = (const float*)d_in[6];
    const float* rl_cw    = (const float*)d_in[7];
    const float* rl_cb    = (const float*)d_in[8];
    const float* bn_gamma = (const float*)d_in[9];
    const float* bn_beta  = (const float*)d_in[10];
    const float* bn_mean  = (const float*)d_in[11];
    const float* bn_var   = (const float*)d_in[12];
    const float* conv2_w  = (const float*)d_in[13];
    const float* conv2_b  = (const float*)d_in[14];
    const float* conv3_w  = (const float*)d_in[15];
    const float* conv3_b  = (const float*)d_in[16];
    const float* conv4_w  = (const float*)d_in[17];
    const float* conv4_b  = (const float*)d_in[18];
    const float* conv5_w  = (const float*)d_in[19];
    const float* conv5_b  = (const float*)d_in[20];
    const float* fc1_w    = (const float*)d_in[21];
    const float* fc1_b    = (const float*)d_in[22];
    const float* fc2_w    = (const float*)d_in[23];
    const float* fc2_b    = (const float*)d_in[24];
    const float* fc3_w    = (const float*)d_in[25];
    const float* fc3_b    = (const float*)d_in[26];
    float* out = (float*)d_out;

    float *b1,*b2,*b3,*b4,*b5,*b6,*pt,*f1,*f2;
    cudaGetSymbolAddress((void**)&b1, g_buf1);
    cudaGetSymbolAddress((void**)&b2, g_buf2);
    cudaGetSymbolAddress((void**)&b3, g_buf3);
    cudaGetSymbolAddress((void**)&b4, g_buf4);
    cudaGetSymbolAddress((void**)&b5, g_buf5);
    cudaGetSymbolAddress((void**)&b6, g_buf6);
    cudaGetSymbolAddress((void**)&pt, g_part);
    cudaGetSymbolAddress((void**)&f1, g_fc1);
    cudaGetSymbolAddress((void**)&f2, g_fc2);

    const int region_smem = (15488 + 288*36) * 4;   // 103424 B
    cudaFuncSetAttribute(region_kernel,
                         cudaFuncAttributeMaxDynamicSharedMemorySize, region_smem);

    // 1. conv1: out tile 32x16, oc split in 2
    conv1_kernel<<<dim3(5,10,BATCH*2), dim3(16,8)>>>(x, conv1_w, conv1_b, b1);

    // 2. region + relu + maxpool + bn
    region_kernel<<<BATCH*64, 256, region_smem>>>(
        b1, rl_gamma, rl_beta, rl_mean, rl_var, rl_cw, rl_cb,
        bn_gamma, bn_beta, bn_mean, bn_var, b2);

    // 3. conv2: 32->16, 8x8, 80->73
    conv_kernel2<32,8,80,80,73,73,4><<<dim3(3,5,BATCH), dim3(16,8)>>>(
        b2, conv2_w, conv2_b, b3);

    // 4. conv3: 16->16, 8x8, 73->66
    conv_kernel2<16,8,73,73,66,66,4><<<dim3(3,5,BATCH), dim3(16,8)>>>(
        b3, conv3_w, conv3_b, b4);

    // 5. conv4: 16->16, 6x6 stride 2, 66->31
    conv_kernel<16,16,6,2,66,66,31,31,4><<<dim3(2,2,BATCH), dim3(16,8)>>>(
        b4, conv4_w, conv4_b, b5);

    // 6. conv5: 16->16, 5x5, 31->27
    conv_kernel<16,16,5,1,31,31,27,27,8><<<dim3(2,2,BATCH), dim3(16,8)>>>(
        b5, conv5_w, conv5_b, b6);

    // 7. fc1
    fc_partial<<<dim3(16,8), 128>>>(b6, fc1_w, pt, 4096, 11664, 1458);
    fc_reduce<<<512, 256>>>(pt, fc1_b, f1, 4096, 8, 1);

    // 8. fc2
    fc_partial<<<dim3(8,8), 128>>>(f1, fc2_w, pt, 2048, 4096, 512);
    fc_reduce<<<256, 256>>>(pt, fc2_b, f2, 2048, 8, 1);

    // 9. fc3 + log_softmax
    fc3_softmax<<<BATCH, 768>>>(f2, fc3_w, fc3_b, out);
}

// round 3
// speedup vs baseline: 1.3385x; 1.1467x over previous
#include <cuda_runtime.h>
#include <cuda_bf16.h>
#include <math.h>

#define BATCH 32
#define EPS 1e-5f

// ---------------- scratch ----------------
__device__ float g_buf1[BATCH*32*160*160];
__device__ float g_buf2[BATCH*32*80*80];
__device__ float g_buf3[BATCH*16*73*73];
__device__ float g_buf4[BATCH*16*66*66];
__device__ float g_buf5[BATCH*16*31*31];
__device__ float g_buf6[BATCH*16*27*27];
__device__ float g_cpart[2*BATCH*16*73*73];   // conv partial sums (max = conv2)
__device__ float g_part[12*32*4096];          // fc partials
__device__ float g_fc1[BATCH*4096];
__device__ float g_fc2[BATCH*2048];

// =====================================================================
// conv1: [32,3,170,170] -> [32,32,160,160], 11x11
// =====================================================================
__global__ void __launch_bounds__(128) conv1_kernel(
    const float* __restrict__ x, const float* __restrict__ w,
    const float* __restrict__ bias, float* __restrict__ out)
{
    __shared__ float xs[3*26*42];
    __shared__ float ws[363*16];
    __shared__ float bs[16];
    const int tx = threadIdx.x, ty = threadIdx.y;
    const int tid = ty*16 + tx;
    const int z = blockIdx.z;
    const int b = z >> 1, half = z & 1;

    for (int i = tid; i < 363*16; i += 128) {
        int ckk = i >> 4, oc = i & 15;
        ws[i] = w[(half*16 + oc)*363 + ckk];
    }
    if (tid < 16) bs[tid] = bias[half*16 + tid];

    const int ix0 = blockIdx.x*32;
    const int iy0 = blockIdx.y*16;
    const float* xb = x + (size_t)b*3*170*170;
    for (int i = tid; i < 3*26*42; i += 128) {
        int c = i / (26*42), r = i - c*(26*42);
        int yy = r / 42, xx = r - yy*42;
        xs[i] = xb[((size_t)c*170 + iy0 + yy)*170 + ix0 + xx];
    }
    __syncthreads();

    float a00[16], a01[16], a10[16], a11[16];
#pragma unroll
    for (int q = 0; q < 16; q++) { a00[q]=bs[q]; a01[q]=bs[q]; a10[q]=bs[q]; a11[q]=bs[q]; }

    for (int c = 0; c < 3; c++) {
        for (int kh = 0; kh < 11; kh++) {
            const float* x0 = &xs[c*26*42 + (ty+kh)*42 + tx];
            const float* x1 = x0 + 8*42;
            const float* wrow = &ws[(c*121 + kh*11)*16];
#pragma unroll
            for (int kw = 0; kw < 11; kw++) {
                float v00 = x0[kw], v01 = x0[16+kw];
                float v10 = x1[kw], v11 = x1[16+kw];
                const float4* wp = (const float4*)(wrow + kw*16);
#pragma unroll
                for (int q = 0; q < 4; q++) {
                    float4 wv = wp[q];
                    a00[q*4+0]=fmaf(wv.x,v00,a00[q*4+0]); a00[q*4+1]=fmaf(wv.y,v00,a00[q*4+1]);
                    a00[q*4+2]=fmaf(wv.z,v00,a00[q*4+2]); a00[q*4+3]=fmaf(wv.w,v00,a00[q*4+3]);
                    a01[q*4+0]=fmaf(wv.x,v01,a01[q*4+0]); a01[q*4+1]=fmaf(wv.y,v01,a01[q*4+1]);
                    a01[q*4+2]=fmaf(wv.z,v01,a01[q*4+2]); a01[q*4+3]=fmaf(wv.w,v01,a01[q*4+3]);
                    a10[q*4+0]=fmaf(wv.x,v10,a10[q*4+0]); a10[q*4+1]=fmaf(wv.y,v10,a10[q*4+1]);
                    a10[q*4+2]=fmaf(wv.z,v10,a10[q*4+2]); a10[q*4+3]=fmaf(wv.w,v10,a10[q*4+3]);
                    a11[q*4+0]=fmaf(wv.x,v11,a11[q*4+0]); a11[q*4+1]=fmaf(wv.y,v11,a11[q*4+1]);
                    a11[q*4+2]=fmaf(wv.z,v11,a11[q*4+2]); a11[q*4+3]=fmaf(wv.w,v11,a11[q*4+3]);
                }
            }
        }
    }
    const int ox = ix0 + tx, oy = iy0 + ty;
#pragma unroll
    for (int q = 0; q < 16; q++) {
        int oc = half*16 + q;
        float* op = out + (((size_t)b*32 + oc)*160 + oy)*160 + ox;
        op[0] = a00[q]; op[16] = a01[q];
        op[8*160] = a10[q]; op[8*160+16] = a11[q];
    }
}

// =====================================================================
// Region layer fused
// =====================================================================
__global__ void __launch_bounds__(256) region_kernel(
    const float* __restrict__ in,
    const float* __restrict__ rl_gamma, const float* __restrict__ rl_beta,
    const float* __restrict__ rl_mean,  const float* __restrict__ rl_var,
    const float* __restrict__ rl_cw,    const float* __restrict__ rl_cb,
    const float* __restrict__ bn_g, const float* __restrict__ bn_b,
    const float* __restrict__ bn_m, const float* __restrict__ bn_v,
    float* __restrict__ out)
{
    extern __shared__ float sm[];
    float* act = sm;                   // 32*484
    float* wsT = sm + 15488;           // 288*36
    __shared__ float sc[32], sh[32], s2[32], t2[32], cb[32];

    const int blk = blockIdx.x;
    const int b = blk >> 6;
    const int patch = blk & 63;
    const int gi = patch >> 3, gj = patch & 7;
    const int k = gj*(gi+1);
    const int tid = threadIdx.x;

    if (tid < 32) {
        float g = rl_gamma[k*32+tid];
        float s = g * rsqrtf(rl_var[k*32+tid] + EPS);
        sc[tid] = s;
        sh[tid] = rl_beta[k*32+tid] - rl_mean[k*32+tid]*s;
        float ss = bn_g[tid] * rsqrtf(bn_v[tid] + EPS);
        s2[tid] = ss;
        t2[tid] = bn_b[tid] - bn_m[tid]*ss;
        cb[tid] = rl_cb[k*32+tid];
    }
    for (int i = tid; i < 15488; i += 256) act[i] = 0.f;
    __syncthreads();

    const float* inb = in + (size_t)b*32*160*160;
    for (int i = tid; i < 32*400; i += 256) {
        int ic = i / 400, r = i - ic*400;
        int y = r / 20, xx = r - y*20;
        float v = inb[((size_t)ic*160 + gi*20 + y)*160 + gj*20 + xx];
        act[ic*484 + (y+1)*22 + (xx+1)] = fmaxf(fmaf(v, sc[ic], sh[ic]), 0.f);
    }
    for (int i = tid; i < 9216; i += 256) {
        int oc = i / 288, r = i - oc*288;
        wsT[r*36 + oc] = rl_cw[(size_t)k*9216 + i];
    }
    __syncthreads();

    for (int item = tid; item < 800; item += 256) {
        int ocq = item / 100, pos = item - ocq*100;
        int oc0 = ocq*4;
        int py = pos / 10, px = pos - py*10;
        int yb = 2*py, xb = 2*px;

        float acc[4][4];
#pragma unroll
        for (int o = 0; o < 4; o++) {
            float bv = cb[oc0+o];
            acc[o][0]=bv; acc[o][1]=bv; acc[o][2]=bv; acc[o][3]=bv;
        }

        for (int ic = 0; ic < 32; ic++) {
            float a[4][4];
#pragma unroll
            for (int dy = 0; dy < 4; dy++) {
                const float2* rp = (const float2*)&act[ic*484 + (yb+dy)*22 + xb];
                float2 v0 = rp[0], v1 = rp[1];
                a[dy][0]=v0.x; a[dy][1]=v0.y; a[dy][2]=v1.x; a[dy][3]=v1.y;
            }
            const float* wr = &wsT[(ic*9)*36 + oc0];
#pragma unroll
            for (int kk = 0; kk < 9; kk++) {
                int ky = kk/3, kx = kk - ky*3;
                float4 wv = *(const float4*)(wr + kk*36);
                float e00 = a[ky][kx],   e01 = a[ky][kx+1];
                float e10 = a[ky+1][kx], e11 = a[ky+1][kx+1];
                acc[0][0]=fmaf(wv.x,e00,acc[0][0]); acc[0][1]=fmaf(wv.x,e01,acc[0][1]);
                acc[0][2]=fmaf(wv.x,e10,acc[0][2]); acc[0][3]=fmaf(wv.x,e11,acc[0][3]);
                acc[1][0]=fmaf(wv.y,e00,acc[1][0]); acc[1][1]=fmaf(wv.y,e01,acc[1][1]);
                acc[1][2]=fmaf(wv.y,e10,acc[1][2]); acc[1][3]=fmaf(wv.y,e11,acc[1][3]);
                acc[2][0]=fmaf(wv.z,e00,acc[2][0]); acc[2][1]=fmaf(wv.z,e01,acc[2][1]);
                acc[2][2]=fmaf(wv.z,e10,acc[2][2]); acc[2][3]=fmaf(wv.z,e11,acc[2][3]);
                acc[3][0]=fmaf(wv.w,e00,acc[3][0]); acc[3][1]=fmaf(wv.w,e01,acc[3][1]);
                acc[3][2]=fmaf(wv.w,e10,acc[3][2]); acc[3][3]=fmaf(wv.w,e11,acc[3][3]);
            }
        }
#pragma unroll
        for (int o = 0; o < 4; o++) {
            int oc = oc0 + o;
            const float* xrb = inb + ((size_t)oc*160 + gi*20 + yb)*160 + gj*20 + xb;
            float v0 = fmaxf(acc[o][0] + xrb[0], 0.f);
            float v1 = fmaxf(acc[o][1] + xrb[1], 0.f);
            float v2 = fmaxf(acc[o][2] + xrb[160], 0.f);
            float v3 = fmaxf(acc[o][3] + xrb[161], 0.f);
            float mx = fmaxf(fmaxf(v0, v1), fmaxf(v2, v3));
            out[(((size_t)b*32 + oc)*80 + gi*10 + py)*80 + gj*10 + px] =
                fmaf(mx, s2[oc], t2[oc]);
        }
    }
}

// =====================================================================
// conv2/conv3 partial: CIN split across blockIdx.z parity. No bias/relu.
// =====================================================================
template<int CIN, int CINH, int KS, int HIN, int WIN, int HOUT, int WOUT, int ICC>
__global__ void __launch_bounds__(128) conv_split2(
    const float* __restrict__ in, const float* __restrict__ w,
    float* __restrict__ part)
{
    constexpr int TIW = 32 + KS - 1;
    constexpr int TIH = 16 + KS - 1;
    __shared__ float xs[ICC*TIH*TIW];
    __shared__ float ws[ICC*KS*KS*16];

    const int tx = threadIdx.x, ty = threadIdx.y;
    const int tid = ty*16 + tx;
    const int z = blockIdx.z;
    const int b = z >> 1, split = z & 1;
    const int c0 = split*CINH;
    const int ix0 = blockIdx.x*32, iy0 = blockIdx.y*16;

    float a00[16], a01[16], a10[16], a11[16];
#pragma unroll
    for (int q = 0; q < 16; q++) { a00[q]=0.f; a01[q]=0.f; a10[q]=0.f; a11[q]=0.f; }

    for (int cc = c0; cc < c0 + CINH; cc += ICC) {
        __syncthreads();
        for (int i = tid; i < ICC*TIH*TIW; i += 128) {
            int icl = i / (TIH*TIW), r = i - icl*(TIH*TIW);
            int yy = r / TIW, xx = r - yy*TIW;
            int gy = iy0 + yy, gx = ix0 + xx;
            float v = 0.f;
            if (gy < HIN && gx < WIN)
                v = in[(((size_t)b*CIN + cc + icl)*HIN + gy)*WIN + gx];
            xs[i] = v;
        }
        for (int i = tid; i < ICC*KS*KS*16; i += 128) {
            int oc = i & 15, r = i >> 4;
            int icl = r / (KS*KS), kk = r - icl*(KS*KS);
            ws[i] = w[((size_t)oc*CIN + cc + icl)*KS*KS + kk];
        }
        __syncthreads();
#pragma unroll 1
        for (int icl = 0; icl < ICC; icl++) {
            for (int kh = 0; kh < KS; kh++) {
                const float* x0 = &xs[icl*TIH*TIW + (ty+kh)*TIW + tx];
                const float* x1 = x0 + 8*TIW;
                const float* wrow = &ws[(icl*KS*KS + kh*KS)*16];
#pragma unroll
                for (int kw = 0; kw < KS; kw++) {
                    float v00 = x0[kw], v01 = x0[16+kw];
                    float v10 = x1[kw], v11 = x1[16+kw];
                    const float4* wp = (const float4*)(wrow + kw*16);
#pragma unroll
                    for (int q = 0; q < 4; q++) {
                        float4 wv = wp[q];
                        a00[q*4+0]=fmaf(wv.x,v00,a00[q*4+0]); a00[q*4+1]=fmaf(wv.y,v00,a00[q*4+1]);
                        a00[q*4+2]=fmaf(wv.z,v00,a00[q*4+2]); a00[q*4+3]=fmaf(wv.w,v00,a00[q*4+3]);
                        a01[q*4+0]=fmaf(wv.x,v01,a01[q*4+0]); a01[q*4+1]=fmaf(wv.y,v01,a01[q*4+1]);
                        a01[q*4+2]=fmaf(wv.z,v01,a01[q*4+2]); a01[q*4+3]=fmaf(wv.w,v01,a01[q*4+3]);
                        a10[q*4+0]=fmaf(wv.x,v10,a10[q*4+0]); a10[q*4+1]=fmaf(wv.y,v10,a10[q*4+1]);
                        a10[q*4+2]=fmaf(wv.z,v10,a10[q*4+2]); a10[q*4+3]=fmaf(wv.w,v10,a10[q*4+3]);
                        a11[q*4+0]=fmaf(wv.x,v11,a11[q*4+0]); a11[q*4+1]=fmaf(wv.y,v11,a11[q*4+1]);
                        a11[q*4+2]=fmaf(wv.z,v11,a11[q*4+2]); a11[q*4+3]=fmaf(wv.w,v11,a11[q*4+3]);
                    }
                }
            }
        }
    }
    const size_t tot = (size_t)BATCH*16*HOUT*WOUT;
    float* pb = part + (size_t)split*tot;
    const int ox0 = ix0 + tx, oy0 = iy0 + ty;
#pragma unroll
    for (int q = 0; q < 16; q++) {
        float* op = pb + (((size_t)b*16 + q)*HOUT + oy0)*WOUT + ox0;
        if (oy0 < HOUT) {
            if (ox0      < WOUT) op[0]  = a00[q];
            if (ox0 + 16 < WOUT) op[16] = a01[q];
        }
        if (oy0 + 8 < HOUT) {
            if (ox0      < WOUT) op[8*(size_t)WOUT]      = a10[q];
            if (ox0 + 16 < WOUT) op[8*(size_t)WOUT + 16] = a11[q];
        }
    }
}

// =====================================================================
// conv4/conv5 partial: 16x16 tile, CIN split
// =====================================================================
template<int CIN, int CINH, int COUT, int KS, int STRIDE, int HIN, int WIN,
         int HOUT, int WOUT, int ICC>
__global__ void __launch_bounds__(128) conv_split(
    const float* __restrict__ in, const float* __restrict__ w,
    float* __restrict__ part)
{
    constexpr int TIN = 15*STRIDE + KS;
    __shared__ float xs[ICC*TIN*TIN];
    __shared__ float ws[ICC*KS*KS*COUT];

    const int tx = threadIdx.x, ty = threadIdx.y;
    const int tid = ty*16 + tx;
    const int z = blockIdx.z;
    const int b = z >> 1, split = z & 1;
    const int c0 = split*CINH;
    const int oy0 = blockIdx.y*16 + ty;
    const int ox  = blockIdx.x*16 + tx;
    const int iy0 = blockIdx.y*16*STRIDE;
    const int ix0 = blockIdx.x*16*STRIDE;

    float acc0[COUT], acc1[COUT];
#pragma unroll
    for (int oc = 0; oc < COUT; oc++) { acc0[oc] = 0.f; acc1[oc] = 0.f; }

    for (int cc = c0; cc < c0 + CINH; cc += ICC) {
        __syncthreads();
        for (int i = tid; i < ICC*TIN*TIN; i += 128) {
            int icl = i / (TIN*TIN), r = i - icl*(TIN*TIN);
            int yy = r / TIN, xx = r - yy*TIN;
            int gy = iy0 + yy, gx = ix0 + xx;
            float v = 0.f;
            if (gy < HIN && gx < WIN)
                v = in[(((size_t)b*CIN + cc + icl)*HIN + gy)*WIN + gx];
            xs[i] = v;
        }
        for (int i = tid; i < ICC*KS*KS*COUT; i += 128) {
            int oc = i % COUT; int r = i / COUT;
            int icl = r / (KS*KS); int kk = r - icl*(KS*KS);
            ws[i] = w[((size_t)oc*CIN + cc + icl)*KS*KS + kk];
        }
        __syncthreads();
#pragma unroll 1
        for (int icl = 0; icl < ICC; icl++) {
            for (int kh = 0; kh < KS; kh++) {
                const float* x0 = &xs[icl*TIN*TIN + (ty*STRIDE + kh)*TIN + tx*STRIDE];
                const float* x1 = &xs[icl*TIN*TIN + ((ty+8)*STRIDE + kh)*TIN + tx*STRIDE];
                const float* wrow = &ws[(icl*KS*KS + kh*KS)*COUT];
#pragma unroll
                for (int kw = 0; kw < KS; kw++) {
                    float v0 = x0[kw];
                    float v1 = x1[kw];
                    const float4* wp = (const float4*)(wrow + kw*COUT);
#pragma unroll
                    for (int q = 0; q < COUT/4; q++) {
                        float4 wv = wp[q];
                        acc0[q*4+0]=fmaf(wv.x,v0,acc0[q*4+0]);
                        acc0[q*4+1]=fmaf(wv.y,v0,acc0[q*4+1]);
                        acc0[q*4+2]=fmaf(wv.z,v0,acc0[q*4+2]);
                        acc0[q*4+3]=fmaf(wv.w,v0,acc0[q*4+3]);
                        acc1[q*4+0]=fmaf(wv.x,v1,acc1[q*4+0]);
                        acc1[q*4+1]=fmaf(wv.y,v1,acc1[q*4+1]);
                        acc1[q*4+2]=fmaf(wv.z,v1,acc1[q*4+2]);
                        acc1[q*4+3]=fmaf(wv.w,v1,acc1[q*4+3]);
                    }
                }
            }
        }
    }
    const size_t tot = (size_t)BATCH*COUT*HOUT*WOUT;
    float* pb = part + (size_t)split*tot;
    if (ox < WOUT) {
#pragma unroll
        for (int oc = 0; oc < COUT; oc++) {
            if (oy0 < HOUT)
                pb[(((size_t)b*COUT + oc)*HOUT + oy0)*WOUT + ox] = acc0[oc];
            if (oy0 + 8 < HOUT)
                pb[(((size_t)b*COUT + oc)*HOUT + oy0 + 8)*WOUT + ox] = acc1[oc];
        }
    }
}

// combine two CIN-split partials + bias + relu (COUT = 16)
__global__ void combine_relu(const float* __restrict__ p,
                             const float* __restrict__ bias,
                             float* __restrict__ out, int HW, int total)
{
    int i = blockIdx.x*256 + threadIdx.x;
    if (i >= total) return;
    int oc = (i / HW) & 15;
    out[i] = fmaxf(p[i] + p[i + total] + bias[oc], 0.f);
}

// =====================================================================
// fc partial / reduce / fc3
// =====================================================================
#define FC_CHUNK 160
__global__ void __launch_bounds__(128) fc_partial(
    const float* __restrict__ x, const float* __restrict__ w,
    float* __restrict__ part, int N, int K, int ktlen)
{
    __shared__ float xs[32*FC_CHUNK];
    const int tid = threadIdx.x;
    const int n0 = blockIdx.x*256 + tid;
    const int n1 = n0 + 128;
    const int k0 = blockIdx.y*ktlen;

    float acc0[32], acc1[32];
#pragma unroll
    for (int m = 0; m < 32; m++) { acc0[m]=0.f; acc1[m]=0.f; }

    for (int kc = 0; kc < ktlen; kc += FC_CHUNK) {
        int cl = min(FC_CHUNK, ktlen - kc);
        __syncthreads();
        for (int i = tid; i < 32*cl; i += 128) {
            int m = i / cl, kk = i - m*cl;
            xs[m*FC_CHUNK + kk] = x[(size_t)m*K + k0 + kc + kk];
        }
        __syncthreads();
        const float* w0 = w + (size_t)n0*K + k0 + kc;
        const float* w1 = w + (size_t)n1*K + k0 + kc;
        for (int kk = 0; kk < cl; kk += 2) {
            float2 a0 = *(const float2*)(w0 + kk);
            float2 a1 = *(const float2*)(w1 + kk);
#pragma unroll
            for (int m = 0; m < 32; m++) {
                float2 xv = *(const float2*)&xs[m*FC_CHUNK + kk];
                acc0[m] = fmaf(a0.x, xv.x, fmaf(a0.y, xv.y, acc0[m]));
                acc1[m] = fmaf(a1.x, xv.x, fmaf(a1.y, xv.y, acc1[m]));
            }
        }
    }
    float* pr = part + (size_t)blockIdx.y*32*N;
#pragma unroll
    for (int m = 0; m < 32; m++) {
        pr[(size_t)m*N + n0] = acc0[m];
        pr[(size_t)m*N + n1] = acc1[m];
    }
}

__global__ void fc_reduce(const float* __restrict__ part,
                          const float* __restrict__ bias,
                          float* __restrict__ out, int N, int KT, int do_relu)
{
    int i = blockIdx.x*256 + threadIdx.x;
    if (i >= 32*N) return;
    int n = i % N;
    float s = bias[n];
    for (int kt = 0; kt < KT; kt++) s += part[(size_t)kt*32*N + i];
    out[i] = do_relu ? fmaxf(s, 0.f) : s;
}

__global__ void __launch_bounds__(768) fc3_softmax(
    const float* __restrict__ x, const float* __restrict__ w,
    const float* __restrict__ bias, float* __restrict__ out)
{
    __shared__ float lg[24];
    const int b = blockIdx.x;
    const int tid = threadIdx.x;
    const int wo = tid >> 5, lane = tid & 31;

    const float* xr = x + (size_t)b*2048;
    const float* wr = w + (size_t)wo*2048;
    float s = 0.f;
    for (int k = lane; k < 2048; k += 32) s = fmaf(wr[k], xr[k], s);
#pragma unroll
    for (int off = 16; off; off >>= 1) s += __shfl_xor_sync(0xffffffffu, s, off);
    if (lane == 0) lg[wo] = s + bias[wo];
    __syncthreads();

    if (tid < 24) {
        int a = tid % 12;
        float z0 = lg[a], z1 = lg[12 + a];
        float m = fmaxf(z0, z1);
        float lse = m + logf(expf(z0 - m) + expf(z1 - m));
        out[b*24 + tid] = lg[tid] - lse;
    }
}

// =====================================================================
// launch
// =====================================================================
extern "C" void kernel_launch(void* const* d_in, const int* in_sizes, int n_in,
                              void* d_out, int out_size)
{
    const float* x        = (const float*)d_in[0];
    const float* conv1_w  = (const float*)d_in[1];
    const float* conv1_b  = (const float*)d_in[2];
    const float* rl_gamma = (const float*)d_in[3];
    const float* rl_beta  = (const float*)d_in[4];
    const float* rl_mean  = (const float*)d_in[5];
    const float* rl_var   = (const float*)d_in[6];
    const float* rl_cw    = (const float*)d_in[7];
    const float* rl_cb    = (const float*)d_in[8];
    const float* bn_gamma = (const float*)d_in[9];
    const float* bn_beta  = (const float*)d_in[10];
    const float* bn_mean  = (const float*)d_in[11];
    const float* bn_var   = (const float*)d_in[12];
    const float* conv2_w  = (const float*)d_in[13];
    const float* conv2_b  = (const float*)d_in[14];
    const float* conv3_w  = (const float*)d_in[15];
    const float* conv3_b  = (const float*)d_in[16];
    const float* conv4_w  = (const float*)d_in[17];
    const float* conv4_b  = (const float*)d_in[18];
    const float* conv5_w  = (const float*)d_in[19];
    const float* conv5_b  = (const float*)d_in[20];
    const float* fc1_w    = (const float*)d_in[21];
    const float* fc1_b    = (const float*)d_in[22];
    const float* fc2_w    = (const float*)d_in[23];
    const float* fc2_b    = (const float*)d_in[24];
    const float* fc3_w    = (const float*)d_in[25];
    const float* fc3_b    = (const float*)d_in[26];
    float* out = (float*)d_out;

    float *b1,*b2,*b3,*b4,*b5,*b6,*cp,*pt,*f1,*f2;
    cudaGetSymbolAddress((void**)&b1, g_buf1);
    cudaGetSymbolAddress((void**)&b2, g_buf2);
    cudaGetSymbolAddress((void**)&b3, g_buf3);
    cudaGetSymbolAddress((void**)&b4, g_buf4);
    cudaGetSymbolAddress((void**)&b5, g_buf5);
    cudaGetSymbolAddress((void**)&b6, g_buf6);
    cudaGetSymbolAddress((void**)&cp, g_cpart);
    cudaGetSymbolAddress((void**)&pt, g_part);
    cudaGetSymbolAddress((void**)&f1, g_fc1);
    cudaGetSymbolAddress((void**)&f2, g_fc2);

    const int region_smem = (15488 + 288*36) * 4;
    cudaFuncSetAttribute(region_kernel,
                         cudaFuncAttributeMaxDynamicSharedMemorySize, region_smem);

    // 1. conv1
    conv1_kernel<<<dim3(5,10,BATCH*2), dim3(16,8)>>>(x, conv1_w, conv1_b, b1);

    // 2. region
    region_kernel<<<BATCH*64, 256, region_smem>>>(
        b1, rl_gamma, rl_beta, rl_mean, rl_var, rl_cw, rl_cb,
        bn_gamma, bn_beta, bn_mean, bn_var, b2);

    // 3. conv2: 32->16, 8x8, 80->73 (CIN split 2x16)
    conv_split2<32,16,8,80,80,73,73,4><<<dim3(3,5,BATCH*2), dim3(16,8)>>>(
        b2, conv2_w, cp);
    { int hw = 73*73, tot = BATCH*16*hw;
      combine_relu<<<(tot+255)/256, 256>>>(cp, conv2_b, b3, hw, tot); }

    // 4. conv3: 16->16, 8x8, 73->66 (CIN split 2x8)
    conv_split2<16,8,8,73,73,66,66,4><<<dim3(3,5,BATCH*2), dim3(16,8)>>>(
        b3, conv3_w, cp);
    { int hw = 66*66, tot = BATCH*16*hw;
      combine_relu<<<(tot+255)/256, 256>>>(cp, conv3_b, b4, hw, tot); }

    // 5. conv4: 16->16, 6x6 s2, 66->31 (CIN split 2x8)
    conv_split<16,8,16,6,2,66,66,31,31,4><<<dim3(2,2,BATCH*2), dim3(16,8)>>>(
        b4, conv4_w, cp);
    { int hw = 31*31, tot = BATCH*16*hw;
      combine_relu<<<(tot+255)/256, 256>>>(cp, conv4_b, b5, hw, tot); }

    // 6. conv5: 16->16, 5x5, 31->27 (CIN split 2x8)
    conv_split<16,8,16,5,1,31,31,27,27,8><<<dim3(2,2,BATCH*2), dim3(16,8)>>>(
        b5, conv5_w, cp);
    { int hw = 27*27, tot = BATCH*16*hw;
      combine_relu<<<(tot+255)/256, 256>>>(cp, conv5_b, b6, hw, tot); }

    // 7. fc1: K=11664 split into 12 tiles of 972
    fc_partial<<<dim3(16,12), 128>>>(b6, fc1_w, pt, 4096, 11664, 972);
    fc_reduce<<<512, 256>>>(pt, fc1_b, f1, 4096, 12, 1);

    // 8. fc2: K=4096 split into 16 tiles of 256
    fc_partial<<<dim3(8,16), 128>>>(f1, fc2_w, pt, 2048, 4096, 256);
    fc_reduce<<<256, 256>>>(pt, fc2_b, f2, 2048, 16, 1);

    // 9. fc3 + log_softmax
    fc3_softmax<<<BATCH, 768>>>(f2, fc3_w, fc3_b, out);
}

// round 4
// speedup vs baseline: 1.4359x; 1.0728x over previous
#include <cuda_runtime.h>
#include <cuda_bf16.h>
#include <math.h>

#define BATCH 32
#define EPS 1e-5f

typedef unsigned long long u64;
__device__ __forceinline__ u64 pk2(float v) {
    u64 r; asm("mov.b64 %0,{%1,%1};" : "=l"(r) : "f"(v)); return r;
}
__device__ __forceinline__ float2 unpk(u64 a) {
    float2 f; asm("mov.b64 {%0,%1},%2;" : "=f"(f.x), "=f"(f.y) : "l"(a)); return f;
}
__device__ __forceinline__ void fma2(u64& d, u64 a, u64 b) {
    asm("fma.rn.f32x2 %0,%1,%2,%0;" : "+l"(d) : "l"(a), "l"(b));
}

// ---------------- scratch ----------------
__device__ float g_buf1[BATCH*32*160*160];
__device__ float g_buf2[BATCH*32*80*80];
__device__ float g_buf3[BATCH*16*73*73];
__device__ float g_buf4[BATCH*16*66*66];
__device__ float g_buf5[BATCH*16*31*31];
__device__ float g_buf6[BATCH*16*27*27];
__device__ float g_cpart[2*BATCH*16*73*73];
__device__ float g_part[16*32*4096];
__device__ float g_fc1[BATCH*4096];
__device__ float g_fc2[BATCH*2048];

// =====================================================================
// conv1: [32,3,170,170] -> [32,32,160,160], 11x11  (f32x2 packed)
// =====================================================================
__global__ void __launch_bounds__(128) conv1_kernel(
    const float* __restrict__ x, const float* __restrict__ w,
    const float* __restrict__ bias, float* __restrict__ out)
{
    __shared__ float xs[3*26*42];
    __shared__ float ws[363*16];
    __shared__ float bs[16];
    const int tx = threadIdx.x, ty = threadIdx.y;
    const int tid = ty*16 + tx;
    const int z = blockIdx.z;
    const int b = z >> 1, half = z & 1;

    for (int i = tid; i < 363*16; i += 128) {
        int ckk = i >> 4, oc = i & 15;
        ws[i] = w[(half*16 + oc)*363 + ckk];
    }
    if (tid < 16) bs[tid] = bias[half*16 + tid];

    const int ix0 = blockIdx.x*32;
    const int iy0 = blockIdx.y*16;
    const float* xb = x + (size_t)b*3*170*170;
    for (int i = tid; i < 3*26*42; i += 128) {
        int c = i / (26*42), r = i - c*(26*42);
        int yy = r / 42, xx = r - yy*42;
        xs[i] = xb[((size_t)c*170 + iy0 + yy)*170 + ix0 + xx];
    }
    __syncthreads();

    u64 a00[8], a01[8], a10[8], a11[8];
#pragma unroll
    for (int q = 0; q < 8; q++) {
        u64 bp = *(const u64*)&bs[2*q];
        a00[q]=bp; a01[q]=bp; a10[q]=bp; a11[q]=bp;
    }

    for (int c = 0; c < 3; c++) {
        for (int kh = 0; kh < 11; kh++) {
            const float* x0 = &xs[c*26*42 + (ty+kh)*42 + tx];
            const float* x1 = x0 + 8*42;
            const float* wrow = &ws[(c*121 + kh*11)*16];
#pragma unroll
            for (int kw = 0; kw < 11; kw++) {
                u64 p00 = pk2(x0[kw]),    p01 = pk2(x0[16+kw]);
                u64 p10 = pk2(x1[kw]),    p11 = pk2(x1[16+kw]);
                const ulonglong2* wp = (const ulonglong2*)(wrow + kw*16);
#pragma unroll
                for (int q = 0; q < 4; q++) {
                    ulonglong2 wv = wp[q];
                    fma2(a00[2*q],   p00, wv.x); fma2(a00[2*q+1], p00, wv.y);
                    fma2(a01[2*q],   p01, wv.x); fma2(a01[2*q+1], p01, wv.y);
                    fma2(a10[2*q],   p10, wv.x); fma2(a10[2*q+1], p10, wv.y);
                    fma2(a11[2*q],   p11, wv.x); fma2(a11[2*q+1], p11, wv.y);
                }
            }
        }
    }
    const int ox = ix0 + tx, oy = iy0 + ty;
#pragma unroll
    for (int q = 0; q < 8; q++) {
        int oc = half*16 + 2*q;
        float* op  = out + (((size_t)b*32 + oc)*160 + oy)*160 + ox;
        float* op2 = op + 25600;
        float2 f00 = unpk(a00[q]), f01 = unpk(a01[q]);
        float2 f10 = unpk(a10[q]), f11 = unpk(a11[q]);
        op[0]  = f00.x; op[16]  = f01.x; op[8*160]  = f10.x; op[8*160+16]  = f11.x;
        op2[0] = f00.y; op2[16] = f01.y; op2[8*160] = f10.y; op2[8*160+16] = f11.y;
    }
}

// =====================================================================
// Region layer fused (f32x2 packed over oc pairs)
// =====================================================================
__global__ void __launch_bounds__(256) region_kernel(
    const float* __restrict__ in,
    const float* __restrict__ rl_gamma, const float* __restrict__ rl_beta,
    const float* __restrict__ rl_mean,  const float* __restrict__ rl_var,
    const float* __restrict__ rl_cw,    const float* __restrict__ rl_cb,
    const float* __restrict__ bn_g, const float* __restrict__ bn_b,
    const float* __restrict__ bn_m, const float* __restrict__ bn_v,
    float* __restrict__ out)
{
    extern __shared__ float sm[];
    float* act = sm;                   // 32*484
    float* wsT = sm + 15488;           // 288*36
    __shared__ float sc[32], sh[32], s2[32], t2[32], cb[32];

    const int blk = blockIdx.x;
    const int b = blk >> 6;
    const int patch = blk & 63;
    const int gi = patch >> 3, gj = patch & 7;
    const int k = gj*(gi+1);
    const int tid = threadIdx.x;

    if (tid < 32) {
        float g = rl_gamma[k*32+tid];
        float s = g * rsqrtf(rl_var[k*32+tid] + EPS);
        sc[tid] = s;
        sh[tid] = rl_beta[k*32+tid] - rl_mean[k*32+tid]*s;
        float ss = bn_g[tid] * rsqrtf(bn_v[tid] + EPS);
        s2[tid] = ss;
        t2[tid] = bn_b[tid] - bn_m[tid]*ss;
        cb[tid] = rl_cb[k*32+tid];
    }
    for (int i = tid; i < 15488; i += 256) act[i] = 0.f;
    __syncthreads();

    const float* inb = in + (size_t)b*32*160*160;
    for (int i = tid; i < 32*400; i += 256) {
        int ic = i / 400, r = i - ic*400;
        int y = r / 20, xx = r - y*20;
        float v = inb[((size_t)ic*160 + gi*20 + y)*160 + gj*20 + xx];
        act[ic*484 + (y+1)*22 + (xx+1)] = fmaxf(fmaf(v, sc[ic], sh[ic]), 0.f);
    }
    for (int i = tid; i < 9216; i += 256) {
        int oc = i / 288, r = i - oc*288;
        wsT[r*36 + oc] = rl_cw[(size_t)k*9216 + i];
    }
    __syncthreads();

    for (int item = tid; item < 800; item += 256) {
        int ocq = item / 100, pos = item - ocq*100;
        int oc0 = ocq*4;
        int py = pos / 10, px = pos - py*10;
        int yb = 2*py, xb = 2*px;

        // accp[ocp][pix]: pair over (oc0+2ocp, oc0+2ocp+1)
        u64 accp[2][4];
#pragma unroll
        for (int ocp = 0; ocp < 2; ocp++) {
            u64 bp = *(const u64*)&cb[oc0 + 2*ocp];
            accp[ocp][0]=bp; accp[ocp][1]=bp; accp[ocp][2]=bp; accp[ocp][3]=bp;
        }

        for (int ic = 0; ic < 32; ic++) {
            // load 4x4 activation window, pre-pack broadcasts
            u64 pa[4][4];
#pragma unroll
            for (int dy = 0; dy < 4; dy++) {
                const float2* rp = (const float2*)&act[ic*484 + (yb+dy)*22 + xb];
                float2 v0 = rp[0], v1 = rp[1];
                pa[dy][0]=pk2(v0.x); pa[dy][1]=pk2(v0.y);
                pa[dy][2]=pk2(v1.x); pa[dy][3]=pk2(v1.y);
            }
            const float* wr = &wsT[(ic*9)*36 + oc0];
#pragma unroll
            for (int kk = 0; kk < 9; kk++) {
                int ky = kk/3, kx = kk - ky*3;
                ulonglong2 wv = *(const ulonglong2*)(wr + kk*36);
                u64 e00 = pa[ky][kx],   e01 = pa[ky][kx+1];
                u64 e10 = pa[ky+1][kx], e11 = pa[ky+1][kx+1];
                fma2(accp[0][0], wv.x, e00); fma2(accp[0][1], wv.x, e01);
                fma2(accp[0][2], wv.x, e10); fma2(accp[0][3], wv.x, e11);
                fma2(accp[1][0], wv.y, e00); fma2(accp[1][1], wv.y, e01);
                fma2(accp[1][2], wv.y, e10); fma2(accp[1][3], wv.y, e11);
            }
        }
        float acc[4][4];
#pragma unroll
        for (int ocp = 0; ocp < 2; ocp++)
#pragma unroll
            for (int p = 0; p < 4; p++) {
                float2 f = unpk(accp[ocp][p]);
                acc[2*ocp][p] = f.x; acc[2*ocp+1][p] = f.y;
            }
#pragma unroll
        for (int o = 0; o < 4; o++) {
            int oc = oc0 + o;
            const float* xrb = inb + ((size_t)oc*160 + gi*20 + yb)*160 + gj*20 + xb;
            float v0 = fmaxf(acc[o][0] + xrb[0], 0.f);
            float v1 = fmaxf(acc[o][1] + xrb[1], 0.f);
            float v2 = fmaxf(acc[o][2] + xrb[160], 0.f);
            float v3 = fmaxf(acc[o][3] + xrb[161], 0.f);
            float mx = fmaxf(fmaxf(v0, v1), fmaxf(v2, v3));
            out[(((size_t)b*32 + oc)*80 + gi*10 + py)*80 + gj*10 + px] =
                fmaf(mx, s2[oc], t2[oc]);
        }
    }
}

// =====================================================================
// conv2/conv3 partial (f32x2), CIN split
// =====================================================================
template<int CIN, int CINH, int KS, int HIN, int WIN, int HOUT, int WOUT, int ICC>
__global__ void __launch_bounds__(128) conv_split2(
    const float* __restrict__ in, const float* __restrict__ w,
    float* __restrict__ part)
{
    constexpr int TIW = 32 + KS - 1;
    constexpr int TIH = 16 + KS - 1;
    __shared__ float xs[ICC*TIH*TIW];
    __shared__ float ws[ICC*KS*KS*16];

    const int tx = threadIdx.x, ty = threadIdx.y;
    const int tid = ty*16 + tx;
    const int z = blockIdx.z;
    const int b = z >> 1, split = z & 1;
    const int c0 = split*CINH;
    const int ix0 = blockIdx.x*32, iy0 = blockIdx.y*16;

    u64 a00[8], a01[8], a10[8], a11[8];
#pragma unroll
    for (int q = 0; q < 8; q++) { a00[q]=0ull; a01[q]=0ull; a10[q]=0ull; a11[q]=0ull; }

    for (int cc = c0; cc < c0 + CINH; cc += ICC) {
        __syncthreads();
        for (int i = tid; i < ICC*TIH*TIW; i += 128) {
            int icl = i / (TIH*TIW), r = i - icl*(TIH*TIW);
            int yy = r / TIW, xx = r - yy*TIW;
            int gy = iy0 + yy, gx = ix0 + xx;
            float v = 0.f;
            if (gy < HIN && gx < WIN)
                v = in[(((size_t)b*CIN + cc + icl)*HIN + gy)*WIN + gx];
            xs[i] = v;
        }
        for (int i = tid; i < ICC*KS*KS*16; i += 128) {
            int oc = i & 15, r = i >> 4;
            int icl = r / (KS*KS), kk = r - icl*(KS*KS);
            ws[i] = w[((size_t)oc*CIN + cc + icl)*KS*KS + kk];
        }
        __syncthreads();
#pragma unroll 1
        for (int icl = 0; icl < ICC; icl++) {
            for (int kh = 0; kh < KS; kh++) {
                const float* x0 = &xs[icl*TIH*TIW + (ty+kh)*TIW + tx];
                const float* x1 = x0 + 8*TIW;
                const float* wrow = &ws[(icl*KS*KS + kh*KS)*16];
#pragma unroll
                for (int kw = 0; kw < KS; kw++) {
                    u64 p00 = pk2(x0[kw]),    p01 = pk2(x0[16+kw]);
                    u64 p10 = pk2(x1[kw]),    p11 = pk2(x1[16+kw]);
                    const ulonglong2* wp = (const ulonglong2*)(wrow + kw*16);
#pragma unroll
                    for (int q = 0; q < 4; q++) {
                        ulonglong2 wv = wp[q];
                        fma2(a00[2*q],   p00, wv.x); fma2(a00[2*q+1], p00, wv.y);
                        fma2(a01[2*q],   p01, wv.x); fma2(a01[2*q+1], p01, wv.y);
                        fma2(a10[2*q],   p10, wv.x); fma2(a10[2*q+1], p10, wv.y);
                        fma2(a11[2*q],   p11, wv.x); fma2(a11[2*q+1], p11, wv.y);
                    }
                }
            }
        }
    }
    const size_t tot = (size_t)BATCH*16*HOUT*WOUT;
    float* pb = part + (size_t)split*tot;
    const int ox0 = ix0 + tx, oy0 = iy0 + ty;
#pragma unroll
    for (int q = 0; q < 8; q++) {
        float2 f00 = unpk(a00[q]), f01 = unpk(a01[q]);
        float2 f10 = unpk(a10[q]), f11 = unpk(a11[q]);
#pragma unroll
        for (int h = 0; h < 2; h++) {
            int oc = 2*q + h;
            float v00 = h ? f00.y : f00.x, v01 = h ? f01.y : f01.x;
            float v10 = h ? f10.y : f10.x, v11 = h ? f11.y : f11.x;
            float* op = pb + (((size_t)b*16 + oc)*HOUT + oy0)*WOUT + ox0;
            if (oy0 < HOUT) {
                if (ox0      < WOUT) op[0]  = v00;
                if (ox0 + 16 < WOUT) op[16] = v01;
            }
            if (oy0 + 8 < HOUT) {
                if (ox0      < WOUT) op[8*(size_t)WOUT]      = v10;
                if (ox0 + 16 < WOUT) op[8*(size_t)WOUT + 16] = v11;
            }
        }
    }
}

// =====================================================================
// conv4/conv5 partial (f32x2), 16x16 tile, CIN split
// =====================================================================
template<int CIN, int CINH, int KS, int STRIDE, int HIN, int WIN,
         int HOUT, int WOUT, int ICC>
__global__ void __launch_bounds__(128) conv_split(
    const float* __restrict__ in, const float* __restrict__ w,
    float* __restrict__ part)
{
    constexpr int TIN = 15*STRIDE + KS;
    __shared__ float xs[ICC*TIN*TIN];
    __shared__ float ws[ICC*KS*KS*16];

    const int tx = threadIdx.x, ty = threadIdx.y;
    const int tid = ty*16 + tx;
    const int z = blockIdx.z;
    const int b = z >> 1, split = z & 1;
    const int c0 = split*CINH;
    const int oy0 = blockIdx.y*16 + ty;
    const int ox  = blockIdx.x*16 + tx;
    const int iy0 = blockIdx.y*16*STRIDE;
    const int ix0 = blockIdx.x*16*STRIDE;

    u64 acc0[8], acc1[8];
#pragma unroll
    for (int q = 0; q < 8; q++) { acc0[q]=0ull; acc1[q]=0ull; }

    for (int cc = c0; cc < c0 + CINH; cc += ICC) {
        __syncthreads();
        for (int i = tid; i < ICC*TIN*TIN; i += 128) {
            int icl = i / (TIN*TIN), r = i - icl*(TIN*TIN);
            int yy = r / TIN, xx = r - yy*TIN;
            int gy = iy0 + yy, gx = ix0 + xx;
            float v = 0.f;
            if (gy < HIN && gx < WIN)
                v = in[(((size_t)b*CIN + cc + icl)*HIN + gy)*WIN + gx];
            xs[i] = v;
        }
        for (int i = tid; i < ICC*KS*KS*16; i += 128) {
            int oc = i & 15; int r = i >> 4;
            int icl = r / (KS*KS); int kk = r - icl*(KS*KS);
            ws[i] = w[((size_t)oc*CIN + cc + icl)*KS*KS + kk];
        }
        __syncthreads();
#pragma unroll 1
        for (int icl = 0; icl < ICC; icl++) {
            for (int kh = 0; kh < KS; kh++) {
                const float* x0 = &xs[icl*TIN*TIN + (ty*STRIDE + kh)*TIN + tx*STRIDE];
                const float* x1 = &xs[icl*TIN*TIN + ((ty+8)*STRIDE + kh)*TIN + tx*STRIDE];
                const float* wrow = &ws[(icl*KS*KS + kh*KS)*16];
#pragma unroll
                for (int kw = 0; kw < KS; kw++) {
                    u64 p0 = pk2(x0[kw]);
                    u64 p1 = pk2(x1[kw]);
                    const ulonglong2* wp = (const ulonglong2*)(wrow + kw*16);
#pragma unroll
                    for (int q = 0; q < 4; q++) {
                        ulonglong2 wv = wp[q];
                        fma2(acc0[2*q],   p0, wv.x); fma2(acc0[2*q+1], p0, wv.y);
                        fma2(acc1[2*q],   p1, wv.x); fma2(acc1[2*q+1], p1, wv.y);
                    }
                }
            }
        }
    }
    const size_t tot = (size_t)BATCH*16*HOUT*WOUT;
    float* pb = part + (size_t)split*tot;
    if (ox < WOUT) {
#pragma unroll
        for (int q = 0; q < 8; q++) {
            float2 f0 = unpk(acc0[q]), f1 = unpk(acc1[q]);
#pragma unroll
            for (int h = 0; h < 2; h++) {
                int oc = 2*q + h;
                float v0 = h ? f0.y : f0.x;
                float v1 = h ? f1.y : f1.x;
                if (oy0 < HOUT)
                    pb[(((size_t)b*16 + oc)*HOUT + oy0)*WOUT + ox] = v0;
                if (oy0 + 8 < HOUT)
                    pb[(((size_t)b*16 + oc)*HOUT + oy0 + 8)*WOUT + ox] = v1;
            }
        }
    }
}

// combine two CIN-split partials + bias + relu (COUT = 16)
__global__ void combine_relu(const float* __restrict__ p,
                             const float* __restrict__ bias,
                             float* __restrict__ out, int HW, int total)
{
    int i = blockIdx.x*256 + threadIdx.x;
    if (i >= total) return;
    int oc = (i / HW) & 15;
    out[i] = fmaxf(p[i] + p[i + total] + bias[oc], 0.f);
}

// =====================================================================
// fc partial / reduce / fc3
// =====================================================================
#define FC_CHUNK 160
__global__ void __launch_bounds__(128) fc_partial(
    const float* __restrict__ x, const float* __restrict__ w,
    float* __restrict__ part, int N, int K, int ktlen)
{
    __shared__ float xs[32*FC_CHUNK];
    const int tid = threadIdx.x;
    const int n0 = blockIdx.x*256 + tid;
    const int n1 = n0 + 128;
    const int k0 = blockIdx.y*ktlen;

    float acc0[32], acc1[32];
#pragma unroll
    for (int m = 0; m < 32; m++) { acc0[m]=0.f; acc1[m]=0.f; }

    for (int kc = 0; kc < ktlen; kc += FC_CHUNK) {
        int cl = min(FC_CHUNK, ktlen - kc);
        __syncthreads();
        for (int i = tid; i < 32*cl; i += 128) {
            int m = i / cl, kk = i - m*cl;
            xs[m*FC_CHUNK + kk] = x[(size_t)m*K + k0 + kc + kk];
        }
        __syncthreads();
        const float* w0 = w + (size_t)n0*K + k0 + kc;
        const float* w1 = w + (size_t)n1*K + k0 + kc;
        for (int kk = 0; kk < cl; kk += 2) {
            float2 a0 = *(const float2*)(w0 + kk);
            float2 a1 = *(const float2*)(w1 + kk);
#pragma unroll
            for (int m = 0; m < 32; m++) {
                float2 xv = *(const float2*)&xs[m*FC_CHUNK + kk];
                acc0[m] = fmaf(a0.x, xv.x, fmaf(a0.y, xv.y, acc0[m]));
                acc1[m] = fmaf(a1.x, xv.x, fmaf(a1.y, xv.y, acc1[m]));
            }
        }
    }
    float* pr = part + (size_t)blockIdx.y*32*N;
#pragma unroll
    for (int m = 0; m < 32; m++) {
        pr[(size_t)m*N + n0] = acc0[m];
        pr[(size_t)m*N + n1] = acc1[m];
    }
}

__global__ void fc_reduce(const float* __restrict__ part,
                          const float* __restrict__ bias,
                          float* __restrict__ out, int N, int KT, int do_relu)
{
    int i = blockIdx.x*256 + threadIdx.x;
    if (i >= 32*N) return;
    int n = i % N;
    float s = bias[n];
    for (int kt = 0; kt < KT; kt++) s += part[(size_t)kt*32*N + i];
    out[i] = do_relu ? fmaxf(s, 0.f) : s;
}

__global__ void __launch_bounds__(768) fc3_softmax(
    const float* __restrict__ x, const float* __restrict__ w,
    const float* __restrict__ bias, float* __restrict__ out)
{
    __shared__ float lg[24];
    const int b = blockIdx.x;
    const int tid = threadIdx.x;
    const int wo = tid >> 5, lane = tid & 31;

    const float* xr = x + (size_t)b*2048;
    const float* wr = w + (size_t)wo*2048;
    float s = 0.f;
    for (int k = lane; k < 2048; k += 32) s = fmaf(wr[k], xr[k], s);
#pragma unroll
    for (int off = 16; off; off >>= 1) s += __shfl_xor_sync(0xffffffffu, s, off);
    if (lane == 0) lg[wo] = s + bias[wo];
    __syncthreads();

    if (tid < 24) {
        int a = tid % 12;
        float z0 = lg[a], z1 = lg[12 + a];
        float m = fmaxf(z0, z1);
        float lse = m + logf(expf(z0 - m) + expf(z1 - m));
        out[b*24 + tid] = lg[tid] - lse;
    }
}

// =====================================================================
// launch
// =====================================================================
extern "C" void kernel_launch(void* const* d_in, const int* in_sizes, int n_in,
                              void* d_out, int out_size)
{
    const float* x        = (const float*)d_in[0];
    const float* conv1_w  = (const float*)d_in[1];
    const float* conv1_b  = (const float*)d_in[2];
    const float* rl_gamma = (const float*)d_in[3];
    const float* rl_beta  = (const float*)d_in[4];
    const float* rl_mean  = (const float*)d_in[5];
    const float* rl_var   = (const float*)d_in[6];
    const float* rl_cw    = (const float*)d_in[7];
    const float* rl_cb    = (const float*)d_in[8];
    const float* bn_gamma = (const float*)d_in[9];
    const float* bn_beta  = (const float*)d_in[10];
    const float* bn_mean  = (const float*)d_in[11];
    const float* bn_var   = (const float*)d_in[12];
    const float* conv2_w  = (const float*)d_in[13];
    const float* conv2_b  = (const float*)d_in[14];
    const float* conv3_w  = (const float*)d_in[15];
    const float* conv3_b  = (const float*)d_in[16];
    const float* conv4_w  = (const float*)d_in[17];
    const float* conv4_b  = (const float*)d_in[18];
    const float* conv5_w  = (const float*)d_in[19];
    const float* conv5_b  = (const float*)d_in[20];
    const float* fc1_w    = (const float*)d_in[21];
    const float* fc1_b    = (const float*)d_in[22];
    const float* fc2_w    = (const float*)d_in[23];
    const float* fc2_b    = (const float*)d_in[24];
    const float* fc3_w    = (const float*)d_in[25];
    const float* fc3_b    = (const float*)d_in[26];
    float* out = (float*)d_out;

    float *b1,*b2,*b3,*b4,*b5,*b6,*cp,*pt,*f1,*f2;
    cudaGetSymbolAddress((void**)&b1, g_buf1);
    cudaGetSymbolAddress((void**)&b2, g_buf2);
    cudaGetSymbolAddress((void**)&b3, g_buf3);
    cudaGetSymbolAddress((void**)&b4, g_buf4);
    cudaGetSymbolAddress((void**)&b5, g_buf5);
    cudaGetSymbolAddress((void**)&b6, g_buf6);
    cudaGetSymbolAddress((void**)&cp, g_cpart);
    cudaGetSymbolAddress((void**)&pt, g_part);
    cudaGetSymbolAddress((void**)&f1, g_fc1);
    cudaGetSymbolAddress((void**)&f2, g_fc2);

    const int region_smem = (15488 + 288*36) * 4;
    cudaFuncSetAttribute(region_kernel,
                         cudaFuncAttributeMaxDynamicSharedMemorySize, region_smem);

    // 1. conv1
    conv1_kernel<<<dim3(5,10,BATCH*2), dim3(16,8)>>>(x, conv1_w, conv1_b, b1);

    // 2. region
    region_kernel<<<BATCH*64, 256, region_smem>>>(
        b1, rl_gamma, rl_beta, rl_mean, rl_var, rl_cw, rl_cb,
        bn_gamma, bn_beta, bn_mean, bn_var, b2);

    // 3. conv2: 32->16, 8x8, 80->73 (CIN split 2x16)
    conv_split2<32,16,8,80,80,73,73,4><<<dim3(3,5,BATCH*2), dim3(16,8)>>>(
        b2, conv2_w, cp);
    { int hw = 73*73, tot = BATCH*16*hw;
      combine_relu<<<(tot+255)/256, 256>>>(cp, conv2_b, b3, hw, tot); }

    // 4. conv3: 16->16, 8x8, 73->66 (CIN split 2x8)
    conv_split2<16,8,8,73,73,66,66,4><<<dim3(3,5,BATCH*2), dim3(16,8)>>>(
        b3, conv3_w, cp);
    { int hw = 66*66, tot = BATCH*16*hw;
      combine_relu<<<(tot+255)/256, 256>>>(cp, conv3_b, b4, hw, tot); }

    // 5. conv4: 16->16, 6x6 s2, 66->31 (CIN split 2x8)
    conv_split<16,8,6,2,66,66,31,31,4><<<dim3(2,2,BATCH*2), dim3(16,8)>>>(
        b4, conv4_w, cp);
    { int hw = 31*31, tot = BATCH*16*hw;
      combine_relu<<<(tot+255)/256, 256>>>(cp, conv4_b, b5, hw, tot); }

    // 6. conv5: 16->16, 5x5, 31->27 (CIN split 2x8)
    conv_split<16,8,5,1,31,31,27,27,8><<<dim3(2,2,BATCH*2), dim3(16,8)>>>(
        b5, conv5_w, cp);
    { int hw = 27*27, tot = BATCH*16*hw;
      combine_relu<<<(tot+255)/256, 256>>>(cp, conv5_b, b6, hw, tot); }

    // 7. fc1: K=11664 split into 12 tiles of 972
    fc_partial<<<dim3(16,12), 128>>>(b6, fc1_w, pt, 4096, 11664, 972);
    fc_reduce<<<512, 256>>>(pt, fc1_b, f1, 4096, 12, 1);

    // 8. fc2: K=4096 split into 16 tiles of 256
    fc_partial<<<dim3(8,16), 128>>>(f1, fc2_w, pt, 2048, 4096, 256);
    fc_reduce<<<256, 256>>>(pt, fc2_b, f2, 2048, 16, 1);

    // 9. fc3 + log_softmax
    fc3_softmax<<<BATCH, 768>>>(f2, fc3_w, fc3_b, out);
}

// round 5
// speedup vs baseline: 1.8784x; 1.3082x over previous
#include <cuda_runtime.h>
#include <cuda_bf16.h>
#include <math.h>
#include <stdint.h>

#define BATCH 32
#define EPS 1e-5f

typedef unsigned long long u64;
__device__ __forceinline__ u64 pk2(float v) {
    u64 r; asm("mov.b64 %0,{%1,%1};" : "=l"(r) : "f"(v)); return r;
}
__device__ __forceinline__ float2 unpk(u64 a) {
    float2 f; asm("mov.b64 {%0,%1},%2;" : "=f"(f.x), "=f"(f.y) : "l"(a)); return f;
}
__device__ __forceinline__ void fma2(u64& d, u64 a, u64 b) {
    asm("fma.rn.f32x2 %0,%1,%2,%0;" : "+l"(d) : "l"(a), "l"(b));
}
__device__ __forceinline__ uint32_t f2tf(float f) {
    uint32_t r; asm("cvt.rna.tf32.f32 %0,%1;" : "=r"(r) : "f"(f)); return r;
}
// D += A(16x8,row) * B(8x8,col), tf32 inputs, fp32 accum
__device__ __forceinline__ void mma8(float* c, uint32_t a0, uint32_t a1,
                                     uint32_t a2, uint32_t a3,
                                     uint32_t b0, uint32_t b1) {
    asm("mma.sync.aligned.m16n8k8.row.col.f32.tf32.tf32.f32 "
        "{%0,%1,%2,%3},{%4,%5,%6,%7},{%8,%9},{%0,%1,%2,%3};"
        : "+f"(c[0]), "+f"(c[1]), "+f"(c[2]), "+f"(c[3])
        : "r"(a0), "r"(a1), "r"(a2), "r"(a3), "r"(b0), "r"(b1));
}

// ---------------- scratch ----------------
__device__ float g_buf1[BATCH*32*160*160];
__device__ float g_buf2[BATCH*32*80*80];
__device__ float g_buf3[BATCH*16*73*73];
__device__ float g_buf4[BATCH*16*66*66];
__device__ float g_buf5[BATCH*16*31*31];
__device__ float g_buf6[BATCH*16*27*27];
__device__ float g_cpart[2*BATCH*16*73*73];
__device__ float g_part[16*32*4096];
__device__ float g_fc1[BATCH*4096];
__device__ float g_fc2[BATCH*2048];

// =====================================================================
// conv1 (tf32 tensor cores): [32,3,170,170] -> [32,32,160,160], 11x11
// implicit GEMM: M = 16x32 pixel tile, N = 32 oc, K = 363 (pad 368)
// m16 tile = 16 consecutive x pixels of one output row.
// dyn smem: xs[3*26*42] ws[368*32] lut[368] bs[32]
// =====================================================================
__global__ void __launch_bounds__(256) conv1_tc(
    const float* __restrict__ x, const float* __restrict__ w,
    const float* __restrict__ bias, float* __restrict__ out)
{
    extern __shared__ uint32_t sm_u[];
    uint32_t* xs = sm_u;               // 3276
    uint32_t* ws = sm_u + 3276;        // 11776
    int* lut = (int*)(ws + 11776);     // 368
    float* bs = (float*)(lut + 368);   // 32

    const int tid = threadIdx.x, lane = tid & 31, wp = tid >> 5;
    const int b = blockIdx.z;
    const int iy0 = blockIdx.y*16, ix0 = blockIdx.x*32;

    for (int i = tid; i < 368; i += 256) {
        int v = 0;
        if (i < 363) {
            int c = i/121, r = i - c*121, kh = r/11, kw = r - kh*11;
            v = c*(26*42) + kh*42 + kw;
        }
        lut[i] = v;
    }
    for (int i = tid; i < 32*368; i += 256) {
        int oc = i / 368, k = i - oc*368;
        float v = (k < 363) ? w[oc*363 + k] : 0.f;
        ws[k*32 + oc] = f2tf(v);
    }
    const float* xb = x + (size_t)b*3*170*170;
    for (int i = tid; i < 3*26*42; i += 256) {
        int c = i / (26*42), r = i - c*(26*42), yy = r/42, xx = r - yy*42;
        xs[i] = f2tf(xb[((size_t)c*170 + iy0 + yy)*170 + ix0 + xx]);
    }
    if (tid < 32) bs[tid] = bias[tid];
    __syncthreads();

    float acc[4][4][4];
#pragma unroll
    for (int m = 0; m < 4; m++)
#pragma unroll
        for (int n = 0; n < 4; n++)
#pragma unroll
            for (int q = 0; q < 4; q++) acc[m][n][q] = 0.f;

    const int gr = lane >> 2, gc = lane & 3;
    int mb[4];
#pragma unroll
    for (int i = 0; i < 4; i++) {
        int t = wp*4 + i;
        mb[i] = (t >> 1)*42 + (t & 1)*16 + gr;
    }

    for (int k0 = 0; k0 < 368; k0 += 8) {
        int o1 = lut[k0 + gc], o2 = lut[k0 + gc + 4];
        const uint32_t* wk = &ws[(k0 + gc)*32 + gr];
        uint32_t bf0[4], bf1[4];
#pragma unroll
        for (int nt = 0; nt < 4; nt++) { bf0[nt] = wk[nt*8]; bf1[nt] = wk[128 + nt*8]; }
#pragma unroll
        for (int mt = 0; mt < 4; mt++) {
            uint32_t a0 = xs[mb[mt] + o1], a1 = xs[mb[mt] + 8 + o1];
            uint32_t a2 = xs[mb[mt] + o2], a3 = xs[mb[mt] + 8 + o2];
#pragma unroll
            for (int nt = 0; nt < 4; nt++)
                mma8(acc[mt][nt], a0, a1, a2, a3, bf0[nt], bf1[nt]);
        }
    }
#pragma unroll
    for (int mt = 0; mt < 4; mt++) {
        int t = wp*4 + mt;
        int yp = iy0 + (t >> 1), xp = ix0 + (t & 1)*16 + gr;
#pragma unroll
        for (int nt = 0; nt < 4; nt++) {
            int oc = nt*8 + gc*2;
            float* o0 = out + (((size_t)b*32 + oc)*160 + yp)*160 + xp;
            o0[0]     = acc[mt][nt][0] + bs[oc];
            o0[25600] = acc[mt][nt][1] + bs[oc+1];
            o0[8]     = acc[mt][nt][2] + bs[oc];
            o0[25608] = acc[mt][nt][3] + bs[oc+1];
        }
    }
}

// =====================================================================
// conv2/conv3 (tf32 tensor cores): 8x8 kernel, COUT=16, CIN chunked by 8
// tile 16x32 px; K-chunk = 8*64 = 512; bias+relu fused at store
// dyn smem: xs[8*23*39]=7176 ws[512*16]=8192 lut[512] bs[16]
// =====================================================================
template<int CIN, int HIN, int WIN, int HOUT, int WOUT>
__global__ void __launch_bounds__(256) conv_tc8(
    const float* __restrict__ in, const float* __restrict__ w,
    const float* __restrict__ bias, float* __restrict__ out)
{
    constexpr int TIH = 23, TIW = 39;
    extern __shared__ uint32_t sm_u[];
    uint32_t* xs = sm_u;               // 7176
    uint32_t* ws = sm_u + 7176;        // 8192
    int* lut = (int*)(ws + 8192);      // 512
    float* bs = (float*)(lut + 512);   // 16

    const int tid = threadIdx.x, lane = tid & 31, wp = tid >> 5;
    const int b = blockIdx.z;
    const int iy0 = blockIdx.y*16, ix0 = blockIdx.x*32;

    for (int i = tid; i < 512; i += 256) {
        int cl = i >> 6, r = i & 63, kh = r >> 3, kw = r & 7;
        lut[i] = cl*(TIH*TIW) + kh*TIW + kw;
    }
    if (tid < 16) bs[tid] = bias[tid];

    float acc[4][2][4];
#pragma unroll
    for (int m = 0; m < 4; m++)
#pragma unroll
        for (int n = 0; n < 2; n++)
#pragma unroll
            for (int q = 0; q < 4; q++) acc[m][n][q] = 0.f;

    const int gr = lane >> 2, gc = lane & 3;
    int mb[4];
#pragma unroll
    for (int i = 0; i < 4; i++) {
        int t = wp*4 + i;
        mb[i] = (t >> 1)*TIW + (t & 1)*16 + gr;
    }

    for (int cc = 0; cc < CIN; cc += 8) {
        __syncthreads();
        for (int i = tid; i < 8*TIH*TIW; i += 256) {
            int cl = i / (TIH*TIW), r = i - cl*(TIH*TIW);
            int yy = r / TIW, xx = r - yy*TIW;
            int gy = iy0 + yy, gx = ix0 + xx;
            float v = 0.f;
            if (gy < HIN && gx < WIN)
                v = in[(((size_t)b*CIN + cc + cl)*HIN + gy)*WIN + gx];
            xs[i] = f2tf(v);
        }
        for (int i = tid; i < 16*512; i += 256) {
            int oc = i >> 9, kl = i & 511;
            int cl = kl >> 6, kk = kl & 63;
            ws[kl*16 + oc] = f2tf(w[((size_t)oc*CIN + cc + cl)*64 + kk]);
        }
        __syncthreads();

        for (int k0 = 0; k0 < 512; k0 += 8) {
            int o1 = lut[k0 + gc], o2 = lut[k0 + gc + 4];
            const uint32_t* wk = &ws[(k0 + gc)*16 + gr];
            uint32_t bf0[2], bf1[2];
#pragma unroll
            for (int nt = 0; nt < 2; nt++) { bf0[nt] = wk[nt*8]; bf1[nt] = wk[64 + nt*8]; }
#pragma unroll
            for (int mt = 0; mt < 4; mt++) {
                uint32_t a0 = xs[mb[mt] + o1], a1 = xs[mb[mt] + 8 + o1];
                uint32_t a2 = xs[mb[mt] + o2], a3 = xs[mb[mt] + 8 + o2];
#pragma unroll
                for (int nt = 0; nt < 2; nt++)
                    mma8(acc[mt][nt], a0, a1, a2, a3, bf0[nt], bf1[nt]);
            }
        }
    }

    const size_t cstride = (size_t)HOUT*WOUT;
#pragma unroll
    for (int mt = 0; mt < 4; mt++) {
        int t = wp*4 + mt;
        int yp = iy0 + (t >> 1), xp = ix0 + (t & 1)*16 + gr;
        if (yp < HOUT) {
#pragma unroll
            for (int nt = 0; nt < 2; nt++) {
                int oc = nt*8 + gc*2;
                float* o0 = out + (((size_t)b*16 + oc)*HOUT + yp)*WOUT + xp;
                if (xp < WOUT) {
                    o0[0]       = fmaxf(acc[mt][nt][0] + bs[oc],   0.f);
                    o0[cstride] = fmaxf(acc[mt][nt][1] + bs[oc+1], 0.f);
                }
                if (xp + 8 < WOUT) {
                    o0[8]         = fmaxf(acc[mt][nt][2] + bs[oc],   0.f);
                    o0[cstride+8] = fmaxf(acc[mt][nt][3] + bs[oc+1], 0.f);
                }
            }
        }
    }
}

// =====================================================================
// Region layer fused (f32x2 packed) — unchanged
// =====================================================================
__global__ void __launch_bounds__(256) region_kernel(
    const float* __restrict__ in,
    const float* __restrict__ rl_gamma, const float* __restrict__ rl_beta,
    const float* __restrict__ rl_mean,  const float* __restrict__ rl_var,
    const float* __restrict__ rl_cw,    const float* __restrict__ rl_cb,
    const float* __restrict__ bn_g, const float* __restrict__ bn_b,
    const float* __restrict__ bn_m, const float* __restrict__ bn_v,
    float* __restrict__ out)
{
    extern __shared__ float sm[];
    float* act = sm;                   // 32*484
    float* wsT = sm + 15488;           // 288*36
    __shared__ float sc[32], sh[32], s2[32], t2[32], cb[32];

    const int blk = blockIdx.x;
    const int b = blk >> 6;
    const int patch = blk & 63;
    const int gi = patch >> 3, gj = patch & 7;
    const int k = gj*(gi+1);
    const int tid = threadIdx.x;

    if (tid < 32) {
        float g = rl_gamma[k*32+tid];
        float s = g * rsqrtf(rl_var[k*32+tid] + EPS);
        sc[tid] = s;
        sh[tid] = rl_beta[k*32+tid] - rl_mean[k*32+tid]*s;
        float ss = bn_g[tid] * rsqrtf(bn_v[tid] + EPS);
        s2[tid] = ss;
        t2[tid] = bn_b[tid] - bn_m[tid]*ss;
        cb[tid] = rl_cb[k*32+tid];
    }
    for (int i = tid; i < 15488; i += 256) act[i] = 0.f;
    __syncthreads();

    const float* inb = in + (size_t)b*32*160*160;
    for (int i = tid; i < 32*400; i += 256) {
        int ic = i / 400, r = i - ic*400;
        int y = r / 20, xx = r - y*20;
        float v = inb[((size_t)ic*160 + gi*20 + y)*160 + gj*20 + xx];
        act[ic*484 + (y+1)*22 + (xx+1)] = fmaxf(fmaf(v, sc[ic], sh[ic]), 0.f);
    }
    for (int i = tid; i < 9216; i += 256) {
        int oc = i / 288, r = i - oc*288;
        wsT[r*36 + oc] = rl_cw[(size_t)k*9216 + i];
    }
    __syncthreads();

    for (int item = tid; item < 800; item += 256) {
        int ocq = item / 100, pos = item - ocq*100;
        int oc0 = ocq*4;
        int py = pos / 10, px = pos - py*10;
        int yb = 2*py, xb = 2*px;

        u64 accp[2][4];
#pragma unroll
        for (int ocp = 0; ocp < 2; ocp++) {
            u64 bp = *(const u64*)&cb[oc0 + 2*ocp];
            accp[ocp][0]=bp; accp[ocp][1]=bp; accp[ocp][2]=bp; accp[ocp][3]=bp;
        }

        for (int ic = 0; ic < 32; ic++) {
            u64 pa[4][4];
#pragma unroll
            for (int dy = 0; dy < 4; dy++) {
                const float2* rp = (const float2*)&act[ic*484 + (yb+dy)*22 + xb];
                float2 v0 = rp[0], v1 = rp[1];
                pa[dy][0]=pk2(v0.x); pa[dy][1]=pk2(v0.y);
                pa[dy][2]=pk2(v1.x); pa[dy][3]=pk2(v1.y);
            }
            const float* wr = &wsT[(ic*9)*36 + oc0];
#pragma unroll
            for (int kk = 0; kk < 9; kk++) {
                int ky = kk/3, kx = kk - ky*3;
                ulonglong2 wv = *(const ulonglong2*)(wr + kk*36);
                u64 e00 = pa[ky][kx],   e01 = pa[ky][kx+1];
                u64 e10 = pa[ky+1][kx], e11 = pa[ky+1][kx+1];
                fma2(accp[0][0], wv.x, e00); fma2(accp[0][1], wv.x, e01);
                fma2(accp[0][2], wv.x, e10); fma2(accp[0][3], wv.x, e11);
                fma2(accp[1][0], wv.y, e00); fma2(accp[1][1], wv.y, e01);
                fma2(accp[1][2], wv.y, e10); fma2(accp[1][3], wv.y, e11);
            }
        }
        float acc[4][4];
#pragma unroll
        for (int ocp = 0; ocp < 2; ocp++)
#pragma unroll
            for (int p = 0; p < 4; p++) {
                float2 f = unpk(accp[ocp][p]);
                acc[2*ocp][p] = f.x; acc[2*ocp+1][p] = f.y;
            }
#pragma unroll
        for (int o = 0; o < 4; o++) {
            int oc = oc0 + o;
            const float* xrb = inb + ((size_t)oc*160 + gi*20 + yb)*160 + gj*20 + xb;
            float v0 = fmaxf(acc[o][0] + xrb[0], 0.f);
            float v1 = fmaxf(acc[o][1] + xrb[1], 0.f);
            float v2 = fmaxf(acc[o][2] + xrb[160], 0.f);
            float v3 = fmaxf(acc[o][3] + xrb[161], 0.f);
            float mx = fmaxf(fmaxf(v0, v1), fmaxf(v2, v3));
            out[(((size_t)b*32 + oc)*80 + gi*10 + py)*80 + gj*10 + px] =
                fmaf(mx, s2[oc], t2[oc]);
        }
    }
}

// =====================================================================
// conv4/conv5 partial (f32x2), 16x16 tile, CIN split — unchanged
// =====================================================================
template<int CIN, int CINH, int KS, int STRIDE, int HIN, int WIN,
         int HOUT, int WOUT, int ICC>
__global__ void __launch_bounds__(128) conv_split(
    const float* __restrict__ in, const float* __restrict__ w,
    float* __restrict__ part)
{
    constexpr int TIN = 15*STRIDE + KS;
    __shared__ float xs[ICC*TIN*TIN];
    __shared__ float ws[ICC*KS*KS*16];

    const int tx = threadIdx.x, ty = threadIdx.y;
    const int tid = ty*16 + tx;
    const int z = blockIdx.z;
    const int b = z >> 1, split = z & 1;
    const int c0 = split*CINH;
    const int oy0 = blockIdx.y*16 + ty;
    const int ox  = blockIdx.x*16 + tx;
    const int iy0 = blockIdx.y*16*STRIDE;
    const int ix0 = blockIdx.x*16*STRIDE;

    u64 acc0[8], acc1[8];
#pragma unroll
    for (int q = 0; q < 8; q++) { acc0[q]=0ull; acc1[q]=0ull; }

    for (int cc = c0; cc < c0 + CINH; cc += ICC) {
        __syncthreads();
        for (int i = tid; i < ICC*TIN*TIN; i += 128) {
            int icl = i / (TIN*TIN), r = i - icl*(TIN*TIN);
            int yy = r / TIN, xx = r - yy*TIN;
            int gy = iy0 + yy, gx = ix0 + xx;
            float v = 0.f;
            if (gy < HIN && gx < WIN)
                v = in[(((size_t)b*CIN + cc + icl)*HIN + gy)*WIN + gx];
            xs[i] = v;
        }
        for (int i = tid; i < ICC*KS*KS*16; i += 128) {
            int oc = i & 15; int r = i >> 4;
            int icl = r / (KS*KS); int kk = r - icl*(KS*KS);
            ws[i] = w[((size_t)oc*CIN + cc + icl)*KS*KS + kk];
        }
        __syncthreads();
#pragma unroll 1
        for (int icl = 0; icl < ICC; icl++) {
            for (int kh = 0; kh < KS; kh++) {
                const float* x0 = &xs[icl*TIN*TIN + (ty*STRIDE + kh)*TIN + tx*STRIDE];
                const float* x1 = &xs[icl*TIN*TIN + ((ty+8)*STRIDE + kh)*TIN + tx*STRIDE];
                const float* wrow = &ws[(icl*KS*KS + kh*KS)*16];
#pragma unroll
                for (int kw = 0; kw < KS; kw++) {
                    u64 p0 = pk2(x0[kw]);
                    u64 p1 = pk2(x1[kw]);
                    const ulonglong2* wp = (const ulonglong2*)(wrow + kw*16);
#pragma unroll
                    for (int q = 0; q < 4; q++) {
                        ulonglong2 wv = wp[q];
                        fma2(acc0[2*q],   p0, wv.x); fma2(acc0[2*q+1], p0, wv.y);
                        fma2(acc1[2*q],   p1, wv.x); fma2(acc1[2*q+1], p1, wv.y);
                    }
                }
            }
        }
    }
    const size_t tot = (size_t)BATCH*16*HOUT*WOUT;
    float* pb = part + (size_t)split*tot;
    if (ox < WOUT) {
#pragma unroll
        for (int q = 0; q < 8; q++) {
            float2 f0 = unpk(acc0[q]), f1 = unpk(acc1[q]);
#pragma unroll
            for (int h = 0; h < 2; h++) {
                int oc = 2*q + h;
                float v0 = h ? f0.y : f0.x;
                float v1 = h ? f1.y : f1.x;
                if (oy0 < HOUT)
                    pb[(((size_t)b*16 + oc)*HOUT + oy0)*WOUT + ox] = v0;
                if (oy0 + 8 < HOUT)
                    pb[(((size_t)b*16 + oc)*HOUT + oy0 + 8)*WOUT + ox] = v1;
            }
        }
    }
}

__global__ void combine_relu(const float* __restrict__ p,
                             const float* __restrict__ bias,
                             float* __restrict__ out, int HW, int total)
{
    int i = blockIdx.x*256 + threadIdx.x;
    if (i >= total) return;
    int oc = (i / HW) & 15;
    out[i] = fmaxf(p[i] + p[i + total] + bias[oc], 0.f);
}

// =====================================================================
// fc partial / reduce / fc3 — unchanged
// =====================================================================
#define FC_CHUNK 160
__global__ void __launch_bounds__(128) fc_partial(
    const float* __restrict__ x, const float* __restrict__ w,
    float* __restrict__ part, int N, int K, int ktlen)
{
    __shared__ float xs[32*FC_CHUNK];
    const int tid = threadIdx.x;
    const int n0 = blockIdx.x*256 + tid;
    const int n1 = n0 + 128;
    const int k0 = blockIdx.y*ktlen;

    float acc0[32], acc1[32];
#pragma unroll
    for (int m = 0; m < 32; m++) { acc0[m]=0.f; acc1[m]=0.f; }

    for (int kc = 0; kc < ktlen; kc += FC_CHUNK) {
        int cl = min(FC_CHUNK, ktlen - kc);
        __syncthreads();
        for (int i = tid; i < 32*cl; i += 128) {
            int m = i / cl, kk = i - m*cl;
            xs[m*FC_CHUNK + kk] = x[(size_t)m*K + k0 + kc + kk];
        }
        __syncthreads();
        const float* w0 = w + (size_t)n0*K + k0 + kc;
        const float* w1 = w + (size_t)n1*K + k0 + kc;
        for (int kk = 0; kk < cl; kk += 2) {
            float2 a0 = *(const float2*)(w0 + kk);
            float2 a1 = *(const float2*)(w1 + kk);
#pragma unroll
            for (int m = 0; m < 32; m++) {
                float2 xv = *(const float2*)&xs[m*FC_CHUNK + kk];
                acc0[m] = fmaf(a0.x, xv.x, fmaf(a0.y, xv.y, acc0[m]));
                acc1[m] = fmaf(a1.x, xv.x, fmaf(a1.y, xv.y, acc1[m]));
            }
        }
    }
    float* pr = part + (size_t)blockIdx.y*32*N;
#pragma unroll
    for (int m = 0; m < 32; m++) {
        pr[(size_t)m*N + n0] = acc0[m];
        pr[(size_t)m*N + n1] = acc1[m];
    }
}

__global__ void fc_reduce(const float* __restrict__ part,
                          const float* __restrict__ bias,
                          float* __restrict__ out, int N, int KT, int do_relu)
{
    int i = blockIdx.x*256 + threadIdx.x;
    if (i >= 32*N) return;
    int n = i % N;
    float s = bias[n];
    for (int kt = 0; kt < KT; kt++) s += part[(size_t)kt*32*N + i];
    out[i] = do_relu ? fmaxf(s, 0.f) : s;
}

__global__ void __launch_bounds__(768) fc3_softmax(
    const float* __restrict__ x, const float* __restrict__ w,
    const float* __restrict__ bias, float* __restrict__ out)
{
    __shared__ float lg[24];
    const int b = blockIdx.x;
    const int tid = threadIdx.x;
    const int wo = tid >> 5, lane = tid & 31;

    const float* xr = x + (size_t)b*2048;
    const float* wr = w + (size_t)wo*2048;
    float s = 0.f;
    for (int k = lane; k < 2048; k += 32) s = fmaf(wr[k], xr[k], s);
#pragma unroll
    for (int off = 16; off; off >>= 1) s += __shfl_xor_sync(0xffffffffu, s, off);
    if (lane == 0) lg[wo] = s + bias[wo];
    __syncthreads();

    if (tid < 24) {
        int a = tid % 12;
        float z0 = lg[a], z1 = lg[12 + a];
        float m = fmaxf(z0, z1);
        float lse = m + logf(expf(z0 - m) + expf(z1 - m));
        out[b*24 + tid] = lg[tid] - lse;
    }
}

// =====================================================================
// launch
// =====================================================================
extern "C" void kernel_launch(void* const* d_in, const int* in_sizes, int n_in,
                              void* d_out, int out_size)
{
    const float* x        = (const float*)d_in[0];
    const float* conv1_w  = (const float*)d_in[1];
    const float* conv1_b  = (const float*)d_in[2];
    const float* rl_gamma = (const float*)d_in[3];
    const float* rl_beta  = (const float*)d_in[4];
    const float* rl_mean  = (const float*)d_in[5];
    const float* rl_var   = (const float*)d_in[6];
    const float* rl_cw    = (const float*)d_in[7];
    const float* rl_cb    = (const float*)d_in[8];
    const float* bn_gamma = (const float*)d_in[9];
    const float* bn_beta  = (const float*)d_in[10];
    const float* bn_mean  = (const float*)d_in[11];
    const float* bn_var   = (const float*)d_in[12];
    const float* conv2_w  = (const float*)d_in[13];
    const float* conv2_b  = (const float*)d_in[14];
    const float* conv3_w  = (const float*)d_in[15];
    const float* conv3_b  = (const float*)d_in[16];
    const float* conv4_w  = (const float*)d_in[17];
    const float* conv4_b  = (const float*)d_in[18];
    const float* conv5_w  = (const float*)d_in[19];
    const float* conv5_b  = (const float*)d_in[20];
    const float* fc1_w    = (const float*)d_in[21];
    const float* fc1_b    = (const float*)d_in[22];
    const float* fc2_w    = (const float*)d_in[23];
    const float* fc2_b    = (const float*)d_in[24];
    const float* fc3_w    = (const float*)d_in[25];
    const float* fc3_b    = (const float*)d_in[26];
    float* out = (float*)d_out;

    float *b1,*b2,*b3,*b4,*b5,*b6,*cp,*pt,*f1,*f2;
    cudaGetSymbolAddress((void**)&b1, g_buf1);
    cudaGetSymbolAddress((void**)&b2, g_buf2);
    cudaGetSymbolAddress((void**)&b3, g_buf3);
    cudaGetSymbolAddress((void**)&b4, g_buf4);
    cudaGetSymbolAddress((void**)&b5, g_buf5);
    cudaGetSymbolAddress((void**)&b6, g_buf6);
    cudaGetSymbolAddress((void**)&cp, g_cpart);
    cudaGetSymbolAddress((void**)&pt, g_part);
    cudaGetSymbolAddress((void**)&f1, g_fc1);
    cudaGetSymbolAddress((void**)&f2, g_fc2);

    const int region_smem = (15488 + 288*36) * 4;
    cudaFuncSetAttribute(region_kernel,
                         cudaFuncAttributeMaxDynamicSharedMemorySize, region_smem);

    const int c1_smem = (3276 + 11776 + 368 + 32) * 4;       // 61808
    cudaFuncSetAttribute(conv1_tc,
                         cudaFuncAttributeMaxDynamicSharedMemorySize, c1_smem);
    const int ctc_smem = (7176 + 8192 + 512 + 16) * 4;       // 63584
    cudaFuncSetAttribute(conv_tc8<32,80,80,73,73>,
                         cudaFuncAttributeMaxDynamicSharedMemorySize, ctc_smem);
    cudaFuncSetAttribute(conv_tc8<16,73,73,66,66>,
                         cudaFuncAttributeMaxDynamicSharedMemorySize, ctc_smem);

    // 1. conv1 (tensor cores)
    conv1_tc<<<dim3(5,10,BATCH), 256, c1_smem>>>(x, conv1_w, conv1_b, b1);

    // 2. region
    region_kernel<<<BATCH*64, 256, region_smem>>>(
        b1, rl_gamma, rl_beta, rl_mean, rl_var, rl_cw, rl_cb,
        bn_gamma, bn_beta, bn_mean, bn_var, b2);

    // 3. conv2: 32->16, 8x8, 80->73 (tensor cores, fused bias+relu)
    conv_tc8<32,80,80,73,73><<<dim3(3,5,BATCH), 256, ctc_smem>>>(
        b2, conv2_w, conv2_b, b3);

    // 4. conv3: 16->16, 8x8, 73->66 (tensor cores)
    conv_tc8<16,73,73,66,66><<<dim3(3,5,BATCH), 256, ctc_smem>>>(
        b3, conv3_w, conv3_b, b4);

    // 5. conv4: 16->16, 6x6 s2, 66->31 (CIN split 2x8)
    conv_split<16,8,6,2,66,66,31,31,4><<<dim3(2,2,BATCH*2), dim3(16,8)>>>(
        b4, conv4_w, cp);
    { int hw = 31*31, tot = BATCH*16*hw;
      combine_relu<<<(tot+255)/256, 256>>>(cp, conv4_b, b5, hw, tot); }

    // 6. conv5: 16->16, 5x5, 31->27 (CIN split 2x8)
    conv_split<16,8,5,1,31,31,27,27,8><<<dim3(2,2,BATCH*2), dim3(16,8)>>>(
        b5, conv5_w, cp);
    { int hw = 27*27, tot = BATCH*16*hw;
      combine_relu<<<(tot+255)/256, 256>>>(cp, conv5_b, b6, hw, tot); }

    // 7. fc1: K=11664 split into 12 tiles of 972
    fc_partial<<<dim3(16,12), 128>>>(b6, fc1_w, pt, 4096, 11664, 972);
    fc_reduce<<<512, 256>>>(pt, fc1_b, f1, 4096, 12, 1);

    // 8. fc2: K=4096 split into 16 tiles of 256
    fc_partial<<<dim3(8,16), 128>>>(f1, fc2_w, pt, 2048, 4096, 256);
    fc_reduce<<<256, 256>>>(pt, fc2_b, f2, 2048, 16, 1);

    // 9. fc3 + log_softmax
    fc3_softmax<<<BATCH, 768>>>(f2, fc3_w, fc3_b, out);
}

// round 6
// speedup vs baseline: 2.0229x; 1.0769x over previous
#include <cuda_runtime.h>
#include <cuda_bf16.h>
#include <math.h>
#include <stdint.h>

#define BATCH 32
#define EPS 1e-5f

typedef unsigned long long u64;
__device__ __forceinline__ u64 pk2(float v) {
    u64 r; asm("mov.b64 %0,{%1,%1};" : "=l"(r) : "f"(v)); return r;
}
__device__ __forceinline__ float2 unpk(u64 a) {
    float2 f; asm("mov.b64 {%0,%1},%2;" : "=f"(f.x), "=f"(f.y) : "l"(a)); return f;
}
__device__ __forceinline__ void fma2(u64& d, u64 a, u64 b) {
    asm("fma.rn.f32x2 %0,%1,%2,%0;" : "+l"(d) : "l"(a), "l"(b));
}
__device__ __forceinline__ uint32_t f2tf(float f) {
    uint32_t r; asm("cvt.rna.tf32.f32 %0,%1;" : "=r"(r) : "f"(f)); return r;
}
__device__ __forceinline__ void mma8(float* c, uint32_t a0, uint32_t a1,
                                     uint32_t a2, uint32_t a3,
                                     uint32_t b0, uint32_t b1) {
    asm("mma.sync.aligned.m16n8k8.row.col.f32.tf32.tf32.f32 "
        "{%0,%1,%2,%3},{%4,%5,%6,%7},{%8,%9},{%0,%1,%2,%3};"
        : "+f"(c[0]), "+f"(c[1]), "+f"(c[2]), "+f"(c[3])
        : "r"(a0), "r"(a1), "r"(a2), "r"(a3), "r"(b0), "r"(b1));
}

// ---------------- scratch ----------------
__device__ float g_buf1[BATCH*32*160*160];
__device__ float g_buf2[BATCH*32*80*80];
__device__ float g_buf3[BATCH*16*73*73];
__device__ float g_buf4[BATCH*16*66*66];
__device__ float g_buf5[BATCH*16*31*31];
__device__ float g_buf6[BATCH*16*27*27];
__device__ float g_cpart[2*BATCH*16*73*73];
__device__ float g_part[16*32*4096];
__device__ float g_fc1[BATCH*4096];
__device__ float g_fc2[BATCH*2048];

// =====================================================================
// conv1 (tf32): [32,3,170,170] -> [32,32,160,160], 11x11
// =====================================================================
__global__ void __launch_bounds__(256) conv1_tc(
    const float* __restrict__ x, const float* __restrict__ w,
    const float* __restrict__ bias, float* __restrict__ out)
{
    extern __shared__ uint32_t sm_u[];
    uint32_t* xs = sm_u;               // 3276
    uint32_t* ws = sm_u + 3276;        // 11776
    int* lut = (int*)(ws + 11776);     // 368
    float* bs = (float*)(lut + 368);   // 32

    const int tid = threadIdx.x, lane = tid & 31, wp = tid >> 5;
    const int b = blockIdx.z;
    const int iy0 = blockIdx.y*16, ix0 = blockIdx.x*32;

    for (int i = tid; i < 368; i += 256) {
        int v = 0;
        if (i < 363) {
            int c = i/121, r = i - c*121, kh = r/11, kw = r - kh*11;
            v = c*(26*42) + kh*42 + kw;
        }
        lut[i] = v;
    }
    for (int i = tid; i < 32*368; i += 256) {
        int oc = i / 368, k = i - oc*368;
        float v = (k < 363) ? w[oc*363 + k] : 0.f;
        ws[k*32 + oc] = f2tf(v);
    }
    const float* xb = x + (size_t)b*3*170*170;
    for (int i = tid; i < 3*26*42; i += 256) {
        int c = i / (26*42), r = i - c*(26*42), yy = r/42, xx = r - yy*42;
        xs[i] = f2tf(xb[((size_t)c*170 + iy0 + yy)*170 + ix0 + xx]);
    }
    if (tid < 32) bs[tid] = bias[tid];
    __syncthreads();

    float acc[4][4][4];
#pragma unroll
    for (int m = 0; m < 4; m++)
#pragma unroll
        for (int n = 0; n < 4; n++)
#pragma unroll
            for (int q = 0; q < 4; q++) acc[m][n][q] = 0.f;

    const int gr = lane >> 2, gc = lane & 3;
    int mb[4];
#pragma unroll
    for (int i = 0; i < 4; i++) {
        int t = wp*4 + i;
        mb[i] = (t >> 1)*42 + (t & 1)*16 + gr;
    }

    for (int k0 = 0; k0 < 368; k0 += 8) {
        int o1 = lut[k0 + gc], o2 = lut[k0 + gc + 4];
        const uint32_t* wk = &ws[(k0 + gc)*32 + gr];
        uint32_t bf0[4], bf1[4];
#pragma unroll
        for (int nt = 0; nt < 4; nt++) { bf0[nt] = wk[nt*8]; bf1[nt] = wk[128 + nt*8]; }
#pragma unroll
        for (int mt = 0; mt < 4; mt++) {
            uint32_t a0 = xs[mb[mt] + o1], a1 = xs[mb[mt] + 8 + o1];
            uint32_t a2 = xs[mb[mt] + o2], a3 = xs[mb[mt] + 8 + o2];
#pragma unroll
            for (int nt = 0; nt < 4; nt++)
                mma8(acc[mt][nt], a0, a1, a2, a3, bf0[nt], bf1[nt]);
        }
    }
#pragma unroll
    for (int mt = 0; mt < 4; mt++) {
        int t = wp*4 + mt;
        int yp = iy0 + (t >> 1), xp = ix0 + (t & 1)*16 + gr;
#pragma unroll
        for (int nt = 0; nt < 4; nt++) {
            int oc = nt*8 + gc*2;
            float* o0 = out + (((size_t)b*32 + oc)*160 + yp)*160 + xp;
            o0[0]     = acc[mt][nt][0] + bs[oc];
            o0[25600] = acc[mt][nt][1] + bs[oc+1];
            o0[8]     = acc[mt][nt][2] + bs[oc];
            o0[25608] = acc[mt][nt][3] + bs[oc+1];
        }
    }
}

// =====================================================================
// region (tf32 tensor cores): per patch GEMM M=400(25xm16), N=32, K=288
// pass1: conv into smem; pass2: bias+residual+relu+pool+bn2
// dyn smem u32: act[15488] ws[9216] lut[288]  (act aliased as res[12800] f32)
// =====================================================================
__global__ void __launch_bounds__(256) region_tc(
    const float* __restrict__ in,
    const float* __restrict__ rl_gamma, const float* __restrict__ rl_beta,
    const float* __restrict__ rl_mean,  const float* __restrict__ rl_var,
    const float* __restrict__ rl_cw,    const float* __restrict__ rl_cb,
    const float* __restrict__ bn_g, const float* __restrict__ bn_b,
    const float* __restrict__ bn_m, const float* __restrict__ bn_v,
    float* __restrict__ out)
{
    extern __shared__ uint32_t smu[];
    uint32_t* act = smu;               // 15488 (32*484), zero-padded 22x22
    uint32_t* ws  = smu + 15488;       // 9216 = 288*32, [k][oc]
    int* lut = (int*)(ws + 9216);      // 288
    __shared__ float sc[32], sh[32], s2[32], t2[32], cb[32];

    const int blk = blockIdx.x;
    const int b = blk >> 6;
    const int patch = blk & 63;
    const int gi = patch >> 3, gj = patch & 7;
    const int kidx = gj*(gi+1);
    const int tid = threadIdx.x, lane = tid & 31, wp = tid >> 5;
    const int gr = lane >> 2, gc = lane & 3;

    if (tid < 32) {
        float g = rl_gamma[kidx*32+tid];
        float s = g * rsqrtf(rl_var[kidx*32+tid] + EPS);
        sc[tid] = s;
        sh[tid] = rl_beta[kidx*32+tid] - rl_mean[kidx*32+tid]*s;
        float ss = bn_g[tid] * rsqrtf(bn_v[tid] + EPS);
        s2[tid] = ss;
        t2[tid] = bn_b[tid] - bn_m[tid]*ss;
        cb[tid] = rl_cb[kidx*32+tid];
    }
    for (int i = tid; i < 15488; i += 256) act[i] = 0u;   // tf32 zero == 0 bits
    for (int i = tid; i < 288; i += 256) {
        int ic = i/9, r = i - ic*9;
        lut[i] = ic*484 + (r/3)*22 + (r%3);
    }
    __syncthreads();

    const float* inb = in + (size_t)b*32*160*160;
    for (int i = tid; i < 32*400; i += 256) {
        int ic = i / 400, r = i - ic*400;
        int y = r / 20, xx = r - y*20;
        float v = inb[((size_t)ic*160 + gi*20 + y)*160 + gj*20 + xx];
        act[ic*484 + (y+1)*22 + (xx+1)] = f2tf(fmaxf(fmaf(v, sc[ic], sh[ic]), 0.f));
    }
    for (int i = tid; i < 9216; i += 256) {
        int oc = i / 288, kk = i - oc*288;
        ws[kk*32 + oc] = f2tf(rl_cw[(size_t)kidx*9216 + i]);
    }
    __syncthreads();

    // warp wp handles m-tiles t = wp, wp+8, wp+16, (wp+24 if ==24)
    const int ntiles = (wp == 0) ? 4 : 3;
    int ra0[4], ra1[4];
#pragma unroll
    for (int ti = 0; ti < 4; ti++) {
        int t = wp + 8*ti;
        int p0 = t*16 + gr, p1 = p0 + 8;
        if (t < 25) {
            ra0[ti] = (p0/20)*22 + (p0%20);
            ra1[ti] = (p1/20)*22 + (p1%20);
        } else { ra0[ti] = 0; ra1[ti] = 0; }
    }

    float acc[4][4][4];
#pragma unroll
    for (int m = 0; m < 4; m++)
#pragma unroll
        for (int n = 0; n < 4; n++)
#pragma unroll
            for (int q = 0; q < 4; q++) acc[m][n][q] = 0.f;

    for (int k0 = 0; k0 < 288; k0 += 8) {
        int o1 = lut[k0 + gc], o2 = lut[k0 + gc + 4];
        const uint32_t* wk  = &ws[(k0 + gc)*32 + gr];
        const uint32_t* wk2 = &ws[(k0 + gc + 4)*32 + gr];
        uint32_t b0[4], b1[4];
#pragma unroll
        for (int nt = 0; nt < 4; nt++) { b0[nt] = wk[nt*8]; b1[nt] = wk2[nt*8]; }
#pragma unroll
        for (int ti = 0; ti < 4; ti++) {
            if (ti >= ntiles) break;
            uint32_t a0 = act[ra0[ti] + o1], a1 = act[ra1[ti] + o1];
            uint32_t a2 = act[ra0[ti] + o2], a3 = act[ra1[ti] + o2];
#pragma unroll
            for (int nt = 0; nt < 4; nt++)
                mma8(acc[ti][nt], a0, a1, a2, a3, b0[nt], b1[nt]);
        }
    }
    __syncthreads();

    float* res = (float*)smu;          // 12800 = 32*400, aliases act
#pragma unroll
    for (int ti = 0; ti < 4; ti++) {
        if (ti >= ntiles) break;
        int t = wp + 8*ti;
        int p0 = t*16 + gr, p1 = p0 + 8;
#pragma unroll
        for (int nt = 0; nt < 4; nt++) {
            int oc0 = nt*8 + 2*gc;
            res[oc0*400 + p0]     = acc[ti][nt][0];
            res[(oc0+1)*400 + p0] = acc[ti][nt][1];
            res[oc0*400 + p1]     = acc[ti][nt][2];
            res[(oc0+1)*400 + p1] = acc[ti][nt][3];
        }
    }
    __syncthreads();

    // pass2: 3200 items = 32 oc x 100 pooled
    for (int item = tid; item < 3200; item += 256) {
        int oc = item / 100, pos = item - oc*100;
        int py = pos / 10, px = pos - py*10;
        float bv = cb[oc];
        const float* xrb = inb + ((size_t)oc*160 + gi*20 + 2*py)*160 + gj*20 + 2*px;
        int p = (2*py)*20 + 2*px;
        float v0 = fmaxf(res[oc*400 + p]      + bv + xrb[0],   0.f);
        float v1 = fmaxf(res[oc*400 + p + 1]  + bv + xrb[1],   0.f);
        float v2 = fmaxf(res[oc*400 + p + 20] + bv + xrb[160], 0.f);
        float v3 = fmaxf(res[oc*400 + p + 21] + bv + xrb[161], 0.f);
        float mx = fmaxf(fmaxf(v0, v1), fmaxf(v2, v3));
        out[(((size_t)b*32 + oc)*80 + gi*10 + py)*80 + gj*10 + px] =
            fmaf(mx, s2[oc], t2[oc]);
    }
}

// =====================================================================
// conv2/conv3 (tf32): 8x8 kernel, COUT=16, CIN chunked by 8
// =====================================================================
template<int CIN, int HIN, int WIN, int HOUT, int WOUT>
__global__ void __launch_bounds__(256) conv_tc8(
    const float* __restrict__ in, const float* __restrict__ w,
    const float* __restrict__ bias, float* __restrict__ out)
{
    constexpr int TIH = 23, TIW = 39;
    extern __shared__ uint32_t sm_u[];
    uint32_t* xs = sm_u;               // 7176
    uint32_t* ws = sm_u + 7176;        // 8192
    int* lut = (int*)(ws + 8192);      // 512
    float* bs = (float*)(lut + 512);   // 16

    const int tid = threadIdx.x, lane = tid & 31, wp = tid >> 5;
    const int b = blockIdx.z;
    const int iy0 = blockIdx.y*16, ix0 = blockIdx.x*32;

    for (int i = tid; i < 512; i += 256) {
        int cl = i >> 6, r = i & 63, kh = r >> 3, kw = r & 7;
        lut[i] = cl*(TIH*TIW) + kh*TIW + kw;
    }
    if (tid < 16) bs[tid] = bias[tid];

    float acc[4][2][4];
#pragma unroll
    for (int m = 0; m < 4; m++)
#pragma unroll
        for (int n = 0; n < 2; n++)
#pragma unroll
            for (int q = 0; q < 4; q++) acc[m][n][q] = 0.f;

    const int gr = lane >> 2, gc = lane & 3;
    int mb[4];
#pragma unroll
    for (int i = 0; i < 4; i++) {
        int t = wp*4 + i;
        mb[i] = (t >> 1)*TIW + (t & 1)*16 + gr;
    }

    for (int cc = 0; cc < CIN; cc += 8) {
        __syncthreads();
        for (int i = tid; i < 8*TIH*TIW; i += 256) {
            int cl = i / (TIH*TIW), r = i - cl*(TIH*TIW);
            int yy = r / TIW, xx = r - yy*TIW;
            int gy = iy0 + yy, gx = ix0 + xx;
            float v = 0.f;
            if (gy < HIN && gx < WIN)
                v = in[(((size_t)b*CIN + cc + cl)*HIN + gy)*WIN + gx];
            xs[i] = f2tf(v);
        }
        for (int i = tid; i < 16*512; i += 256) {
            int oc = i >> 9, kl = i & 511;
            int cl = kl >> 6, kk = kl & 63;
            ws[kl*16 + oc] = f2tf(w[((size_t)oc*CIN + cc + cl)*64 + kk]);
        }
        __syncthreads();

        for (int k0 = 0; k0 < 512; k0 += 8) {
            int o1 = lut[k0 + gc], o2 = lut[k0 + gc + 4];
            const uint32_t* wk = &ws[(k0 + gc)*16 + gr];
            uint32_t bf0[2], bf1[2];
#pragma unroll
            for (int nt = 0; nt < 2; nt++) { bf0[nt] = wk[nt*8]; bf1[nt] = wk[64 + nt*8]; }
#pragma unroll
            for (int mt = 0; mt < 4; mt++) {
                uint32_t a0 = xs[mb[mt] + o1], a1 = xs[mb[mt] + 8 + o1];
                uint32_t a2 = xs[mb[mt] + o2], a3 = xs[mb[mt] + 8 + o2];
#pragma unroll
                for (int nt = 0; nt < 2; nt++)
                    mma8(acc[mt][nt], a0, a1, a2, a3, bf0[nt], bf1[nt]);
            }
        }
    }

    const size_t cstride = (size_t)HOUT*WOUT;
#pragma unroll
    for (int mt = 0; mt < 4; mt++) {
        int t = wp*4 + mt;
        int yp = iy0 + (t >> 1), xp = ix0 + (t & 1)*16 + gr;
        if (yp < HOUT) {
#pragma unroll
            for (int nt = 0; nt < 2; nt++) {
                int oc = nt*8 + gc*2;
                float* o0 = out + (((size_t)b*16 + oc)*HOUT + yp)*WOUT + xp;
                if (xp < WOUT) {
                    o0[0]       = fmaxf(acc[mt][nt][0] + bs[oc],   0.f);
                    o0[cstride] = fmaxf(acc[mt][nt][1] + bs[oc+1], 0.f);
                }
                if (xp + 8 < WOUT) {
                    o0[8]         = fmaxf(acc[mt][nt][2] + bs[oc],   0.f);
                    o0[cstride+8] = fmaxf(acc[mt][nt][3] + bs[oc+1], 0.f);
                }
            }
        }
    }
}

// =====================================================================
// conv4/conv5 partial (f32x2), CIN split — unchanged
// =====================================================================
template<int CIN, int CINH, int KS, int STRIDE, int HIN, int WIN,
         int HOUT, int WOUT, int ICC>
__global__ void __launch_bounds__(128) conv_split(
    const float* __restrict__ in, const float* __restrict__ w,
    float* __restrict__ part)
{
    constexpr int TIN = 15*STRIDE + KS;
    __shared__ float xs[ICC*TIN*TIN];
    __shared__ float ws[ICC*KS*KS*16];

    const int tx = threadIdx.x, ty = threadIdx.y;
    const int tid = ty*16 + tx;
    const int z = blockIdx.z;
    const int b = z >> 1, split = z & 1;
    const int c0 = split*CINH;
    const int oy0 = blockIdx.y*16 + ty;
    const int ox  = blockIdx.x*16 + tx;
    const int iy0 = blockIdx.y*16*STRIDE;
    const int ix0 = blockIdx.x*16*STRIDE;

    u64 acc0[8], acc1[8];
#pragma unroll
    for (int q = 0; q < 8; q++) { acc0[q]=0ull; acc1[q]=0ull; }

    for (int cc = c0; cc < c0 + CINH; cc += ICC) {
        __syncthreads();
        for (int i = tid; i < ICC*TIN*TIN; i += 128) {
            int icl = i / (TIN*TIN), r = i - icl*(TIN*TIN);
            int yy = r / TIN, xx = r - yy*TIN;
            int gy = iy0 + yy, gx = ix0 + xx;
            float v = 0.f;
            if (gy < HIN && gx < WIN)
                v = in[(((size_t)b*CIN + cc + icl)*HIN + gy)*WIN + gx];
            xs[i] = v;
        }
        for (int i = tid; i < ICC*KS*KS*16; i += 128) {
            int oc = i & 15; int r = i >> 4;
            int icl = r / (KS*KS); int kk = r - icl*(KS*KS);
            ws[i] = w[((size_t)oc*CIN + cc + icl)*KS*KS + kk];
        }
        __syncthreads();
#pragma unroll 1
        for (int icl = 0; icl < ICC; icl++) {
            for (int kh = 0; kh < KS; kh++) {
                const float* x0 = &xs[icl*TIN*TIN + (ty*STRIDE + kh)*TIN + tx*STRIDE];
                const float* x1 = &xs[icl*TIN*TIN + ((ty+8)*STRIDE + kh)*TIN + tx*STRIDE];
                const float* wrow = &ws[(icl*KS*KS + kh*KS)*16];
#pragma unroll
                for (int kw = 0; kw < KS; kw++) {
                    u64 p0 = pk2(x0[kw]);
                    u64 p1 = pk2(x1[kw]);
                    const ulonglong2* wp = (const ulonglong2*)(wrow + kw*16);
#pragma unroll
                    for (int q = 0; q < 4; q++) {
                        ulonglong2 wv = wp[q];
                        fma2(acc0[2*q],   p0, wv.x); fma2(acc0[2*q+1], p0, wv.y);
                        fma2(acc1[2*q],   p1, wv.x); fma2(acc1[2*q+1], p1, wv.y);
                    }
                }
            }
        }
    }
    const size_t tot = (size_t)BATCH*16*HOUT*WOUT;
    float* pb = part + (size_t)split*tot;
    if (ox < WOUT) {
#pragma unroll
        for (int q = 0; q < 8; q++) {
            float2 f0 = unpk(acc0[q]), f1 = unpk(acc1[q]);
#pragma unroll
            for (int h = 0; h < 2; h++) {
                int oc = 2*q + h;
                float v0 = h ? f0.y : f0.x;
                float v1 = h ? f1.y : f1.x;
                if (oy0 < HOUT)
                    pb[(((size_t)b*16 + oc)*HOUT + oy0)*WOUT + ox] = v0;
                if (oy0 + 8 < HOUT)
                    pb[(((size_t)b*16 + oc)*HOUT + oy0 + 8)*WOUT + ox] = v1;
            }
        }
    }
}

__global__ void combine_relu(const float* __restrict__ p,
                             const float* __restrict__ bias,
                             float* __restrict__ out, int HW, int total)
{
    int i = blockIdx.x*256 + threadIdx.x;
    if (i >= total) return;
    int oc = (i / HW) & 15;
    out[i] = fmaxf(p[i] + p[i + total] + bias[oc], 0.f);
}

// =====================================================================
// fc partial / reduce / fc3 — unchanged
// =====================================================================
#define FC_CHUNK 160
__global__ void __launch_bounds__(128) fc_partial(
    const float* __restrict__ x, const float* __restrict__ w,
    float* __restrict__ part, int N, int K, int ktlen)
{
    __shared__ float xs[32*FC_CHUNK];
    const int tid = threadIdx.x;
    const int n0 = blockIdx.x*256 + tid;
    const int n1 = n0 + 128;
    const int k0 = blockIdx.y*ktlen;

    float acc0[32], acc1[32];
#pragma unroll
    for (int m = 0; m < 32; m++) { acc0[m]=0.f; acc1[m]=0.f; }

    for (int kc = 0; kc < ktlen; kc += FC_CHUNK) {
        int cl = min(FC_CHUNK, ktlen - kc);
        __syncthreads();
        for (int i = tid; i < 32*cl; i += 128) {
            int m = i / cl, kk = i - m*cl;
            xs[m*FC_CHUNK + kk] = x[(size_t)m*K + k0 + kc + kk];
        }
        __syncthreads();
        const float* w0 = w + (size_t)n0*K + k0 + kc;
        const float* w1 = w + (size_t)n1*K + k0 + kc;
        for (int kk = 0; kk < cl; kk += 2) {
            float2 a0 = *(const float2*)(w0 + kk);
            float2 a1 = *(const float2*)(w1 + kk);
#pragma unroll
            for (int m = 0; m < 32; m++) {
                float2 xv = *(const float2*)&xs[m*FC_CHUNK + kk];
                acc0[m] = fmaf(a0.x, xv.x, fmaf(a0.y, xv.y, acc0[m]));
                acc1[m] = fmaf(a1.x, xv.x, fmaf(a1.y, xv.y, acc1[m]));
            }
        }
    }
    float* pr = part + (size_t)blockIdx.y*32*N;
#pragma unroll
    for (int m = 0; m < 32; m++) {
        pr[(size_t)m*N + n0] = acc0[m];
        pr[(size_t)m*N + n1] = acc1[m];
    }
}

__global__ void fc_reduce(const float* __restrict__ part,
                          const float* __restrict__ bias,
                          float* __restrict__ out, int N, int KT, int do_relu)
{
    int i = blockIdx.x*256 + threadIdx.x;
    if (i >= 32*N) return;
    int n = i % N;
    float s = bias[n];
    for (int kt = 0; kt < KT; kt++) s += part[(size_t)kt*32*N + i];
    out[i] = do_relu ? fmaxf(s, 0.f) : s;
}

__global__ void __launch_bounds__(768) fc3_softmax(
    const float* __restrict__ x, const float* __restrict__ w,
    const float* __restrict__ bias, float* __restrict__ out)
{
    __shared__ float lg[24];
    const int b = blockIdx.x;
    const int tid = threadIdx.x;
    const int wo = tid >> 5, lane = tid & 31;

    const float* xr = x + (size_t)b*2048;
    const float* wr = w + (size_t)wo*2048;
    float s = 0.f;
    for (int k = lane; k < 2048; k += 32) s = fmaf(wr[k], xr[k], s);
#pragma unroll
    for (int off = 16; off; off >>= 1) s += __shfl_xor_sync(0xffffffffu, s, off);
    if (lane == 0) lg[wo] = s + bias[wo];
    __syncthreads();

    if (tid < 24) {
        int a = tid % 12;
        float z0 = lg[a], z1 = lg[12 + a];
        float m = fmaxf(z0, z1);
        float lse = m + logf(expf(z0 - m) + expf(z1 - m));
        out[b*24 + tid] = lg[tid] - lse;
    }
}

// =====================================================================
// launch
// =====================================================================
extern "C" void kernel_launch(void* const* d_in, const int* in_sizes, int n_in,
                              void* d_out, int out_size)
{
    const float* x        = (const float*)d_in[0];
    const float* conv1_w  = (const float*)d_in[1];
    const float* conv1_b  = (const float*)d_in[2];
    const float* rl_gamma = (const float*)d_in[3];
    const float* rl_beta  = (const float*)d_in[4];
    const float* rl_mean  = (const float*)d_in[5];
    const float* rl_var   = (const float*)d_in[6];
    const float* rl_cw    = (const float*)d_in[7];
    const float* rl_cb    = (const float*)d_in[8];
    const float* bn_gamma = (const float*)d_in[9];
    const float* bn_beta  = (const float*)d_in[10];
    const float* bn_mean  = (const float*)d_in[11];
    const float* bn_var   = (const float*)d_in[12];
    const float* conv2_w  = (const float*)d_in[13];
    const float* conv2_b  = (const float*)d_in[14];
    const float* conv3_w  = (const float*)d_in[15];
    const float* conv3_b  = (const float*)d_in[16];
    const float* conv4_w  = (const float*)d_in[17];
    const float* conv4_b  = (const float*)d_in[18];
    const float* conv5_w  = (const float*)d_in[19];
    const float* conv5_b  = (const float*)d_in[20];
    const float* fc1_w    = (const float*)d_in[21];
    const float* fc1_b    = (const float*)d_in[22];
    const float* fc2_w    = (const float*)d_in[23];
    const float* fc2_b    = (const float*)d_in[24];
    const float* fc3_w    = (const float*)d_in[25];
    const float* fc3_b    = (const float*)d_in[26];
    float* out = (float*)d_out;

    float *b1,*b2,*b3,*b4,*b5,*b6,*cp,*pt,*f1,*f2;
    cudaGetSymbolAddress((void**)&b1, g_buf1);
    cudaGetSymbolAddress((void**)&b2, g_buf2);
    cudaGetSymbolAddress((void**)&b3, g_buf3);
    cudaGetSymbolAddress((void**)&b4, g_buf4);
    cudaGetSymbolAddress((void**)&b5, g_buf5);
    cudaGetSymbolAddress((void**)&b6, g_buf6);
    cudaGetSymbolAddress((void**)&cp, g_cpart);
    cudaGetSymbolAddress((void**)&pt, g_part);
    cudaGetSymbolAddress((void**)&f1, g_fc1);
    cudaGetSymbolAddress((void**)&f2, g_fc2);

    const int c1_smem = (3276 + 11776 + 368 + 32) * 4;
    cudaFuncSetAttribute(conv1_tc,
                         cudaFuncAttributeMaxDynamicSharedMemorySize, c1_smem);
    const int reg_smem = (15488 + 9216 + 288) * 4;           // 99968
    cudaFuncSetAttribute(region_tc,
                         cudaFuncAttributeMaxDynamicSharedMemorySize, reg_smem);
    const int ctc_smem = (7176 + 8192 + 512 + 16) * 4;
    cudaFuncSetAttribute(conv_tc8<32,80,80,73,73>,
                         cudaFuncAttributeMaxDynamicSharedMemorySize, ctc_smem);
    cudaFuncSetAttribute(conv_tc8<16,73,73,66,66>,
                         cudaFuncAttributeMaxDynamicSharedMemorySize, ctc_smem);

    // 1. conv1 (tensor cores)
    conv1_tc<<<dim3(5,10,BATCH), 256, c1_smem>>>(x, conv1_w, conv1_b, b1);

    // 2. region (tensor cores)
    region_tc<<<BATCH*64, 256, reg_smem>>>(
        b1, rl_gamma, rl_beta, rl_mean, rl_var, rl_cw, rl_cb,
        bn_gamma, bn_beta, bn_mean, bn_var, b2);

    // 3. conv2 (tensor cores)
    conv_tc8<32,80,80,73,73><<<dim3(3,5,BATCH), 256, ctc_smem>>>(
        b2, conv2_w, conv2_b, b3);

    // 4. conv3 (tensor cores)
    conv_tc8<16,73,73,66,66><<<dim3(3,5,BATCH), 256, ctc_smem>>>(
        b3, conv3_w, conv3_b, b4);

    // 5. conv4 (CIN split 2x8)
    conv_split<16,8,6,2,66,66,31,31,4><<<dim3(2,2,BATCH*2), dim3(16,8)>>>(
        b4, conv4_w, cp);
    { int hw = 31*31, tot = BATCH*16*hw;
      combine_relu<<<(tot+255)/256, 256>>>(cp, conv4_b, b5, hw, tot); }

    // 6. conv5 (CIN split 2x8)
    conv_split<16,8,5,1,31,31,27,27,8><<<dim3(2,2,BATCH*2), dim3(16,8)>>>(
        b5, conv5_w, cp);
    { int hw = 27*27, tot = BATCH*16*hw;
      combine_relu<<<(tot+255)/256, 256>>>(cp, conv5_b, b6, hw, tot); }

    // 7. fc1
    fc_partial<<<dim3(16,12), 128>>>(b6, fc1_w, pt, 4096, 11664, 972);
    fc_reduce<<<512, 256>>>(pt, fc1_b, f1, 4096, 12, 1);

    // 8. fc2
    fc_partial<<<dim3(8,16), 128>>>(f1, fc2_w, pt, 2048, 4096, 256);
    fc_reduce<<<256, 256>>>(pt, fc2_b, f2, 2048, 16, 1);

    // 9. fc3 + log_softmax
    fc3_softmax<<<BATCH, 768>>>(f2, fc3_w, fc3_b, out);
}

// round 7
// speedup vs baseline: 2.4637x; 1.2179x over previous
#include <cuda_runtime.h>
#include <cuda_bf16.h>
#include <math.h>
#include <stdint.h>

#define BATCH 32
#define EPS 1e-5f

typedef unsigned long long u64;
__device__ __forceinline__ u64 pk2(float v) {
    u64 r; asm("mov.b64 %0,{%1,%1};" : "=l"(r) : "f"(v)); return r;
}
__device__ __forceinline__ float2 unpk(u64 a) {
    float2 f; asm("mov.b64 {%0,%1},%2;" : "=f"(f.x), "=f"(f.y) : "l"(a)); return f;
}
__device__ __forceinline__ void fma2(u64& d, u64 a, u64 b) {
    asm("fma.rn.f32x2 %0,%1,%2,%0;" : "+l"(d) : "l"(a), "l"(b));
}
__device__ __forceinline__ uint32_t f2tf(float f) {
    uint32_t r; asm("cvt.rna.tf32.f32 %0,%1;" : "=r"(r) : "f"(f)); return r;
}
__device__ __forceinline__ void mma8(float* c, uint32_t a0, uint32_t a1,
                                     uint32_t a2, uint32_t a3,
                                     uint32_t b0, uint32_t b1) {
    asm("mma.sync.aligned.m16n8k8.row.col.f32.tf32.tf32.f32 "
        "{%0,%1,%2,%3},{%4,%5,%6,%7},{%8,%9},{%0,%1,%2,%3};"
        : "+f"(c[0]), "+f"(c[1]), "+f"(c[2]), "+f"(c[3])
        : "r"(a0), "r"(a1), "r"(a2), "r"(a3), "r"(b0), "r"(b1));
}

// ---------------- scratch ----------------
__device__ float g_buf1[BATCH*32*160*160];
__device__ float g_buf2[BATCH*32*80*80];
__device__ float g_buf3[BATCH*16*73*73];
__device__ float g_buf4[BATCH*16*66*66];
__device__ float g_buf5[BATCH*16*31*31];
__device__ float g_buf6[BATCH*16*27*27];
__device__ float g_cpart[2*BATCH*16*73*73];
__device__ float g_part[24*32*4096];
__device__ float g_fc1[BATCH*4096];
__device__ float g_fc2[BATCH*2048];

// =====================================================================
// conv1 (tf32): [32,3,170,170] -> [32,32,160,160], 11x11  (unchanged)
// =====================================================================
__global__ void __launch_bounds__(256) conv1_tc(
    const float* __restrict__ x, const float* __restrict__ w,
    const float* __restrict__ bias, float* __restrict__ out)
{
    extern __shared__ uint32_t sm_u[];
    uint32_t* xs = sm_u;               // 3276
    uint32_t* ws = sm_u + 3276;        // 11776
    int* lut = (int*)(ws + 11776);     // 368
    float* bs = (float*)(lut + 368);   // 32

    const int tid = threadIdx.x, lane = tid & 31, wp = tid >> 5;
    const int b = blockIdx.z;
    const int iy0 = blockIdx.y*16, ix0 = blockIdx.x*32;

    for (int i = tid; i < 368; i += 256) {
        int v = 0;
        if (i < 363) {
            int c = i/121, r = i - c*121, kh = r/11, kw = r - kh*11;
            v = c*(26*42) + kh*42 + kw;
        }
        lut[i] = v;
    }
    for (int i = tid; i < 32*368; i += 256) {
        int oc = i / 368, k = i - oc*368;
        float v = (k < 363) ? w[oc*363 + k] : 0.f;
        ws[k*32 + oc] = f2tf(v);
    }
    const float* xb = x + (size_t)b*3*170*170;
    for (int i = tid; i < 3*26*42; i += 256) {
        int c = i / (26*42), r = i - c*(26*42), yy = r/42, xx = r - yy*42;
        xs[i] = f2tf(xb[((size_t)c*170 + iy0 + yy)*170 + ix0 + xx]);
    }
    if (tid < 32) bs[tid] = bias[tid];
    __syncthreads();

    float acc[4][4][4];
#pragma unroll
    for (int m = 0; m < 4; m++)
#pragma unroll
        for (int n = 0; n < 4; n++)
#pragma unroll
            for (int q = 0; q < 4; q++) acc[m][n][q] = 0.f;

    const int gr = lane >> 2, gc = lane & 3;
    int mb[4];
#pragma unroll
    for (int i = 0; i < 4; i++) {
        int t = wp*4 + i;
        mb[i] = (t >> 1)*42 + (t & 1)*16 + gr;
    }

    for (int k0 = 0; k0 < 368; k0 += 8) {
        int o1 = lut[k0 + gc], o2 = lut[k0 + gc + 4];
        const uint32_t* wk = &ws[(k0 + gc)*32 + gr];
        uint32_t bf0[4], bf1[4];
#pragma unroll
        for (int nt = 0; nt < 4; nt++) { bf0[nt] = wk[nt*8]; bf1[nt] = wk[128 + nt*8]; }
#pragma unroll
        for (int mt = 0; mt < 4; mt++) {
            uint32_t a0 = xs[mb[mt] + o1], a1 = xs[mb[mt] + 8 + o1];
            uint32_t a2 = xs[mb[mt] + o2], a3 = xs[mb[mt] + 8 + o2];
#pragma unroll
            for (int nt = 0; nt < 4; nt++)
                mma8(acc[mt][nt], a0, a1, a2, a3, bf0[nt], bf1[nt]);
        }
    }
#pragma unroll
    for (int mt = 0; mt < 4; mt++) {
        int t = wp*4 + mt;
        int yp = iy0 + (t >> 1), xp = ix0 + (t & 1)*16 + gr;
#pragma unroll
        for (int nt = 0; nt < 4; nt++) {
            int oc = nt*8 + gc*2;
            float* o0 = out + (((size_t)b*32 + oc)*160 + yp)*160 + xp;
            o0[0]     = acc[mt][nt][0] + bs[oc];
            o0[25600] = acc[mt][nt][1] + bs[oc+1];
            o0[8]     = acc[mt][nt][2] + bs[oc];
            o0[25608] = acc[mt][nt][3] + bs[oc+1];
        }
    }
}

// =====================================================================
// region (tf32) — unchanged
// =====================================================================
__global__ void __launch_bounds__(256) region_tc(
    const float* __restrict__ in,
    const float* __restrict__ rl_gamma, const float* __restrict__ rl_beta,
    const float* __restrict__ rl_mean,  const float* __restrict__ rl_var,
    const float* __restrict__ rl_cw,    const float* __restrict__ rl_cb,
    const float* __restrict__ bn_g, const float* __restrict__ bn_b,
    const float* __restrict__ bn_m, const float* __restrict__ bn_v,
    float* __restrict__ out)
{
    extern __shared__ uint32_t smu[];
    uint32_t* act = smu;               // 15488
    uint32_t* ws  = smu + 15488;       // 9216
    int* lut = (int*)(ws + 9216);      // 288
    __shared__ float sc[32], sh[32], s2[32], t2[32], cb[32];

    const int blk = blockIdx.x;
    const int b = blk >> 6;
    const int patch = blk & 63;
    const int gi = patch >> 3, gj = patch & 7;
    const int kidx = gj*(gi+1);
    const int tid = threadIdx.x, lane = tid & 31, wp = tid >> 5;
    const int gr = lane >> 2, gc = lane & 3;

    if (tid < 32) {
        float g = rl_gamma[kidx*32+tid];
        float s = g * rsqrtf(rl_var[kidx*32+tid] + EPS);
        sc[tid] = s;
        sh[tid] = rl_beta[kidx*32+tid] - rl_mean[kidx*32+tid]*s;
        float ss = bn_g[tid] * rsqrtf(bn_v[tid] + EPS);
        s2[tid] = ss;
        t2[tid] = bn_b[tid] - bn_m[tid]*ss;
        cb[tid] = rl_cb[kidx*32+tid];
    }
    for (int i = tid; i < 15488; i += 256) act[i] = 0u;
    for (int i = tid; i < 288; i += 256) {
        int ic = i/9, r = i - ic*9;
        lut[i] = ic*484 + (r/3)*22 + (r%3);
    }
    __syncthreads();

    const float* inb = in + (size_t)b*32*160*160;
    for (int i = tid; i < 32*400; i += 256) {
        int ic = i / 400, r = i - ic*400;
        int y = r / 20, xx = r - y*20;
        float v = inb[((size_t)ic*160 + gi*20 + y)*160 + gj*20 + xx];
        act[ic*484 + (y+1)*22 + (xx+1)] = f2tf(fmaxf(fmaf(v, sc[ic], sh[ic]), 0.f));
    }
    for (int i = tid; i < 9216; i += 256) {
        int oc = i / 288, kk = i - oc*288;
        ws[kk*32 + oc] = f2tf(rl_cw[(size_t)kidx*9216 + i]);
    }
    __syncthreads();

    const int ntiles = (wp == 0) ? 4 : 3;
    int ra0[4], ra1[4];
#pragma unroll
    for (int ti = 0; ti < 4; ti++) {
        int t = wp + 8*ti;
        int p0 = t*16 + gr, p1 = p0 + 8;
        if (t < 25) {
            ra0[ti] = (p0/20)*22 + (p0%20);
            ra1[ti] = (p1/20)*22 + (p1%20);
        } else { ra0[ti] = 0; ra1[ti] = 0; }
    }

    float acc[4][4][4];
#pragma unroll
    for (int m = 0; m < 4; m++)
#pragma unroll
        for (int n = 0; n < 4; n++)
#pragma unroll
            for (int q = 0; q < 4; q++) acc[m][n][q] = 0.f;

    for (int k0 = 0; k0 < 288; k0 += 8) {
        int o1 = lut[k0 + gc], o2 = lut[k0 + gc + 4];
        const uint32_t* wk  = &ws[(k0 + gc)*32 + gr];
        const uint32_t* wk2 = &ws[(k0 + gc + 4)*32 + gr];
        uint32_t b0[4], b1[4];
#pragma unroll
        for (int nt = 0; nt < 4; nt++) { b0[nt] = wk[nt*8]; b1[nt] = wk2[nt*8]; }
#pragma unroll
        for (int ti = 0; ti < 4; ti++) {
            if (ti >= ntiles) break;
            uint32_t a0 = act[ra0[ti] + o1], a1 = act[ra1[ti] + o1];
            uint32_t a2 = act[ra0[ti] + o2], a3 = act[ra1[ti] + o2];
#pragma unroll
            for (int nt = 0; nt < 4; nt++)
                mma8(acc[ti][nt], a0, a1, a2, a3, b0[nt], b1[nt]);
        }
    }
    __syncthreads();

    float* res = (float*)smu;
#pragma unroll
    for (int ti = 0; ti < 4; ti++) {
        if (ti >= ntiles) break;
        int t = wp + 8*ti;
        int p0 = t*16 + gr, p1 = p0 + 8;
#pragma unroll
        for (int nt = 0; nt < 4; nt++) {
            int oc0 = nt*8 + 2*gc;
            res[oc0*400 + p0]     = acc[ti][nt][0];
            res[(oc0+1)*400 + p0] = acc[ti][nt][1];
            res[oc0*400 + p1]     = acc[ti][nt][2];
            res[(oc0+1)*400 + p1] = acc[ti][nt][3];
        }
    }
    __syncthreads();

    for (int item = tid; item < 3200; item += 256) {
        int oc = item / 100, pos = item - oc*100;
        int py = pos / 10, px = pos - py*10;
        float bv = cb[oc];
        const float* xrb = inb + ((size_t)oc*160 + gi*20 + 2*py)*160 + gj*20 + 2*px;
        int p = (2*py)*20 + 2*px;
        float v0 = fmaxf(res[oc*400 + p]      + bv + xrb[0],   0.f);
        float v1 = fmaxf(res[oc*400 + p + 1]  + bv + xrb[1],   0.f);
        float v2 = fmaxf(res[oc*400 + p + 20] + bv + xrb[160], 0.f);
        float v3 = fmaxf(res[oc*400 + p + 21] + bv + xrb[161], 0.f);
        float mx = fmaxf(fmaxf(v0, v1), fmaxf(v2, v3));
        out[(((size_t)b*32 + oc)*80 + gi*10 + py)*80 + gj*10 + px] =
            fmaf(mx, s2[oc], t2[oc]);
    }
}

// =====================================================================
// conv2/conv3 (tf32), 16x16 output tile. m16-tile = one output row.
// ws layout [oc][k] pad 524 (conflict-free read+write).
// dyn smem u32: xs[8*23*23=4232] ws[16*524=8384] lut[512] bs[16]
// =====================================================================
template<int CIN, int HIN, int WIN, int HOUT, int WOUT>
__global__ void __launch_bounds__(256) conv_tc16(
    const float* __restrict__ in, const float* __restrict__ w,
    const float* __restrict__ bias, float* __restrict__ out)
{
    constexpr int TIH = 23, TIW = 23;
    extern __shared__ uint32_t sm_u[];
    uint32_t* xs = sm_u;               // 4232
    uint32_t* ws = sm_u + 4232;        // 8384
    int* lut = (int*)(ws + 8384);      // 512
    float* bs = (float*)(lut + 512);   // 16

    const int tid = threadIdx.x, lane = tid & 31, wp = tid >> 5;
    const int b = blockIdx.z;
    const int iy0 = blockIdx.y*16, ix0 = blockIdx.x*16;

    for (int i = tid; i < 512; i += 256) {
        int cl = i >> 6, r = i & 63, kh = r >> 3, kw = r & 7;
        lut[i] = cl*(TIH*TIW) + kh*TIW + kw;
    }
    if (tid < 16) bs[tid] = bias[tid];

    float acc[2][2][4];
#pragma unroll
    for (int m = 0; m < 2; m++)
#pragma unroll
        for (int n = 0; n < 2; n++)
#pragma unroll
            for (int q = 0; q < 4; q++) acc[m][n][q] = 0.f;

    const int gr = lane >> 2, gc = lane & 3;
    int mb[2];
#pragma unroll
    for (int i = 0; i < 2; i++) mb[i] = (wp*2 + i)*TIW + gr;

    for (int cc = 0; cc < CIN; cc += 8) {
        __syncthreads();
        for (int i = tid; i < 8*TIH*TIW; i += 256) {
            int cl = i / (TIH*TIW), r = i - cl*(TIH*TIW);
            int yy = r / TIW, xx = r - yy*TIW;
            int gy = iy0 + yy, gx = ix0 + xx;
            float v = 0.f;
            if (gy < HIN && gx < WIN)
                v = in[(((size_t)b*CIN + cc + cl)*HIN + gy)*WIN + gx];
            xs[i] = f2tf(v);
        }
        for (int i = tid; i < 16*512; i += 256) {
            int oc = i >> 9, kl = i & 511;
            int cl = kl >> 6, kk = kl & 63;
            ws[oc*524 + kl] = f2tf(w[((size_t)oc*CIN + cc + cl)*64 + kk]);
        }
        __syncthreads();

        for (int k0 = 0; k0 < 512; k0 += 8) {
            int o1 = lut[k0 + gc], o2 = lut[k0 + gc + 4];
            uint32_t bf0[2], bf1[2];
#pragma unroll
            for (int nt = 0; nt < 2; nt++) {
                const uint32_t* wp_ = &ws[(nt*8 + gr)*524 + k0];
                bf0[nt] = wp_[gc]; bf1[nt] = wp_[gc + 4];
            }
#pragma unroll
            for (int mt = 0; mt < 2; mt++) {
                uint32_t a0 = xs[mb[mt] + o1], a1 = xs[mb[mt] + 8 + o1];
                uint32_t a2 = xs[mb[mt] + o2], a3 = xs[mb[mt] + 8 + o2];
#pragma unroll
                for (int nt = 0; nt < 2; nt++)
                    mma8(acc[mt][nt], a0, a1, a2, a3, bf0[nt], bf1[nt]);
            }
        }
    }

    const size_t cstride = (size_t)HOUT*WOUT;
#pragma unroll
    for (int mt = 0; mt < 2; mt++) {
        int yp = iy0 + wp*2 + mt;
        int xp = ix0 + gr;
        if (yp < HOUT) {
#pragma unroll
            for (int nt = 0; nt < 2; nt++) {
                int oc = nt*8 + gc*2;
                float* o0 = out + (((size_t)b*16 + oc)*HOUT + yp)*WOUT + xp;
                if (xp < WOUT) {
                    o0[0]       = fmaxf(acc[mt][nt][0] + bs[oc],   0.f);
                    o0[cstride] = fmaxf(acc[mt][nt][1] + bs[oc+1], 0.f);
                }
                if (xp + 8 < WOUT) {
                    o0[8]         = fmaxf(acc[mt][nt][2] + bs[oc],   0.f);
                    o0[cstride+8] = fmaxf(acc[mt][nt][3] + bs[oc+1], 0.f);
                }
            }
        }
    }
}

// =====================================================================
// fc (tf32): partial GEMM  part[ky][m][n] = x[m][ks..] . w[n][ks..]
// M=32 (2 m16), N-tile 128/block, K-chunk 64. smem pad-68 layouts.
// =====================================================================
__global__ void __launch_bounds__(256) fc_tc(
    const float* __restrict__ x, const float* __restrict__ w,
    float* __restrict__ part, int N, int K, int klen)
{
    __shared__ uint32_t as[32*68];     // 2176
    __shared__ uint32_t bsm[128*68];   // 8704

    const int tid = threadIdx.x, lane = tid & 31, wp = tid >> 5;
    const int n0 = blockIdx.x*128;
    const int kstart = blockIdx.y*klen;
    const int gr = lane >> 2, gc = lane & 3;
    const int nb = wp*16;

    float acc[2][2][4];
#pragma unroll
    for (int m = 0; m < 2; m++)
#pragma unroll
        for (int n = 0; n < 2; n++)
#pragma unroll
            for (int q = 0; q < 4; q++) acc[m][n][q] = 0.f;

    for (int kc = 0; kc < klen; kc += 64) {
        int cl = min(64, klen - kc);
        __syncthreads();
        for (int i = tid; i < 2048; i += 256) {
            int m = i >> 6, k = i & 63;
            float v = (k < cl) ? x[(size_t)m*K + kstart + kc + k] : 0.f;
            as[m*68 + k] = f2tf(v);
        }
        for (int i = tid; i < 8192; i += 256) {
            int n = i >> 6, k = i & 63;
            float v = (k < cl) ? w[(size_t)(n0 + n)*K + kstart + kc + k] : 0.f;
            bsm[n*68 + k] = f2tf(v);
        }
        __syncthreads();

#pragma unroll
        for (int k0 = 0; k0 < 64; k0 += 8) {
            uint32_t a0[2], a1[2], a2[2], a3[2];
#pragma unroll
            for (int mt = 0; mt < 2; mt++) {
                const uint32_t* ap = &as[(mt*16 + gr)*68 + k0];
                a0[mt] = ap[gc];        a2[mt] = ap[gc + 4];
                a1[mt] = ap[8*68 + gc]; a3[mt] = ap[8*68 + gc + 4];
            }
#pragma unroll
            for (int nt = 0; nt < 2; nt++) {
                const uint32_t* bp = &bsm[(nb + nt*8 + gr)*68 + k0];
                uint32_t b0 = bp[gc], b1 = bp[gc + 4];
#pragma unroll
                for (int mt = 0; mt < 2; mt++)
                    mma8(acc[mt][nt], a0[mt], a1[mt], a2[mt], a3[mt], b0, b1);
            }
        }
    }

    float* pr = part + (size_t)blockIdx.y*32*N;
#pragma unroll
    for (int mt = 0; mt < 2; mt++) {
#pragma unroll
        for (int nt = 0; nt < 2; nt++) {
            int n = n0 + nb + nt*8 + 2*gc;
            int m0 = mt*16 + gr;
            *(float2*)&pr[(size_t)m0*N + n]     = make_float2(acc[mt][nt][0], acc[mt][nt][1]);
            *(float2*)&pr[(size_t)(m0+8)*N + n] = make_float2(acc[mt][nt][2], acc[mt][nt][3]);
        }
    }
}

// =====================================================================
// conv4/conv5 partial (f32x2), CIN split — unchanged
// =====================================================================
template<int CIN, int CINH, int KS, int STRIDE, int HIN, int WIN,
         int HOUT, int WOUT, int ICC>
__global__ void __launch_bounds__(128) conv_split(
    const float* __restrict__ in, const float* __restrict__ w,
    float* __restrict__ part)
{
    constexpr int TIN = 15*STRIDE + KS;
    __shared__ float xs[ICC*TIN*TIN];
    __shared__ float ws[ICC*KS*KS*16];

    const int tx = threadIdx.x, ty = threadIdx.y;
    const int tid = ty*16 + tx;
    const int z = blockIdx.z;
    const int b = z >> 1, split = z & 1;
    const int c0 = split*CINH;
    const int oy0 = blockIdx.y*16 + ty;
    const int ox  = blockIdx.x*16 + tx;
    const int iy0 = blockIdx.y*16*STRIDE;
    const int ix0 = blockIdx.x*16*STRIDE;

    u64 acc0[8], acc1[8];
#pragma unroll
    for (int q = 0; q < 8; q++) { acc0[q]=0ull; acc1[q]=0ull; }

    for (int cc = c0; cc < c0 + CINH; cc += ICC) {
        __syncthreads();
        for (int i = tid; i < ICC*TIN*TIN; i += 128) {
            int icl = i / (TIN*TIN), r = i - icl*(TIN*TIN);
            int yy = r / TIN, xx = r - yy*TIN;
            int gy = iy0 + yy, gx = ix0 + xx;
            float v = 0.f;
            if (gy < HIN && gx < WIN)
                v = in[(((size_t)b*CIN + cc + icl)*HIN + gy)*WIN + gx];
            xs[i] = v;
        }
        for (int i = tid; i < ICC*KS*KS*16; i += 128) {
            int oc = i & 15; int r = i >> 4;
            int icl = r / (KS*KS); int kk = r - icl*(KS*KS);
            ws[i] = w[((size_t)oc*CIN + cc + icl)*KS*KS + kk];
        }
        __syncthreads();
#pragma unroll 1
        for (int icl = 0; icl < ICC; icl++) {
            for (int kh = 0; kh < KS; kh++) {
                const float* x0 = &xs[icl*TIN*TIN + (ty*STRIDE + kh)*TIN + tx*STRIDE];
                const float* x1 = &xs[icl*TIN*TIN + ((ty+8)*STRIDE + kh)*TIN + tx*STRIDE];
                const float* wrow = &ws[(icl*KS*KS + kh*KS)*16];
#pragma unroll
                for (int kw = 0; kw < KS; kw++) {
                    u64 p0 = pk2(x0[kw]);
                    u64 p1 = pk2(x1[kw]);
                    const ulonglong2* wp = (const ulonglong2*)(wrow + kw*16);
#pragma unroll
                    for (int q = 0; q < 4; q++) {
                        ulonglong2 wv = wp[q];
                        fma2(acc0[2*q],   p0, wv.x); fma2(acc0[2*q+1], p0, wv.y);
                        fma2(acc1[2*q],   p1, wv.x); fma2(acc1[2*q+1], p1, wv.y);
                    }
                }
            }
        }
    }
    const size_t tot = (size_t)BATCH*16*HOUT*WOUT;
    float* pb = part + (size_t)split*tot;
    if (ox < WOUT) {
#pragma unroll
        for (int q = 0; q < 8; q++) {
            float2 f0 = unpk(acc0[q]), f1 = unpk(acc1[q]);
#pragma unroll
            for (int h = 0; h < 2; h++) {
                int oc = 2*q + h;
                float v0 = h ? f0.y : f0.x;
                float v1 = h ? f1.y : f1.x;
                if (oy0 < HOUT)
                    pb[(((size_t)b*16 + oc)*HOUT + oy0)*WOUT + ox] = v0;
                if (oy0 + 8 < HOUT)
                    pb[(((size_t)b*16 + oc)*HOUT + oy0 + 8)*WOUT + ox] = v1;
            }
        }
    }
}

__global__ void combine_relu(const float* __restrict__ p,
                             const float* __restrict__ bias,
                             float* __restrict__ out, int HW, int total)
{
    int i = blockIdx.x*256 + threadIdx.x;
    if (i >= total) return;
    int oc = (i / HW) & 15;
    out[i] = fmaxf(p[i] + p[i + total] + bias[oc], 0.f);
}

// =====================================================================
// fc_reduce / fc3 — unchanged
// =====================================================================
__global__ void fc_reduce(const float* __restrict__ part,
                          const float* __restrict__ bias,
                          float* __restrict__ out, int N, int KT, int do_relu)
{
    int i = blockIdx.x*256 + threadIdx.x;
    if (i >= 32*N) return;
    int n = i % N;
    float s = bias[n];
    for (int kt = 0; kt < KT; kt++) s += part[(size_t)kt*32*N + i];
    out[i] = do_relu ? fmaxf(s, 0.f) : s;
}

__global__ void __launch_bounds__(768) fc3_softmax(
    const float* __restrict__ x, const float* __restrict__ w,
    const float* __restrict__ bias, float* __restrict__ out)
{
    __shared__ float lg[24];
    const int b = blockIdx.x;
    const int tid = threadIdx.x;
    const int wo = tid >> 5, lane = tid & 31;

    const float* xr = x + (size_t)b*2048;
    const float* wr = w + (size_t)wo*2048;
    float s = 0.f;
    for (int k = lane; k < 2048; k += 32) s = fmaf(wr[k], xr[k], s);
#pragma unroll
    for (int off = 16; off; off >>= 1) s += __shfl_xor_sync(0xffffffffu, s, off);
    if (lane == 0) lg[wo] = s + bias[wo];
    __syncthreads();

    if (tid < 24) {
        int a = tid % 12;
        float z0 = lg[a], z1 = lg[12 + a];
        float m = fmaxf(z0, z1);
        float lse = m + logf(expf(z0 - m) + expf(z1 - m));
        out[b*24 + tid] = lg[tid] - lse;
    }
}

// =====================================================================
// launch
// =====================================================================
extern "C" void kernel_launch(void* const* d_in, const int* in_sizes, int n_in,
                              void* d_out, int out_size)
{
    const float* x        = (const float*)d_in[0];
    const float* conv1_w  = (const float*)d_in[1];
    const float* conv1_b  = (const float*)d_in[2];
    const float* rl_gamma = (const float*)d_in[3];
    const float* rl_beta  = (const float*)d_in[4];
    const float* rl_mean  = (const float*)d_in[5];
    const float* rl_var   = (const float*)d_in[6];
    const float* rl_cw    = (const float*)d_in[7];
    const float* rl_cb    = (const float*)d_in[8];
    const float* bn_gamma = (const float*)d_in[9];
    const float* bn_beta  = (const float*)d_in[10];
    const float* bn_mean  = (const float*)d_in[11];
    const float* bn_var   = (const float*)d_in[12];
    const float* conv2_w  = (const float*)d_in[13];
    const float* conv2_b  = (const float*)d_in[14];
    const float* conv3_w  = (const float*)d_in[15];
    const float* conv3_b  = (const float*)d_in[16];
    const float* conv4_w  = (const float*)d_in[17];
    const float* conv4_b  = (const float*)d_in[18];
    const float* conv5_w  = (const float*)d_in[19];
    const float* conv5_b  = (const float*)d_in[20];
    const float* fc1_w    = (const float*)d_in[21];
    const float* fc1_b    = (const float*)d_in[22];
    const float* fc2_w    = (const float*)d_in[23];
    const float* fc2_b    = (const float*)d_in[24];
    const float* fc3_w    = (const float*)d_in[25];
    const float* fc3_b    = (const float*)d_in[26];
    float* out = (float*)d_out;

    float *b1,*b2,*b3,*b4,*b5,*b6,*cp,*pt,*f1,*f2;
    cudaGetSymbolAddress((void**)&b1, g_buf1);
    cudaGetSymbolAddress((void**)&b2, g_buf2);
    cudaGetSymbolAddress((void**)&b3, g_buf3);
    cudaGetSymbolAddress((void**)&b4, g_buf4);
    cudaGetSymbolAddress((void**)&b5, g_buf5);
    cudaGetSymbolAddress((void**)&b6, g_buf6);
    cudaGetSymbolAddress((void**)&cp, g_cpart);
    cudaGetSymbolAddress((void**)&pt, g_part);
    cudaGetSymbolAddress((void**)&f1, g_fc1);
    cudaGetSymbolAddress((void**)&f2, g_fc2);

    const int c1_smem = (3276 + 11776 + 368 + 32) * 4;
    cudaFuncSetAttribute(conv1_tc,
                         cudaFuncAttributeMaxDynamicSharedMemorySize, c1_smem);
    const int reg_smem = (15488 + 9216 + 288) * 4;
    cudaFuncSetAttribute(region_tc,
                         cudaFuncAttributeMaxDynamicSharedMemorySize, reg_smem);
    const int c16_smem = (4232 + 8384 + 512 + 16) * 4;       // 52576
    cudaFuncSetAttribute(conv_tc16<32,80,80,73,73>,
                         cudaFuncAttributeMaxDynamicSharedMemorySize, c16_smem);
    cudaFuncSetAttribute(conv_tc16<16,73,73,66,66>,
                         cudaFuncAttributeMaxDynamicSharedMemorySize, c16_smem);

    // 1. conv1
    conv1_tc<<<dim3(5,10,BATCH), 256, c1_smem>>>(x, conv1_w, conv1_b, b1);

    // 2. region
    region_tc<<<BATCH*64, 256, reg_smem>>>(
        b1, rl_gamma, rl_beta, rl_mean, rl_var, rl_cw, rl_cb,
        bn_gamma, bn_beta, bn_mean, bn_var, b2);

    // 3. conv2: 32->16, 8x8, 80->73 (16x16 tiles)
    conv_tc16<32,80,80,73,73><<<dim3(5,5,BATCH), 256, c16_smem>>>(
        b2, conv2_w, conv2_b, b3);

    // 4. conv3: 16->16, 8x8, 73->66 (16x16 tiles)
    conv_tc16<16,73,73,66,66><<<dim3(5,5,BATCH), 256, c16_smem>>>(
        b3, conv3_w, conv3_b, b4);

    // 5. conv4 (CIN split 2x8)
    conv_split<16,8,6,2,66,66,31,31,4><<<dim3(2,2,BATCH*2), dim3(16,8)>>>(
        b4, conv4_w, cp);
    { int hw = 31*31, tot = BATCH*16*hw;
      combine_relu<<<(tot+255)/256, 256>>>(cp, conv4_b, b5, hw, tot); }

    // 6. conv5 (CIN split 2x8)
    conv_split<16,8,5,1,31,31,27,27,8><<<dim3(2,2,BATCH*2), dim3(16,8)>>>(
        b5, conv5_w, cp);
    { int hw = 27*27, tot = BATCH*16*hw;
      combine_relu<<<(tot+255)/256, 256>>>(cp, conv5_b, b6, hw, tot); }

    // 7. fc1: tf32 mma, KT=24 (klen=486, 24*486=11664 exact)
    fc_tc<<<dim3(32,24), 256>>>(b6, fc1_w, pt, 4096, 11664, 486);
    fc_reduce<<<512, 256>>>(pt, fc1_b, f1, 4096, 24, 1);

    // 8. fc2: tf32 mma, KT=16 (klen=256)
    fc_tc<<<dim3(16,16), 256>>>(f1, fc2_w, pt, 2048, 4096, 256);
    fc_reduce<<<256, 256>>>(pt, fc2_b, f2, 2048, 16, 1);

    // 9. fc3 + log_softmax
    fc3_softmax<<<BATCH, 768>>>(f2, fc3_w, fc3_b, out);
}

// round 8
// speedup vs baseline: 2.4871x; 1.0095x over previous
#include <cuda_runtime.h>
#include <cuda_bf16.h>
#include <math.h>
#include <stdint.h>

#define BATCH 32
#define EPS 1e-5f

__device__ __forceinline__ uint32_t f2tf(float f) {
    uint32_t r; asm("cvt.rna.tf32.f32 %0,%1;" : "=r"(r) : "f"(f)); return r;
}
__device__ __forceinline__ void mma8(float* c, uint32_t a0, uint32_t a1,
                                     uint32_t a2, uint32_t a3,
                                     uint32_t b0, uint32_t b1) {
    asm("mma.sync.aligned.m16n8k8.row.col.f32.tf32.tf32.f32 "
        "{%0,%1,%2,%3},{%4,%5,%6,%7},{%8,%9},{%0,%1,%2,%3};"
        : "+f"(c[0]), "+f"(c[1]), "+f"(c[2]), "+f"(c[3])
        : "r"(a0), "r"(a1), "r"(a2), "r"(a3), "r"(b0), "r"(b1));
}

// ---------------- scratch ----------------
__device__ float g_buf1[BATCH*32*160*160];
__device__ float g_buf2[BATCH*32*80*80];
__device__ float g_buf3[BATCH*16*73*73];
__device__ float g_buf4[BATCH*16*66*66];
__device__ float g_buf5[BATCH*16*31*31];
__device__ float g_buf6[BATCH*16*27*27];
__device__ float g_part[24*32*4096];
__device__ float g_fc1[BATCH*4096];
__device__ float g_fc2[BATCH*2048];

// =====================================================================
// conv1 (tf32): [32,3,170,170] -> [32,32,160,160], 11x11
// =====================================================================
__global__ void __launch_bounds__(256) conv1_tc(
    const float* __restrict__ x, const float* __restrict__ w,
    const float* __restrict__ bias, float* __restrict__ out)
{
    extern __shared__ uint32_t sm_u[];
    uint32_t* xs = sm_u;               // 3276
    uint32_t* ws = sm_u + 3276;        // 11776
    int* lut = (int*)(ws + 11776);     // 368
    float* bs = (float*)(lut + 368);   // 32

    const int tid = threadIdx.x, lane = tid & 31, wp = tid >> 5;
    const int b = blockIdx.z;
    const int iy0 = blockIdx.y*16, ix0 = blockIdx.x*32;

    for (int i = tid; i < 368; i += 256) {
        int v = 0;
        if (i < 363) {
            int c = i/121, r = i - c*121, kh = r/11, kw = r - kh*11;
            v = c*(26*42) + kh*42 + kw;
        }
        lut[i] = v;
    }
    for (int i = tid; i < 32*368; i += 256) {
        int oc = i / 368, k = i - oc*368;
        float v = (k < 363) ? w[oc*363 + k] : 0.f;
        ws[k*32 + oc] = f2tf(v);
    }
    const float* xb = x + (size_t)b*3*170*170;
    for (int i = tid; i < 3*26*42; i += 256) {
        int c = i / (26*42), r = i - c*(26*42), yy = r/42, xx = r - yy*42;
        xs[i] = f2tf(xb[((size_t)c*170 + iy0 + yy)*170 + ix0 + xx]);
    }
    if (tid < 32) bs[tid] = bias[tid];
    __syncthreads();

    float acc[4][4][4];
#pragma unroll
    for (int m = 0; m < 4; m++)
#pragma unroll
        for (int n = 0; n < 4; n++)
#pragma unroll
            for (int q = 0; q < 4; q++) acc[m][n][q] = 0.f;

    const int gr = lane >> 2, gc = lane & 3;
    int mb[4];
#pragma unroll
    for (int i = 0; i < 4; i++) {
        int t = wp*4 + i;
        mb[i] = (t >> 1)*42 + (t & 1)*16 + gr;
    }

    for (int k0 = 0; k0 < 368; k0 += 8) {
        int o1 = lut[k0 + gc], o2 = lut[k0 + gc + 4];
        const uint32_t* wk = &ws[(k0 + gc)*32 + gr];
        uint32_t bf0[4], bf1[4];
#pragma unroll
        for (int nt = 0; nt < 4; nt++) { bf0[nt] = wk[nt*8]; bf1[nt] = wk[128 + nt*8]; }
#pragma unroll
        for (int mt = 0; mt < 4; mt++) {
            uint32_t a0 = xs[mb[mt] + o1], a1 = xs[mb[mt] + 8 + o1];
            uint32_t a2 = xs[mb[mt] + o2], a3 = xs[mb[mt] + 8 + o2];
#pragma unroll
            for (int nt = 0; nt < 4; nt++)
                mma8(acc[mt][nt], a0, a1, a2, a3, bf0[nt], bf1[nt]);
        }
    }
#pragma unroll
    for (int mt = 0; mt < 4; mt++) {
        int t = wp*4 + mt;
        int yp = iy0 + (t >> 1), xp = ix0 + (t & 1)*16 + gr;
#pragma unroll
        for (int nt = 0; nt < 4; nt++) {
            int oc = nt*8 + gc*2;
            float* o0 = out + (((size_t)b*32 + oc)*160 + yp)*160 + xp;
            o0[0]     = acc[mt][nt][0] + bs[oc];
            o0[25600] = acc[mt][nt][1] + bs[oc+1];
            o0[8]     = acc[mt][nt][2] + bs[oc];
            o0[25608] = acc[mt][nt][3] + bs[oc+1];
        }
    }
}

// =====================================================================
// region (tf32) — per-patch GEMM + fused BN/res/relu/pool/BN2
// =====================================================================
__global__ void __launch_bounds__(256) region_tc(
    const float* __restrict__ in,
    const float* __restrict__ rl_gamma, const float* __restrict__ rl_beta,
    const float* __restrict__ rl_mean,  const float* __restrict__ rl_var,
    const float* __restrict__ rl_cw,    const float* __restrict__ rl_cb,
    const float* __restrict__ bn_g, const float* __restrict__ bn_b,
    const float* __restrict__ bn_m, const float* __restrict__ bn_v,
    float* __restrict__ out)
{
    extern __shared__ uint32_t smu[];
    uint32_t* act = smu;               // 15488
    uint32_t* ws  = smu + 15488;       // 9216
    int* lut = (int*)(ws + 9216);      // 288
    __shared__ float sc[32], sh[32], s2[32], t2[32], cb[32];

    const int blk = blockIdx.x;
    const int b = blk >> 6;
    const int patch = blk & 63;
    const int gi = patch >> 3, gj = patch & 7;
    const int kidx = gj*(gi+1);
    const int tid = threadIdx.x, lane = tid & 31, wp = tid >> 5;
    const int gr = lane >> 2, gc = lane & 3;

    if (tid < 32) {
        float g = rl_gamma[kidx*32+tid];
        float s = g * rsqrtf(rl_var[kidx*32+tid] + EPS);
        sc[tid] = s;
        sh[tid] = rl_beta[kidx*32+tid] - rl_mean[kidx*32+tid]*s;
        float ss = bn_g[tid] * rsqrtf(bn_v[tid] + EPS);
        s2[tid] = ss;
        t2[tid] = bn_b[tid] - bn_m[tid]*ss;
        cb[tid] = rl_cb[kidx*32+tid];
    }
    for (int i = tid; i < 15488; i += 256) act[i] = 0u;
    for (int i = tid; i < 288; i += 256) {
        int ic = i/9, r = i - ic*9;
        lut[i] = ic*484 + (r/3)*22 + (r%3);
    }
    __syncthreads();

    const float* inb = in + (size_t)b*32*160*160;
    for (int i = tid; i < 32*400; i += 256) {
        int ic = i / 400, r = i - ic*400;
        int y = r / 20, xx = r - y*20;
        float v = inb[((size_t)ic*160 + gi*20 + y)*160 + gj*20 + xx];
        act[ic*484 + (y+1)*22 + (xx+1)] = f2tf(fmaxf(fmaf(v, sc[ic], sh[ic]), 0.f));
    }
    for (int i = tid; i < 9216; i += 256) {
        int oc = i / 288, kk = i - oc*288;
        ws[kk*32 + oc] = f2tf(rl_cw[(size_t)kidx*9216 + i]);
    }
    __syncthreads();

    const int ntiles = (wp == 0) ? 4 : 3;
    int ra0[4], ra1[4];
#pragma unroll
    for (int ti = 0; ti < 4; ti++) {
        int t = wp + 8*ti;
        int p0 = t*16 + gr, p1 = p0 + 8;
        if (t < 25) {
            ra0[ti] = (p0/20)*22 + (p0%20);
            ra1[ti] = (p1/20)*22 + (p1%20);
        } else { ra0[ti] = 0; ra1[ti] = 0; }
    }

    float acc[4][4][4];
#pragma unroll
    for (int m = 0; m < 4; m++)
#pragma unroll
        for (int n = 0; n < 4; n++)
#pragma unroll
            for (int q = 0; q < 4; q++) acc[m][n][q] = 0.f;

    for (int k0 = 0; k0 < 288; k0 += 8) {
        int o1 = lut[k0 + gc], o2 = lut[k0 + gc + 4];
        const uint32_t* wk  = &ws[(k0 + gc)*32 + gr];
        const uint32_t* wk2 = &ws[(k0 + gc + 4)*32 + gr];
        uint32_t b0[4], b1[4];
#pragma unroll
        for (int nt = 0; nt < 4; nt++) { b0[nt] = wk[nt*8]; b1[nt] = wk2[nt*8]; }
#pragma unroll
        for (int ti = 0; ti < 4; ti++) {
            if (ti >= ntiles) break;
            uint32_t a0 = act[ra0[ti] + o1], a1 = act[ra1[ti] + o1];
            uint32_t a2 = act[ra0[ti] + o2], a3 = act[ra1[ti] + o2];
#pragma unroll
            for (int nt = 0; nt < 4; nt++)
                mma8(acc[ti][nt], a0, a1, a2, a3, b0[nt], b1[nt]);
        }
    }
    __syncthreads();

    float* res = (float*)smu;
#pragma unroll
    for (int ti = 0; ti < 4; ti++) {
        if (ti >= ntiles) break;
        int t = wp + 8*ti;
        int p0 = t*16 + gr, p1 = p0 + 8;
#pragma unroll
        for (int nt = 0; nt < 4; nt++) {
            int oc0 = nt*8 + 2*gc;
            res[oc0*400 + p0]     = acc[ti][nt][0];
            res[(oc0+1)*400 + p0] = acc[ti][nt][1];
            res[oc0*400 + p1]     = acc[ti][nt][2];
            res[(oc0+1)*400 + p1] = acc[ti][nt][3];
        }
    }
    __syncthreads();

    for (int item = tid; item < 3200; item += 256) {
        int oc = item / 100, pos = item - oc*100;
        int py = pos / 10, px = pos - py*10;
        float bv = cb[oc];
        const float* xrb = inb + ((size_t)oc*160 + gi*20 + 2*py)*160 + gj*20 + 2*px;
        int p = (2*py)*20 + 2*px;
        float v0 = fmaxf(res[oc*400 + p]      + bv + xrb[0],   0.f);
        float v1 = fmaxf(res[oc*400 + p + 1]  + bv + xrb[1],   0.f);
        float v2 = fmaxf(res[oc*400 + p + 20] + bv + xrb[160], 0.f);
        float v3 = fmaxf(res[oc*400 + p + 21] + bv + xrb[161], 0.f);
        float mx = fmaxf(fmaxf(v0, v1), fmaxf(v2, v3));
        out[(((size_t)b*32 + oc)*80 + gi*10 + py)*80 + gj*10 + px] =
            fmaf(mx, s2[oc], t2[oc]);
    }
}

// =====================================================================
// conv2/conv3 (tf32), 16x16 tile, 8x8 kernel, CIN chunk 8
// =====================================================================
template<int CIN, int HIN, int WIN, int HOUT, int WOUT>
__global__ void __launch_bounds__(256) conv_tc16(
    const float* __restrict__ in, const float* __restrict__ w,
    const float* __restrict__ bias, float* __restrict__ out)
{
    constexpr int TIH = 23, TIW = 23;
    extern __shared__ uint32_t sm_u[];
    uint32_t* xs = sm_u;               // 4232
    uint32_t* ws = sm_u + 4232;        // 8384
    int* lut = (int*)(ws + 8384);      // 512
    float* bs = (float*)(lut + 512);   // 16

    const int tid = threadIdx.x, lane = tid & 31, wp = tid >> 5;
    const int b = blockIdx.z;
    const int iy0 = blockIdx.y*16, ix0 = blockIdx.x*16;

    for (int i = tid; i < 512; i += 256) {
        int cl = i >> 6, r = i & 63, kh = r >> 3, kw = r & 7;
        lut[i] = cl*(TIH*TIW) + kh*TIW + kw;
    }
    if (tid < 16) bs[tid] = bias[tid];

    float acc[2][2][4];
#pragma unroll
    for (int m = 0; m < 2; m++)
#pragma unroll
        for (int n = 0; n < 2; n++)
#pragma unroll
            for (int q = 0; q < 4; q++) acc[m][n][q] = 0.f;

    const int gr = lane >> 2, gc = lane & 3;
    int mb[2];
#pragma unroll
    for (int i = 0; i < 2; i++) mb[i] = (wp*2 + i)*TIW + gr;

    for (int cc = 0; cc < CIN; cc += 8) {
        __syncthreads();
        for (int i = tid; i < 8*TIH*TIW; i += 256) {
            int cl = i / (TIH*TIW), r = i - cl*(TIH*TIW);
            int yy = r / TIW, xx = r - yy*TIW;
            int gy = iy0 + yy, gx = ix0 + xx;
            float v = 0.f;
            if (gy < HIN && gx < WIN)
                v = in[(((size_t)b*CIN + cc + cl)*HIN + gy)*WIN + gx];
            xs[i] = f2tf(v);
        }
        for (int i = tid; i < 16*512; i += 256) {
            int oc = i >> 9, kl = i & 511;
            int cl = kl >> 6, kk = kl & 63;
            ws[oc*524 + kl] = f2tf(w[((size_t)oc*CIN + cc + cl)*64 + kk]);
        }
        __syncthreads();

        for (int k0 = 0; k0 < 512; k0 += 8) {
            int o1 = lut[k0 + gc], o2 = lut[k0 + gc + 4];
            uint32_t bf0[2], bf1[2];
#pragma unroll
            for (int nt = 0; nt < 2; nt++) {
                const uint32_t* wp_ = &ws[(nt*8 + gr)*524 + k0];
                bf0[nt] = wp_[gc]; bf1[nt] = wp_[gc + 4];
            }
#pragma unroll
            for (int mt = 0; mt < 2; mt++) {
                uint32_t a0 = xs[mb[mt] + o1], a1 = xs[mb[mt] + 8 + o1];
                uint32_t a2 = xs[mb[mt] + o2], a3 = xs[mb[mt] + 8 + o2];
#pragma unroll
                for (int nt = 0; nt < 2; nt++)
                    mma8(acc[mt][nt], a0, a1, a2, a3, bf0[nt], bf1[nt]);
            }
        }
    }

    const size_t cstride = (size_t)HOUT*WOUT;
#pragma unroll
    for (int mt = 0; mt < 2; mt++) {
        int yp = iy0 + wp*2 + mt;
        int xp = ix0 + gr;
        if (yp < HOUT) {
#pragma unroll
            for (int nt = 0; nt < 2; nt++) {
                int oc = nt*8 + gc*2;
                float* o0 = out + (((size_t)b*16 + oc)*HOUT + yp)*WOUT + xp;
                if (xp < WOUT) {
                    o0[0]       = fmaxf(acc[mt][nt][0] + bs[oc],   0.f);
                    o0[cstride] = fmaxf(acc[mt][nt][1] + bs[oc+1], 0.f);
                }
                if (xp + 8 < WOUT) {
                    o0[8]         = fmaxf(acc[mt][nt][2] + bs[oc],   0.f);
                    o0[cstride+8] = fmaxf(acc[mt][nt][3] + bs[oc+1], 0.f);
                }
            }
        }
    }
}

// =====================================================================
// conv4/conv5 (tf32): generic small conv, 16x16 tile, stride support,
// CIN chunk 8, fused bias+relu.  16 output channels.
// =====================================================================
template<int CIN, int KS, int STRIDE, int HIN, int WIN, int HOUT, int WOUT>
__global__ void __launch_bounds__(256) conv_tcS(
    const float* __restrict__ in, const float* __restrict__ w,
    const float* __restrict__ bias, float* __restrict__ out)
{
    constexpr int TIW = 15*STRIDE + KS;
    constexpr int KCH = 8*KS*KS;       // K per 8-ic chunk (288 / 200)
    constexpr int KP  = KCH + 4;
    extern __shared__ uint32_t sm_u[];
    uint32_t* xs = sm_u;               // 8*TIW*TIW
    uint32_t* ws = xs + 8*TIW*TIW;     // 16*KP
    int* lut = (int*)(ws + 16*KP);     // KCH
    float* bs = (float*)(lut + KCH);   // 16

    const int tid = threadIdx.x, lane = tid & 31, wp = tid >> 5;
    const int b = blockIdx.z;
    const int iy0in = blockIdx.y*16*STRIDE, ix0in = blockIdx.x*16*STRIDE;

    for (int i = tid; i < KCH; i += 256) {
        int cl = i / (KS*KS), r = i - cl*(KS*KS);
        lut[i] = cl*(TIW*TIW) + (r/KS)*TIW + (r%KS);
    }
    if (tid < 16) bs[tid] = bias[tid];

    float acc[2][2][4];
#pragma unroll
    for (int m = 0; m < 2; m++)
#pragma unroll
        for (int n = 0; n < 2; n++)
#pragma unroll
            for (int q = 0; q < 4; q++) acc[m][n][q] = 0.f;

    const int gr = lane >> 2, gc = lane & 3;
    int mb[2];
#pragma unroll
    for (int i = 0; i < 2; i++)
        mb[i] = (STRIDE*(wp*2 + i))*TIW + STRIDE*gr;
    const int a1off = 8*STRIDE;

    for (int cc = 0; cc < CIN; cc += 8) {
        __syncthreads();
        for (int i = tid; i < 8*TIW*TIW; i += 256) {
            int cl = i / (TIW*TIW), r = i - cl*(TIW*TIW);
            int yy = r / TIW, xx = r - yy*TIW;
            int gy = iy0in + yy, gx = ix0in + xx;
            float v = 0.f;
            if (gy < HIN && gx < WIN)
                v = in[(((size_t)b*CIN + cc + cl)*HIN + gy)*WIN + gx];
            xs[i] = f2tf(v);
        }
        for (int i = tid; i < 16*KCH; i += 256) {
            int oc = i / KCH, kl = i - oc*KCH;
            int cl = kl / (KS*KS), kk = kl - cl*(KS*KS);
            ws[oc*KP + kl] = f2tf(w[((size_t)oc*CIN + cc + cl)*(KS*KS) + kk]);
        }
        __syncthreads();

        for (int k0 = 0; k0 < KCH; k0 += 8) {
            int o1 = lut[k0 + gc], o2 = lut[k0 + gc + 4];
            uint32_t bf0[2], bf1[2];
#pragma unroll
            for (int nt = 0; nt < 2; nt++) {
                const uint32_t* wp_ = &ws[(nt*8 + gr)*KP + k0];
                bf0[nt] = wp_[gc]; bf1[nt] = wp_[gc + 4];
            }
#pragma unroll
            for (int mt = 0; mt < 2; mt++) {
                uint32_t a0 = xs[mb[mt] + o1], a1 = xs[mb[mt] + a1off + o1];
                uint32_t a2 = xs[mb[mt] + o2], a3 = xs[mb[mt] + a1off + o2];
#pragma unroll
                for (int nt = 0; nt < 2; nt++)
                    mma8(acc[mt][nt], a0, a1, a2, a3, bf0[nt], bf1[nt]);
            }
        }
    }

    const size_t cstride = (size_t)HOUT*WOUT;
#pragma unroll
    for (int mt = 0; mt < 2; mt++) {
        int yp = blockIdx.y*16 + wp*2 + mt;
        int xp = blockIdx.x*16 + gr;
        if (yp < HOUT) {
#pragma unroll
            for (int nt = 0; nt < 2; nt++) {
                int oc = nt*8 + gc*2;
                float* o0 = out + (((size_t)b*16 + oc)*HOUT + yp)*WOUT + xp;
                if (xp < WOUT) {
                    o0[0]       = fmaxf(acc[mt][nt][0] + bs[oc],   0.f);
                    o0[cstride] = fmaxf(acc[mt][nt][1] + bs[oc+1], 0.f);
                }
                if (xp + 8 < WOUT) {
                    o0[8]         = fmaxf(acc[mt][nt][2] + bs[oc],   0.f);
                    o0[cstride+8] = fmaxf(acc[mt][nt][3] + bs[oc+1], 0.f);
                }
            }
        }
    }
}

// =====================================================================
// fc (tf32): partial GEMM, M=32, N-tile 128, K-chunk 64
// =====================================================================
__global__ void __launch_bounds__(256) fc_tc(
    const float* __restrict__ x, const float* __restrict__ w,
    float* __restrict__ part, int N, int K, int klen)
{
    __shared__ uint32_t as[32*68];
    __shared__ uint32_t bsm[128*68];

    const int tid = threadIdx.x, lane = tid & 31, wp = tid >> 5;
    const int n0 = blockIdx.x*128;
    const int kstart = blockIdx.y*klen;
    const int gr = lane >> 2, gc = lane & 3;
    const int nb = wp*16;

    float acc[2][2][4];
#pragma unroll
    for (int m = 0; m < 2; m++)
#pragma unroll
        for (int n = 0; n < 2; n++)
#pragma unroll
            for (int q = 0; q < 4; q++) acc[m][n][q] = 0.f;

    for (int kc = 0; kc < klen; kc += 64) {
        int cl = min(64, klen - kc);
        __syncthreads();
        for (int i = tid; i < 2048; i += 256) {
            int m = i >> 6, k = i & 63;
            float v = (k < cl) ? x[(size_t)m*K + kstart + kc + k] : 0.f;
            as[m*68 + k] = f2tf(v);
        }
        for (int i = tid; i < 8192; i += 256) {
            int n = i >> 6, k = i & 63;
            float v = (k < cl) ? w[(size_t)(n0 + n)*K + kstart + kc + k] : 0.f;
            bsm[n*68 + k] = f2tf(v);
        }
        __syncthreads();

#pragma unroll
        for (int k0 = 0; k0 < 64; k0 += 8) {
            uint32_t a0[2], a1[2], a2[2], a3[2];
#pragma unroll
            for (int mt = 0; mt < 2; mt++) {
                const uint32_t* ap = &as[(mt*16 + gr)*68 + k0];
                a0[mt] = ap[gc];        a2[mt] = ap[gc + 4];
                a1[mt] = ap[8*68 + gc]; a3[mt] = ap[8*68 + gc + 4];
            }
#pragma unroll
            for (int nt = 0; nt < 2; nt++) {
                const uint32_t* bp = &bsm[(nb + nt*8 + gr)*68 + k0];
                uint32_t b0 = bp[gc], b1 = bp[gc + 4];
#pragma unroll
                for (int mt = 0; mt < 2; mt++)
                    mma8(acc[mt][nt], a0[mt], a1[mt], a2[mt], a3[mt], b0, b1);
            }
        }
    }

    float* pr = part + (size_t)blockIdx.y*32*N;
#pragma unroll
    for (int mt = 0; mt < 2; mt++) {
#pragma unroll
        for (int nt = 0; nt < 2; nt++) {
            int n = n0 + nb + nt*8 + 2*gc;
            int m0 = mt*16 + gr;
            *(float2*)&pr[(size_t)m0*N + n]     = make_float2(acc[mt][nt][0], acc[mt][nt][1]);
            *(float2*)&pr[(size_t)(m0+8)*N + n] = make_float2(acc[mt][nt][2], acc[mt][nt][3]);
        }
    }
}

__global__ void fc_reduce(const float* __restrict__ part,
                          const float* __restrict__ bias,
                          float* __restrict__ out, int N, int KT, int do_relu)
{
    int i = blockIdx.x*256 + threadIdx.x;
    if (i >= 32*N) return;
    int n = i % N;
    float s = bias[n];
    for (int kt = 0; kt < KT; kt++) s += part[(size_t)kt*32*N + i];
    out[i] = do_relu ? fmaxf(s, 0.f) : s;
}

__global__ void __launch_bounds__(768) fc3_softmax(
    const float* __restrict__ x, const float* __restrict__ w,
    const float* __restrict__ bias, float* __restrict__ out)
{
    __shared__ float lg[24];
    const int b = blockIdx.x;
    const int tid = threadIdx.x;
    const int wo = tid >> 5, lane = tid & 31;

    const float* xr = x + (size_t)b*2048;
    const float* wr = w + (size_t)wo*2048;
    float s = 0.f;
    for (int k = lane; k < 2048; k += 32) s = fmaf(wr[k], xr[k], s);
#pragma unroll
    for (int off = 16; off; off >>= 1) s += __shfl_xor_sync(0xffffffffu, s, off);
    if (lane == 0) lg[wo] = s + bias[wo];
    __syncthreads();

    if (tid < 24) {
        int a = tid % 12;
        float z0 = lg[a], z1 = lg[12 + a];
        float m = fmaxf(z0, z1);
        float lse = m + logf(expf(z0 - m) + expf(z1 - m));
        out[b*24 + tid] = lg[tid] - lse;
    }
}

// =====================================================================
// launch
// =====================================================================
extern "C" void kernel_launch(void* const* d_in, const int* in_sizes, int n_in,
                              void* d_out, int out_size)
{
    const float* x        = (const float*)d_in[0];
    const float* conv1_w  = (const float*)d_in[1];
    const float* conv1_b  = (const float*)d_in[2];
    const float* rl_gamma = (const float*)d_in[3];
    const float* rl_beta  = (const float*)d_in[4];
    const float* rl_mean  = (const float*)d_in[5];
    const float* rl_var   = (const float*)d_in[6];
    const float* rl_cw    = (const float*)d_in[7];
    const float* rl_cb    = (const float*)d_in[8];
    const float* bn_gamma = (const float*)d_in[9];
    const float* bn_beta  = (const float*)d_in[10];
    const float* bn_mean  = (const float*)d_in[11];
    const float* bn_var   = (const float*)d_in[12];
    const float* conv2_w  = (const float*)d_in[13];
    const float* conv2_b  = (const float*)d_in[14];
    const float* conv3_w  = (const float*)d_in[15];
    const float* conv3_b  = (const float*)d_in[16];
    const float* conv4_w  = (const float*)d_in[17];
    const float* conv4_b  = (const float*)d_in[18];
    const float* conv5_w  = (const float*)d_in[19];
    const float* conv5_b  = (const float*)d_in[20];
    const float* fc1_w    = (const float*)d_in[21];
    const float* fc1_b    = (const float*)d_in[22];
    const float* fc2_w    = (const float*)d_in[23];
    const float* fc2_b    = (const float*)d_in[24];
    const float* fc3_w    = (const float*)d_in[25];
    const float* fc3_b    = (const float*)d_in[26];
    float* out = (float*)d_out;

    float *b1,*b2,*b3,*b4,*b5,*b6,*pt,*f1,*f2;
    cudaGetSymbolAddress((void**)&b1, g_buf1);
    cudaGetSymbolAddress((void**)&b2, g_buf2);
    cudaGetSymbolAddress((void**)&b3, g_buf3);
    cudaGetSymbolAddress((void**)&b4, g_buf4);
    cudaGetSymbolAddress((void**)&b5, g_buf5);
    cudaGetSymbolAddress((void**)&b6, g_buf6);
    cudaGetSymbolAddress((void**)&pt, g_part);
    cudaGetSymbolAddress((void**)&f1, g_fc1);
    cudaGetSymbolAddress((void**)&f2, g_fc2);

    const int c1_smem = (3276 + 11776 + 368 + 32) * 4;
    cudaFuncSetAttribute(conv1_tc,
                         cudaFuncAttributeMaxDynamicSharedMemorySize, c1_smem);
    const int reg_smem = (15488 + 9216 + 288) * 4;
    cudaFuncSetAttribute(region_tc,
                         cudaFuncAttributeMaxDynamicSharedMemorySize, reg_smem);
    const int c16_smem = (4232 + 8384 + 512 + 16) * 4;
    cudaFuncSetAttribute(conv_tc16<32,80,80,73,73>,
                         cudaFuncAttributeMaxDynamicSharedMemorySize, c16_smem);
    cudaFuncSetAttribute(conv_tc16<16,73,73,66,66>,
                         cudaFuncAttributeMaxDynamicSharedMemorySize, c16_smem);
    // conv4: TIW=36, KCH=288, KP=292: 8*1296 + 16*292 + 288 + 16 = 15344 u32
    const int c4_smem = (8*36*36 + 16*292 + 288 + 16) * 4;
    cudaFuncSetAttribute(conv_tcS<16,6,2,66,66,31,31>,
                         cudaFuncAttributeMaxDynamicSharedMemorySize, c4_smem);
    // conv5: TIW=20, KCH=200, KP=204: 8*400 + 16*204 + 200 + 16 = 6680 u32
    const int c5_smem = (8*20*20 + 16*204 + 200 + 16) * 4;
    cudaFuncSetAttribute(conv_tcS<16,5,1,31,31,27,27>,
                         cudaFuncAttributeMaxDynamicSharedMemorySize, c5_smem);

    // 1. conv1
    conv1_tc<<<dim3(5,10,BATCH), 256, c1_smem>>>(x, conv1_w, conv1_b, b1);

    // 2. region
    region_tc<<<BATCH*64, 256, reg_smem>>>(
        b1, rl_gamma, rl_beta, rl_mean, rl_var, rl_cw, rl_cb,
        bn_gamma, bn_beta, bn_mean, bn_var, b2);

    // 3. conv2: 32->16, 8x8, 80->73
    conv_tc16<32,80,80,73,73><<<dim3(5,5,BATCH), 256, c16_smem>>>(
        b2, conv2_w, conv2_b, b3);

    // 4. conv3: 16->16, 8x8, 73->66
    conv_tc16<16,73,73,66,66><<<dim3(5,5,BATCH), 256, c16_smem>>>(
        b3, conv3_w, conv3_b, b4);

    // 5. conv4: 16->16, 6x6 s2, 66->31 (tensor, fused)
    conv_tcS<16,6,2,66,66,31,31><<<dim3(2,2,BATCH), 256, c4_smem>>>(
        b4, conv4_w, conv4_b, b5);

    // 6. conv5: 16->16, 5x5, 31->27 (tensor, fused)
    conv_tcS<16,5,1,31,31,27,27><<<dim3(2,2,BATCH), 256, c5_smem>>>(
        b5, conv5_w, conv5_b, b6);

    // 7. fc1: KT=24, klen=486
    fc_tc<<<dim3(32,24), 256>>>(b6, fc1_w, pt, 4096, 11664, 486);
    fc_reduce<<<512, 256>>>(pt, fc1_b, f1, 4096, 24, 1);

    // 8. fc2: KT=16, klen=256
    fc_tc<<<dim3(16,16), 256>>>(f1, fc2_w, pt, 2048, 4096, 256);
    fc_reduce<<<256, 256>>>(pt, fc2_b, f2, 2048, 16, 1);

    // 9. fc3 + log_softmax
    fc3_softmax<<<BATCH, 768>>>(f2, fc3_w, fc3_b, out);
}

// round 9
// speedup vs baseline: 2.8590x; 1.1495x over previous
#include <cuda_runtime.h>
#include <cuda_fp16.h>
#include <cuda_bf16.h>
#include <math.h>
#include <stdint.h>

#define BATCH 32
#define EPS 1e-5f

__device__ __forceinline__ uint32_t f2tf(float f) {
    uint32_t r; asm("cvt.rna.tf32.f32 %0,%1;" : "=r"(r) : "f"(f)); return r;
}
// tf32 m16n8k8
__device__ __forceinline__ void mma8(float* c, uint32_t a0, uint32_t a1,
                                     uint32_t a2, uint32_t a3,
                                     uint32_t b0, uint32_t b1) {
    asm("mma.sync.aligned.m16n8k8.row.col.f32.tf32.tf32.f32 "
        "{%0,%1,%2,%3},{%4,%5,%6,%7},{%8,%9},{%0,%1,%2,%3};"
        : "+f"(c[0]), "+f"(c[1]), "+f"(c[2]), "+f"(c[3])
        : "r"(a0), "r"(a1), "r"(a2), "r"(a3), "r"(b0), "r"(b1));
}
// fp16 m16n8k16, fp32 accum
__device__ __forceinline__ void mma16(float* c, uint32_t a0, uint32_t a1,
                                      uint32_t a2, uint32_t a3,
                                      uint32_t b0, uint32_t b1) {
    asm("mma.sync.aligned.m16n8k16.row.col.f32.f16.f16.f32 "
        "{%0,%1,%2,%3},{%4,%5,%6,%7},{%8,%9},{%0,%1,%2,%3};"
        : "+f"(c[0]), "+f"(c[1]), "+f"(c[2]), "+f"(c[3])
        : "r"(a0), "r"(a1), "r"(a2), "r"(a3), "r"(b0), "r"(b1));
}
__device__ __forceinline__ uint32_t ldu32(const __half* p) {
    return *(const uint32_t*)p;
}

// ---------------- scratch ----------------
__device__ float g_buf1[BATCH*32*160*160];
__device__ float g_buf2[BATCH*32*80*80];
__device__ float g_buf3[BATCH*16*73*73];
__device__ float g_buf4[BATCH*16*66*66];
__device__ float g_buf5[BATCH*16*31*31];
__device__ float g_buf6[BATCH*16*27*27];
__device__ float g_part[24*32*4096];
__device__ float g_fc1[BATCH*4096];
__device__ float g_fc2[BATCH*2048];

// =====================================================================
// conv1 (fp16 mma): [32,3,170,170] -> [32,32,160,160], 11x11
// staging xs[26][42][4ic] half (ic padded 3->4); k' = kh*48 + kw*4 + ic,
// kw padded 11->12. K' = 528 = 33 k16-steps. out tile 32x16 px, 32 oc.
// =====================================================================
#define C1_KP 536
__global__ void __launch_bounds__(256) conv1_h(
    const float* __restrict__ x, const float* __restrict__ w,
    const float* __restrict__ bias, float* __restrict__ out)
{
    extern __shared__ __half smh[];
    __half* xs = smh;                   // 4368 + 64 pad = 4432
    __half* ws = smh + 4432;            // 32*536 = 17152
    float* bs = (float*)(ws + 32*C1_KP);// 32

    const int tid = threadIdx.x, lane = tid & 31, wp = tid >> 5;
    const int b = blockIdx.z;
    const int iy0 = blockIdx.y*16, ix0 = blockIdx.x*32;
    const int gr = lane >> 2, gc = lane & 3;

    // stage input (ic innermost, pad ic=3 and tail with zeros)
    for (int i = tid; i < 4432; i += 256) {
        float v = 0.f;
        if (i < 4368) {
            int p = i >> 2, ic = i & 3;
            int yy = p / 42, xx = p - yy*42;
            if (ic < 3)
                v = x[(((size_t)b*3 + ic)*170 + iy0 + yy)*170 + ix0 + xx];
        }
        xs[i] = __float2half_rn(v);
    }
    // weights: k' = kh*48 + kw*4 + ic
    for (int i = tid; i < 32*528; i += 256) {
        int oc = i / 528, kl = i - oc*528;
        int kh = kl / 48, r = kl - kh*48;
        int kw = r >> 2, ic = r & 3;
        float v = (ic < 3 && kw < 11) ? w[oc*363 + ic*121 + kh*11 + kw] : 0.f;
        ws[oc*C1_KP + kl] = __float2half_rn(v);
    }
    if (tid < 32) bs[tid] = bias[tid];
    __syncthreads();

    float acc[4][4][4];
#pragma unroll
    for (int m = 0; m < 4; m++)
#pragma unroll
        for (int n = 0; n < 4; n++)
#pragma unroll
            for (int q = 0; q < 4; q++) acc[m][n][q] = 0.f;

    const int icl = 2*(gc & 1);         // ic of this thread's k-pair
    const int kwl = gc >> 1;            // kw sub-offset

    for (int j = 0; j < 33; j++) {
        int kh = j / 3, sub = j - kh*3;
        int kw0 = sub*4;
        int k0 = j*16;
        uint32_t bf0[4], bf1[4];
#pragma unroll
        for (int nt = 0; nt < 4; nt++) {
            const __half* bp = &ws[(nt*8 + gr)*C1_KP + k0 + 2*gc];
            bf0[nt] = ldu32(bp); bf1[nt] = ldu32(bp + 8);
        }
#pragma unroll
        for (int mt = 0; mt < 4; mt++) {
            int t = wp*4 + mt;
            int py = t >> 1, pxh = (t & 1)*16;
            int abase = ((py + kh)*42 + pxh + gr + kw0 + kwl)*4 + icl;
            uint32_t a0 = ldu32(&xs[abase]);
            uint32_t a1 = ldu32(&xs[abase + 32]);   // pixel +8
            uint32_t a2 = ldu32(&xs[abase + 8]);    // k +8 (kw +2)
            uint32_t a3 = ldu32(&xs[abase + 40]);
#pragma unroll
            for (int nt = 0; nt < 4; nt++)
                mma16(acc[mt][nt], a0, a1, a2, a3, bf0[nt], bf1[nt]);
        }
    }
#pragma unroll
    for (int mt = 0; mt < 4; mt++) {
        int t = wp*4 + mt;
        int yp = iy0 + (t >> 1), xp = ix0 + (t & 1)*16 + gr;
#pragma unroll
        for (int nt = 0; nt < 4; nt++) {
            int oc = nt*8 + gc*2;
            float* o0 = out + (((size_t)b*32 + oc)*160 + yp)*160 + xp;
            o0[0]     = acc[mt][nt][0] + bs[oc];
            o0[25600] = acc[mt][nt][1] + bs[oc+1];
            o0[8]     = acc[mt][nt][2] + bs[oc];
            o0[25608] = acc[mt][nt][3] + bs[oc+1];
        }
    }
}

// =====================================================================
// region (tf32) — unchanged
// =====================================================================
__global__ void __launch_bounds__(256) region_tc(
    const float* __restrict__ in,
    const float* __restrict__ rl_gamma, const float* __restrict__ rl_beta,
    const float* __restrict__ rl_mean,  const float* __restrict__ rl_var,
    const float* __restrict__ rl_cw,    const float* __restrict__ rl_cb,
    const float* __restrict__ bn_g, const float* __restrict__ bn_b,
    const float* __restrict__ bn_m, const float* __restrict__ bn_v,
    float* __restrict__ out)
{
    extern __shared__ uint32_t smu[];
    uint32_t* act = smu;               // 15488
    uint32_t* ws  = smu + 15488;       // 9216
    int* lut = (int*)(ws + 9216);      // 288
    __shared__ float sc[32], sh[32], s2[32], t2[32], cb[32];

    const int blk = blockIdx.x;
    const int b = blk >> 6;
    const int patch = blk & 63;
    const int gi = patch >> 3, gj = patch & 7;
    const int kidx = gj*(gi+1);
    const int tid = threadIdx.x, lane = tid & 31, wp = tid >> 5;
    const int gr = lane >> 2, gc = lane & 3;

    if (tid < 32) {
        float g = rl_gamma[kidx*32+tid];
        float s = g * rsqrtf(rl_var[kidx*32+tid] + EPS);
        sc[tid] = s;
        sh[tid] = rl_beta[kidx*32+tid] - rl_mean[kidx*32+tid]*s;
        float ss = bn_g[tid] * rsqrtf(bn_v[tid] + EPS);
        s2[tid] = ss;
        t2[tid] = bn_b[tid] - bn_m[tid]*ss;
        cb[tid] = rl_cb[kidx*32+tid];
    }
    for (int i = tid; i < 15488; i += 256) act[i] = 0u;
    for (int i = tid; i < 288; i += 256) {
        int ic = i/9, r = i - ic*9;
        lut[i] = ic*484 + (r/3)*22 + (r%3);
    }
    __syncthreads();

    const float* inb = in + (size_t)b*32*160*160;
    for (int i = tid; i < 32*400; i += 256) {
        int ic = i / 400, r = i - ic*400;
        int y = r / 20, xx = r - y*20;
        float v = inb[((size_t)ic*160 + gi*20 + y)*160 + gj*20 + xx];
        act[ic*484 + (y+1)*22 + (xx+1)] = f2tf(fmaxf(fmaf(v, sc[ic], sh[ic]), 0.f));
    }
    for (int i = tid; i < 9216; i += 256) {
        int oc = i / 288, kk = i - oc*288;
        ws[kk*32 + oc] = f2tf(rl_cw[(size_t)kidx*9216 + i]);
    }
    __syncthreads();

    const int ntiles = (wp == 0) ? 4 : 3;
    int ra0[4], ra1[4];
#pragma unroll
    for (int ti = 0; ti < 4; ti++) {
        int t = wp + 8*ti;
        int p0 = t*16 + gr, p1 = p0 + 8;
        if (t < 25) {
            ra0[ti] = (p0/20)*22 + (p0%20);
            ra1[ti] = (p1/20)*22 + (p1%20);
        } else { ra0[ti] = 0; ra1[ti] = 0; }
    }

    float acc[4][4][4];
#pragma unroll
    for (int m = 0; m < 4; m++)
#pragma unroll
        for (int n = 0; n < 4; n++)
#pragma unroll
            for (int q = 0; q < 4; q++) acc[m][n][q] = 0.f;

    for (int k0 = 0; k0 < 288; k0 += 8) {
        int o1 = lut[k0 + gc], o2 = lut[k0 + gc + 4];
        const uint32_t* wk  = &ws[(k0 + gc)*32 + gr];
        const uint32_t* wk2 = &ws[(k0 + gc + 4)*32 + gr];
        uint32_t b0[4], b1[4];
#pragma unroll
        for (int nt = 0; nt < 4; nt++) { b0[nt] = wk[nt*8]; b1[nt] = wk2[nt*8]; }
#pragma unroll
        for (int ti = 0; ti < 4; ti++) {
            if (ti >= ntiles) break;
            uint32_t a0 = act[ra0[ti] + o1], a1 = act[ra1[ti] + o1];
            uint32_t a2 = act[ra0[ti] + o2], a3 = act[ra1[ti] + o2];
#pragma unroll
            for (int nt = 0; nt < 4; nt++)
                mma8(acc[ti][nt], a0, a1, a2, a3, b0[nt], b1[nt]);
        }
    }
    __syncthreads();

    float* res = (float*)smu;
#pragma unroll
    for (int ti = 0; ti < 4; ti++) {
        if (ti >= ntiles) break;
        int t = wp + 8*ti;
        int p0 = t*16 + gr, p1 = p0 + 8;
#pragma unroll
        for (int nt = 0; nt < 4; nt++) {
            int oc0 = nt*8 + 2*gc;
            res[oc0*400 + p0]     = acc[ti][nt][0];
            res[(oc0+1)*400 + p0] = acc[ti][nt][1];
            res[oc0*400 + p1]     = acc[ti][nt][2];
            res[(oc0+1)*400 + p1] = acc[ti][nt][3];
        }
    }
    __syncthreads();

    for (int item = tid; item < 3200; item += 256) {
        int oc = item / 100, pos = item - oc*100;
        int py = pos / 10, px = pos - py*10;
        float bv = cb[oc];
        const float* xrb = inb + ((size_t)oc*160 + gi*20 + 2*py)*160 + gj*20 + 2*px;
        int p = (2*py)*20 + 2*px;
        float v0 = fmaxf(res[oc*400 + p]      + bv + xrb[0],   0.f);
        float v1 = fmaxf(res[oc*400 + p + 1]  + bv + xrb[1],   0.f);
        float v2 = fmaxf(res[oc*400 + p + 20] + bv + xrb[160], 0.f);
        float v3 = fmaxf(res[oc*400 + p + 21] + bv + xrb[161], 0.f);
        float mx = fmaxf(fmaxf(v0, v1), fmaxf(v2, v3));
        out[(((size_t)b*32 + oc)*80 + gi*10 + py)*80 + gj*10 + px] =
            fmaf(mx, s2[oc], t2[oc]);
    }
}

// =====================================================================
// conv2/conv3 (fp16 mma): 8x8 kernel, COUT=16, 16x16 tile.
// staging xs[23][23][8ic] half; k' = kh*64 + kw*8 + ic; 32 k16/chunk.
// =====================================================================
#define C2_KP 520
template<int CIN, int HIN, int WIN, int HOUT, int WOUT>
__global__ void __launch_bounds__(256) conv_tc16h(
    const float* __restrict__ in, const float* __restrict__ w,
    const float* __restrict__ bias, float* __restrict__ out)
{
    extern __shared__ __half smh[];
    __half* xs = smh;                   // 23*23*8 = 4232 (+8 pad -> 4240)
    __half* ws = smh + 4240;            // 16*520 = 8320
    float* bs = (float*)(ws + 16*C2_KP);// 16

    const int tid = threadIdx.x, lane = tid & 31, wp = tid >> 5;
    const int b = blockIdx.z;
    const int iy0 = blockIdx.y*16, ix0 = blockIdx.x*16;
    const int gr = lane >> 2, gc = lane & 3;

    if (tid < 16) bs[tid] = bias[tid];

    float acc[2][2][4];
#pragma unroll
    for (int m = 0; m < 2; m++)
#pragma unroll
        for (int n = 0; n < 2; n++)
#pragma unroll
            for (int q = 0; q < 4; q++) acc[m][n][q] = 0.f;

    for (int cc = 0; cc < CIN; cc += 8) {
        __syncthreads();
        // stage xs[pix][ic] (ic innermost)
        for (int i = tid; i < 4232; i += 256) {
            int p = i >> 3, ic = i & 7;
            int yy = p / 23, xx = p - yy*23;
            int gy = iy0 + yy, gx = ix0 + xx;
            float v = 0.f;
            if (gy < HIN && gx < WIN)
                v = in[(((size_t)b*CIN + cc + ic)*HIN + gy)*WIN + gx];
            xs[i] = __float2half_rn(v);
        }
        // weights: k' = kh*64 + kw*8 + ic
        for (int i = tid; i < 16*512; i += 256) {
            int oc = i >> 9, kl = i & 511;
            int kh = kl >> 6, kw = (kl >> 3) & 7, ic = kl & 7;
            ws[oc*C2_KP + kl] = __float2half_rn(
                w[((size_t)oc*CIN + cc + ic)*64 + kh*8 + kw]);
        }
        __syncthreads();

        for (int j = 0; j < 32; j++) {
            int kh = j >> 2, kw0 = (j & 3)*2;
            int k0 = j*16;
            uint32_t bf0[2], bf1[2];
#pragma unroll
            for (int nt = 0; nt < 2; nt++) {
                const __half* bp = &ws[(nt*8 + gr)*C2_KP + k0 + 2*gc];
                bf0[nt] = ldu32(bp); bf1[nt] = ldu32(bp + 8);
            }
#pragma unroll
            for (int mt = 0; mt < 2; mt++) {
                int abase = ((wp*2 + mt + kh)*23 + gr + kw0)*8 + 2*gc;
                uint32_t a0 = ldu32(&xs[abase]);
                uint32_t a1 = ldu32(&xs[abase + 64]);   // pixel +8
                uint32_t a2 = ldu32(&xs[abase + 8]);    // kw +1
                uint32_t a3 = ldu32(&xs[abase + 72]);
#pragma unroll
                for (int nt = 0; nt < 2; nt++)
                    mma16(acc[mt][nt], a0, a1, a2, a3, bf0[nt], bf1[nt]);
            }
        }
    }

    const size_t cstride = (size_t)HOUT*WOUT;
#pragma unroll
    for (int mt = 0; mt < 2; mt++) {
        int yp = iy0 + wp*2 + mt;
        int xp = ix0 + gr;
        if (yp < HOUT) {
#pragma unroll
            for (int nt = 0; nt < 2; nt++) {
                int oc = nt*8 + gc*2;
                float* o0 = out + (((size_t)b*16 + oc)*HOUT + yp)*WOUT + xp;
                if (xp < WOUT) {
                    o0[0]       = fmaxf(acc[mt][nt][0] + bs[oc],   0.f);
                    o0[cstride] = fmaxf(acc[mt][nt][1] + bs[oc+1], 0.f);
                }
                if (xp + 8 < WOUT) {
                    o0[8]         = fmaxf(acc[mt][nt][2] + bs[oc],   0.f);
                    o0[cstride+8] = fmaxf(acc[mt][nt][3] + bs[oc+1], 0.f);
                }
            }
        }
    }
}

// =====================================================================
// conv4/conv5 (tf32): generic small conv, stride support — unchanged
// =====================================================================
template<int CIN, int KS, int STRIDE, int HIN, int WIN, int HOUT, int WOUT>
__global__ void __launch_bounds__(256) conv_tcS(
    const float* __restrict__ in, const float* __restrict__ w,
    const float* __restrict__ bias, float* __restrict__ out)
{
    constexpr int TIW = 15*STRIDE + KS;
    constexpr int KCH = 8*KS*KS;
    constexpr int KP  = KCH + 4;
    extern __shared__ uint32_t sm_u[];
    uint32_t* xs = sm_u;
    uint32_t* ws = xs + 8*TIW*TIW;
    int* lut = (int*)(ws + 16*KP);
    float* bs = (float*)(lut + KCH);

    const int tid = threadIdx.x, lane = tid & 31, wp = tid >> 5;
    const int b = blockIdx.z;
    const int iy0in = blockIdx.y*16*STRIDE, ix0in = blockIdx.x*16*STRIDE;

    for (int i = tid; i < KCH; i += 256) {
        int cl = i / (KS*KS), r = i - cl*(KS*KS);
        lut[i] = cl*(TIW*TIW) + (r/KS)*TIW + (r%KS);
    }
    if (tid < 16) bs[tid] = bias[tid];

    float acc[2][2][4];
#pragma unroll
    for (int m = 0; m < 2; m++)
#pragma unroll
        for (int n = 0; n < 2; n++)
#pragma unroll
            for (int q = 0; q < 4; q++) acc[m][n][q] = 0.f;

    const int gr = lane >> 2, gc = lane & 3;
    int mb[2];
#pragma unroll
    for (int i = 0; i < 2; i++)
        mb[i] = (STRIDE*(wp*2 + i))*TIW + STRIDE*gr;
    const int a1off = 8*STRIDE;

    for (int cc = 0; cc < CIN; cc += 8) {
        __syncthreads();
        for (int i = tid; i < 8*TIW*TIW; i += 256) {
            int cl = i / (TIW*TIW), r = i - cl*(TIW*TIW);
            int yy = r / TIW, xx = r - yy*TIW;
            int gy = iy0in + yy, gx = ix0in + xx;
            float v = 0.f;
            if (gy < HIN && gx < WIN)
                v = in[(((size_t)b*CIN + cc + cl)*HIN + gy)*WIN + gx];
            xs[i] = f2tf(v);
        }
        for (int i = tid; i < 16*KCH; i += 256) {
            int oc = i / KCH, kl = i - oc*KCH;
            int cl = kl / (KS*KS), kk = kl - cl*(KS*KS);
            ws[oc*KP + kl] = f2tf(w[((size_t)oc*CIN + cc + cl)*(KS*KS) + kk]);
        }
        __syncthreads();

        for (int k0 = 0; k0 < KCH; k0 += 8) {
            int o1 = lut[k0 + gc], o2 = lut[k0 + gc + 4];
            uint32_t bf0[2], bf1[2];
#pragma unroll
            for (int nt = 0; nt < 2; nt++) {
                const uint32_t* wp_ = &ws[(nt*8 + gr)*KP + k0];
                bf0[nt] = wp_[gc]; bf1[nt] = wp_[gc + 4];
            }
#pragma unroll
            for (int mt = 0; mt < 2; mt++) {
                uint32_t a0 = xs[mb[mt] + o1], a1 = xs[mb[mt] + a1off + o1];
                uint32_t a2 = xs[mb[mt] + o2], a3 = xs[mb[mt] + a1off + o2];
#pragma unroll
                for (int nt = 0; nt < 2; nt++)
                    mma8(acc[mt][nt], a0, a1, a2, a3, bf0[nt], bf1[nt]);
            }
        }
    }

    const size_t cstride = (size_t)HOUT*WOUT;
#pragma unroll
    for (int mt = 0; mt < 2; mt++) {
        int yp = blockIdx.y*16 + wp*2 + mt;
        int xp = blockIdx.x*16 + gr;
        if (yp < HOUT) {
#pragma unroll
            for (int nt = 0; nt < 2; nt++) {
                int oc = nt*8 + gc*2;
                float* o0 = out + (((size_t)b*16 + oc)*HOUT + yp)*WOUT + xp;
                if (xp < WOUT) {
                    o0[0]       = fmaxf(acc[mt][nt][0] + bs[oc],   0.f);
                    o0[cstride] = fmaxf(acc[mt][nt][1] + bs[oc+1], 0.f);
                }
                if (xp + 8 < WOUT) {
                    o0[8]         = fmaxf(acc[mt][nt][2] + bs[oc],   0.f);
                    o0[cstride+8] = fmaxf(acc[mt][nt][3] + bs[oc+1], 0.f);
                }
            }
        }
    }
}

// =====================================================================
// fc (tf32): partial GEMM — unchanged
// =====================================================================
__global__ void __launch_bounds__(256) fc_tc(
    const float* __restrict__ x, const float* __restrict__ w,
    float* __restrict__ part, int N, int K, int klen)
{
    __shared__ uint32_t as[32*68];
    __shared__ uint32_t bsm[128*68];

    const int tid = threadIdx.x, lane = tid & 31, wp = tid >> 5;
    const int n0 = blockIdx.x*128;
    const int kstart = blockIdx.y*klen;
    const int gr = lane >> 2, gc = lane & 3;
    const int nb = wp*16;

    float acc[2][2][4];
#pragma unroll
    for (int m = 0; m < 2; m++)
#pragma unroll
        for (int n = 0; n < 2; n++)
#pragma unroll
            for (int q = 0; q < 4; q++) acc[m][n][q] = 0.f;

    for (int kc = 0; kc < klen; kc += 64) {
        int cl = min(64, klen - kc);
        __syncthreads();
        for (int i = tid; i < 2048; i += 256) {
            int m = i >> 6, k = i & 63;
            float v = (k < cl) ? x[(size_t)m*K + kstart + kc + k] : 0.f;
            as[m*68 + k] = f2tf(v);
        }
        for (int i = tid; i < 8192; i += 256) {
            int n = i >> 6, k = i & 63;
            float v = (k < cl) ? w[(size_t)(n0 + n)*K + kstart + kc + k] : 0.f;
            bsm[n*68 + k] = f2tf(v);
        }
        __syncthreads();

#pragma unroll
        for (int k0 = 0; k0 < 64; k0 += 8) {
            uint32_t a0[2], a1[2], a2[2], a3[2];
#pragma unroll
            for (int mt = 0; mt < 2; mt++) {
                const uint32_t* ap = &as[(mt*16 + gr)*68 + k0];
                a0[mt] = ap[gc];        a2[mt] = ap[gc + 4];
                a1[mt] = ap[8*68 + gc]; a3[mt] = ap[8*68 + gc + 4];
            }
#pragma unroll
            for (int nt = 0; nt < 2; nt++) {
                const uint32_t* bp = &bsm[(nb + nt*8 + gr)*68 + k0];
                uint32_t b0 = bp[gc], b1 = bp[gc + 4];
#pragma unroll
                for (int mt = 0; mt < 2; mt++)
                    mma8(acc[mt][nt], a0[mt], a1[mt], a2[mt], a3[mt], b0, b1);
            }
        }
    }

    float* pr = part + (size_t)blockIdx.y*32*N;
#pragma unroll
    for (int mt = 0; mt < 2; mt++) {
#pragma unroll
        for (int nt = 0; nt < 2; nt++) {
            int n = n0 + nb + nt*8 + 2*gc;
            int m0 = mt*16 + gr;
            *(float2*)&pr[(size_t)m0*N + n]     = make_float2(acc[mt][nt][0], acc[mt][nt][1]);
            *(float2*)&pr[(size_t)(m0+8)*N + n] = make_float2(acc[mt][nt][2], acc[mt][nt][3]);
        }
    }
}

__global__ void fc_reduce(const float* __restrict__ part,
                          const float* __restrict__ bias,
                          float* __restrict__ out, int N, int KT, int do_relu)
{
    int i = blockIdx.x*256 + threadIdx.x;
    if (i >= 32*N) return;
    int n = i % N;
    float s = bias[n];
    for (int kt = 0; kt < KT; kt++) s += part[(size_t)kt*32*N + i];
    out[i] = do_relu ? fmaxf(s, 0.f) : s;
}

__global__ void __launch_bounds__(768) fc3_softmax(
    const float* __restrict__ x, const float* __restrict__ w,
    const float* __restrict__ bias, float* __restrict__ out)
{
    __shared__ float lg[24];
    const int b = blockIdx.x;
    const int tid = threadIdx.x;
    const int wo = tid >> 5, lane = tid & 31;

    const float* xr = x + (size_t)b*2048;
    const float* wr = w + (size_t)wo*2048;
    float s = 0.f;
    for (int k = lane; k < 2048; k += 32) s = fmaf(wr[k], xr[k], s);
#pragma unroll
    for (int off = 16; off; off >>= 1) s += __shfl_xor_sync(0xffffffffu, s, off);
    if (lane == 0) lg[wo] = s + bias[wo];
    __syncthreads();

    if (tid < 24) {
        int a = tid % 12;
        float z0 = lg[a], z1 = lg[12 + a];
        float m = fmaxf(z0, z1);
        float lse = m + logf(expf(z0 - m) + expf(z1 - m));
        out[b*24 + tid] = lg[tid] - lse;
    }
}

// =====================================================================
// launch
// =====================================================================
extern "C" void kernel_launch(void* const* d_in, const int* in_sizes, int n_in,
                              void* d_out, int out_size)
{
    const float* x        = (const float*)d_in[0];
    const float* conv1_w  = (const float*)d_in[1];
    const float* conv1_b  = (const float*)d_in[2];
    const float* rl_gamma = (const float*)d_in[3];
    const float* rl_beta  = (const float*)d_in[4];
    const float* rl_mean  = (const float*)d_in[5];
    const float* rl_var   = (const float*)d_in[6];
    const float* rl_cw    = (const float*)d_in[7];
    const float* rl_cb    = (const float*)d_in[8];
    const float* bn_gamma = (const float*)d_in[9];
    const float* bn_beta  = (const float*)d_in[10];
    const float* bn_mean  = (const float*)d_in[11];
    const float* bn_var   = (const float*)d_in[12];
    const float* conv2_w  = (const float*)d_in[13];
    const float* conv2_b  = (const float*)d_in[14];
    const float* conv3_w  = (const float*)d_in[15];
    const float* conv3_b  = (const float*)d_in[16];
    const float* conv4_w  = (const float*)d_in[17];
    const float* conv4_b  = (const float*)d_in[18];
    const float* conv5_w  = (const float*)d_in[19];
    const float* conv5_b  = (const float*)d_in[20];
    const float* fc1_w    = (const float*)d_in[21];
    const float* fc1_b    = (const float*)d_in[22];
    const float* fc2_w    = (const float*)d_in[23];
    const float* fc2_b    = (const float*)d_in[24];
    const float* fc3_w    = (const float*)d_in[25];
    const float* fc3_b    = (const float*)d_in[26];
    float* out = (float*)d_out;

    float *b1,*b2,*b3,*b4,*b5,*b6,*pt,*f1,*f2;
    cudaGetSymbolAddress((void**)&b1, g_buf1);
    cudaGetSymbolAddress((void**)&b2, g_buf2);
    cudaGetSymbolAddress((void**)&b3, g_buf3);
    cudaGetSymbolAddress((void**)&b4, g_buf4);
    cudaGetSymbolAddress((void**)&b5, g_buf5);
    cudaGetSymbolAddress((void**)&b6, g_buf6);
    cudaGetSymbolAddress((void**)&pt, g_part);
    cudaGetSymbolAddress((void**)&f1, g_fc1);
    cudaGetSymbolAddress((void**)&f2, g_fc2);

    // conv1_h: (4432 + 32*536)*2 + 32*4 = 43296 B
    const int c1_smem = (4432 + 32*C1_KP)*2 + 32*4;
    cudaFuncSetAttribute(conv1_h,
                         cudaFuncAttributeMaxDynamicSharedMemorySize, c1_smem);
    const int reg_smem = (15488 + 9216 + 288) * 4;
    cudaFuncSetAttribute(region_tc,
                         cudaFuncAttributeMaxDynamicSharedMemorySize, reg_smem);
    // conv_tc16h: (4240 + 16*520)*2 + 16*4 = 25184 B
    const int c2_smem = (4240 + 16*C2_KP)*2 + 16*4;
    cudaFuncSetAttribute(conv_tc16h<32,80,80,73,73>,
                         cudaFuncAttributeMaxDynamicSharedMemorySize, c2_smem);
    cudaFuncSetAttribute(conv_tc16h<16,73,73,66,66>,
                         cudaFuncAttributeMaxDynamicSharedMemorySize, c2_smem);
    const int c4_smem = (8*36*36 + 16*292 + 288 + 16) * 4;
    cudaFuncSetAttribute(conv_tcS<16,6,2,66,66,31,31>,
                         cudaFuncAttributeMaxDynamicSharedMemorySize, c4_smem);
    const int c5_smem = (8*20*20 + 16*204 + 200 + 16) * 4;
    cudaFuncSetAttribute(conv_tcS<16,5,1,31,31,27,27>,
                         cudaFuncAttributeMaxDynamicSharedMemorySize, c5_smem);

    // 1. conv1 (fp16 mma)
    conv1_h<<<dim3(5,10,BATCH), 256, c1_smem>>>(x, conv1_w, conv1_b, b1);

    // 2. region (tf32)
    region_tc<<<BATCH*64, 256, reg_smem>>>(
        b1, rl_gamma, rl_beta, rl_mean, rl_var, rl_cw, rl_cb,
        bn_gamma, bn_beta, bn_mean, bn_var, b2);

    // 3. conv2 (fp16 mma)
    conv_tc16h<32,80,80,73,73><<<dim3(5,5,BATCH), 256, c2_smem>>>(
        b2, conv2_w, conv2_b, b3);

    // 4. conv3 (fp16 mma)
    conv_tc16h<16,73,73,66,66><<<dim3(5,5,BATCH), 256, c2_smem>>>(
        b3, conv3_w, conv3_b, b4);

    // 5. conv4 (tf32)
    conv_tcS<16,6,2,66,66,31,31><<<dim3(2,2,BATCH), 256, c4_smem>>>(
        b4, conv4_w, conv4_b, b5);

    // 6. conv5 (tf32)
    conv_tcS<16,5,1,31,31,27,27><<<dim3(2,2,BATCH), 256, c5_smem>>>(
        b5, conv5_w, conv5_b, b6);

    // 7. fc1
    fc_tc<<<dim3(32,24), 256>>>(b6, fc1_w, pt, 4096, 11664, 486);
    fc_reduce<<<512, 256>>>(pt, fc1_b, f1, 4096, 24, 1);

    // 8. fc2
    fc_tc<<<dim3(16,16), 256>>>(f1, fc2_w, pt, 2048, 4096, 256);
    fc_reduce<<<256, 256>>>(pt, fc2_b, f2, 2048, 16, 1);

    // 9. fc3 + log_softmax
    fc3_softmax<<<BATCH, 768>>>(f2, fc3_w, fc3_b, out);
}

// round 10
// speedup vs baseline: 2.9893x; 1.0456x over previous
#include <cuda_runtime.h>
#include <cuda_fp16.h>
#include <cuda_bf16.h>
#include <math.h>
#include <stdint.h>

#define BATCH 32
#define EPS 1e-5f

__device__ __forceinline__ uint32_t f2tf(float f) {
    uint32_t r; asm("cvt.rna.tf32.f32 %0,%1;" : "=r"(r) : "f"(f)); return r;
}
__device__ __forceinline__ void mma8(float* c, uint32_t a0, uint32_t a1,
                                     uint32_t a2, uint32_t a3,
                                     uint32_t b0, uint32_t b1) {
    asm("mma.sync.aligned.m16n8k8.row.col.f32.tf32.tf32.f32 "
        "{%0,%1,%2,%3},{%4,%5,%6,%7},{%8,%9},{%0,%1,%2,%3};"
        : "+f"(c[0]), "+f"(c[1]), "+f"(c[2]), "+f"(c[3])
        : "r"(a0), "r"(a1), "r"(a2), "r"(a3), "r"(b0), "r"(b1));
}
__device__ __forceinline__ void mma16(float* c, uint32_t a0, uint32_t a1,
                                      uint32_t a2, uint32_t a3,
                                      uint32_t b0, uint32_t b1) {
    asm("mma.sync.aligned.m16n8k16.row.col.f32.f16.f16.f32 "
        "{%0,%1,%2,%3},{%4,%5,%6,%7},{%8,%9},{%0,%1,%2,%3};"
        : "+f"(c[0]), "+f"(c[1]), "+f"(c[2]), "+f"(c[3])
        : "r"(a0), "r"(a1), "r"(a2), "r"(a3), "r"(b0), "r"(b1));
}
__device__ __forceinline__ uint32_t s2u(const void* p) {
    return (uint32_t)__cvta_generic_to_shared(p);
}
__device__ __forceinline__ void ldsm4(uint32_t& r0, uint32_t& r1,
                                      uint32_t& r2, uint32_t& r3, uint32_t a) {
    asm volatile("ldmatrix.sync.aligned.m8n8.x4.shared.b16 {%0,%1,%2,%3},[%4];"
        : "=r"(r0), "=r"(r1), "=r"(r2), "=r"(r3) : "r"(a));
}

// ---------------- scratch ----------------
__device__ float g_buf1[BATCH*32*160*160];
__device__ float g_buf2[BATCH*32*80*80];
__device__ float g_buf3[BATCH*16*73*73];
__device__ float g_buf4[BATCH*16*66*66];
__device__ float g_buf5[BATCH*16*31*31];
__device__ float g_buf6[BATCH*16*27*27];
__device__ float g_part[24*32*4096];
__device__ float g_fc1[BATCH*4096];
__device__ float g_fc2[BATCH*2048];

// =====================================================================
// conv1 (fp16 mma + ldmatrix): [32,3,170,170] -> [32,32,160,160], 11x11
// xs0[26][42][4ic] + shifted copy xs1 (for odd-pixel row alignment).
// k' = kh*48 + kw*4 + ic (kw pad 12). 33 k16-steps.
// =====================================================================
#define C1_KP 536
#define C1_XSH 4432
__global__ void __launch_bounds__(256) conv1_h(
    const float* __restrict__ x, const float* __restrict__ w,
    const float* __restrict__ bias, float* __restrict__ out)
{
    extern __shared__ __half smh[];
    __half* xs0 = smh;                  // 4432
    __half* xs1 = smh + C1_XSH;         // 4432 (shifted by 4 halves)
    __half* ws  = smh + 2*C1_XSH;       // 32*536
    float* bs = (float*)(ws + 32*C1_KP);// 32

    const int tid = threadIdx.x, lane = tid & 31, wp = tid >> 5;
    const int b = blockIdx.z;
    const int iy0 = blockIdx.y*16, ix0 = blockIdx.x*32;
    const int gr = lane >> 2, gc = lane & 3;

    // stage input (ic innermost, ic pad 3->4); xs1[i] = xs0[i+4]
    if (tid < 4) xs1[4428 + tid] = __float2half_rn(0.f);
    for (int i = tid; i < C1_XSH; i += 256) {
        float v = 0.f;
        if (i < 4368) {
            int p = i >> 2, ic = i & 3;
            int yy = p / 42, xx = p - yy*42;
            if (ic < 3)
                v = x[(((size_t)b*3 + ic)*170 + iy0 + yy)*170 + ix0 + xx];
        }
        __half h = __float2half_rn(v);
        xs0[i] = h;
        if (i >= 4) xs1[i-4] = h;
    }
    for (int i = tid; i < 32*528; i += 256) {
        int oc = i / 528, kl = i - oc*528;
        int kh = kl / 48, r = kl - kh*48;
        int kw = r >> 2, ic = r & 3;
        float v = (ic < 3 && kw < 11) ? w[oc*363 + ic*121 + kh*11 + kw] : 0.f;
        ws[oc*C1_KP + kl] = __float2half_rn(v);
    }
    if (tid < 32) bs[tid] = bias[tid];
    __syncthreads();

    float acc[4][4][4];
#pragma unroll
    for (int m = 0; m < 4; m++)
#pragma unroll
        for (int n = 0; n < 4; n++)
#pragma unroll
            for (int q = 0; q < 4; q++) acc[m][n][q] = 0.f;

    const int arow = lane & 15;
    const int acol = (lane >> 4) * 8;
    const int boc  = (lane & 7) | ((lane >> 4) << 3);
    const int bk   = ((lane >> 3) & 1) * 8;
    const uint32_t xsb = s2u(xs0);
    uint32_t aaddr[4];
#pragma unroll
    for (int mt = 0; mt < 4; mt++) {
        int t = wp*4 + mt;
        int py = t >> 1, pxh = (t & 1)*16;
        int q = pxh + arow;
        int par = q & 1;
        aaddr[mt] = xsb + (((py*42 + q - par)*4 + acol)*2) + par*(C1_XSH*2);
    }
    const uint32_t baddr0 = s2u(ws) + (boc*C1_KP + bk)*2;
    const uint32_t baddr1 = baddr0 + 16*C1_KP*2;

    for (int j = 0; j < 33; j++) {
        int kh = j / 3, sub = j - kh*3;
        uint32_t aoff = (kh*42 + sub*4)*8;
        uint32_t c0,c1,c2,c3, d0,d1,d2,d3;
        ldsm4(c0,c1,c2,c3, baddr0 + j*32);
        ldsm4(d0,d1,d2,d3, baddr1 + j*32);
#pragma unroll
        for (int mt = 0; mt < 4; mt++) {
            uint32_t a0,a1,a2,a3;
            ldsm4(a0,a1,a2,a3, aaddr[mt] + aoff);
            mma16(acc[mt][0], a0,a1,a2,a3, c0,c1);
            mma16(acc[mt][1], a0,a1,a2,a3, c2,c3);
            mma16(acc[mt][2], a0,a1,a2,a3, d0,d1);
            mma16(acc[mt][3], a0,a1,a2,a3, d2,d3);
        }
    }
#pragma unroll
    for (int mt = 0; mt < 4; mt++) {
        int t = wp*4 + mt;
        int yp = iy0 + (t >> 1), xp = ix0 + (t & 1)*16 + gr;
#pragma unroll
        for (int nt = 0; nt < 4; nt++) {
            int oc = nt*8 + gc*2;
            float* o0 = out + (((size_t)b*32 + oc)*160 + yp)*160 + xp;
            o0[0]     = acc[mt][nt][0] + bs[oc];
            o0[25600] = acc[mt][nt][1] + bs[oc+1];
            o0[8]     = acc[mt][nt][2] + bs[oc];
            o0[25608] = acc[mt][nt][3] + bs[oc+1];
        }
    }
}

// =====================================================================
// region (fp16 mma + ldmatrix): per patch GEMM M=400, N=32, K'=384
// act: 4 ic8-chunks, [22][22][ic8] halves (+16 pad/chunk); kx pad 3->4.
// =====================================================================
#define RG_CH 3888          // halves per chunk (484*8 + 16)
#define RG_KP 392           // K' 384 + 8 pad
__global__ void __launch_bounds__(256) region_h(
    const float* __restrict__ in,
    const float* __restrict__ rl_gamma, const float* __restrict__ rl_beta,
    const float* __restrict__ rl_mean,  const float* __restrict__ rl_var,
    const float* __restrict__ rl_cw,    const float* __restrict__ rl_cb,
    const float* __restrict__ bn_g, const float* __restrict__ bn_b,
    const float* __restrict__ bn_m, const float* __restrict__ bn_v,
    float* __restrict__ out)
{
    extern __shared__ __half smh[];
    __half* act = smh;                  // 4*3888 = 15552
    __half* ws  = smh + 4*RG_CH;        // 32*392 = 12544
    __shared__ float sc[32], sh[32], s2[32], t2[32], cb[32];

    const int blk = blockIdx.x;
    const int b = blk >> 6;
    const int patch = blk & 63;
    const int gi = patch >> 3, gj = patch & 7;
    const int kidx = gj*(gi+1);
    const int tid = threadIdx.x, lane = tid & 31, wp = tid >> 5;
    const int gr = lane >> 2, gc = lane & 3;

    if (tid < 32) {
        float g = rl_gamma[kidx*32+tid];
        float s = g * rsqrtf(rl_var[kidx*32+tid] + EPS);
        sc[tid] = s;
        sh[tid] = rl_beta[kidx*32+tid] - rl_mean[kidx*32+tid]*s;
        float ss = bn_g[tid] * rsqrtf(bn_v[tid] + EPS);
        s2[tid] = ss;
        t2[tid] = bn_b[tid] - bn_m[tid]*ss;
        cb[tid] = rl_cb[kidx*32+tid];
    }
    {   // zero act (incl pads)
        uint32_t* az = (uint32_t*)act;
        for (int i = tid; i < 2*RG_CH; i += 256) az[i] = 0u;
    }
    __syncthreads();

    const float* inb = in + (size_t)b*32*160*160;
    for (int i = tid; i < 32*400; i += 256) {
        int ic = i / 400, r = i - ic*400;
        int y = r / 20, xx = r - y*20;
        float v = inb[((size_t)ic*160 + gi*20 + y)*160 + gj*20 + xx];
        float a = fmaxf(fmaf(v, sc[ic], sh[ic]), 0.f);
        act[(ic >> 3)*RG_CH + ((y+1)*22 + (xx+1))*8 + (ic & 7)] = __float2half_rn(a);
    }
    // weights: k' = j*16 + kxl*8 + ic8;  j = c*6 + ky*2 + h; kx = h*2+kxl
    for (int i = tid; i < 32*384; i += 256) {
        int oc = i / 384, kp = i - oc*384;
        int j = kp >> 4, loc = kp & 15;
        int kxl = loc >> 3, ic8 = loc & 7;
        int c = j / 6, r = j - c*6;
        int ky = r >> 1, kx = (r & 1)*2 + kxl;
        float v = (kx < 3) ?
            rl_cw[(size_t)kidx*9216 + oc*288 + (c*8 + ic8)*9 + ky*3 + kx] : 0.f;
        ws[oc*RG_KP + kp] = __float2half_rn(v);
    }
    __syncthreads();

    const int ntiles = (wp == 0) ? 4 : 3;
    const int arow = lane & 15;
    const int acol = (lane >> 4) * 8;
    const int boc  = (lane & 7) | ((lane >> 4) << 3);
    const int bk   = ((lane >> 3) & 1) * 8;
    uint32_t aaddr[4];
#pragma unroll
    for (int ti = 0; ti < 4; ti++) {
        int t = wp + 8*ti;
        int p = (t < 25) ? t*16 + arow : arow;
        int pixbase = (p/20)*22 + (p%20);
        aaddr[ti] = s2u(act) + (pixbase*8 + acol)*2;
    }
    const uint32_t baddr0 = s2u(ws) + (boc*RG_KP + bk)*2;
    const uint32_t baddr1 = baddr0 + 16*RG_KP*2;

    float acc[4][4][4];
#pragma unroll
    for (int m = 0; m < 4; m++)
#pragma unroll
        for (int n = 0; n < 4; n++)
#pragma unroll
            for (int q = 0; q < 4; q++) acc[m][n][q] = 0.f;

    for (int j = 0; j < 24; j++) {
        int c = j / 6, r = j - c*6;
        int ky = r >> 1, kx0 = (r & 1)*2;
        uint32_t aoff = (c*RG_CH + (ky*22 + kx0)*8)*2;
        uint32_t b0,b1,b2,b3, c0,c1,c2,c3;
        ldsm4(b0,b1,b2,b3, baddr0 + j*32);
        ldsm4(c0,c1,c2,c3, baddr1 + j*32);
#pragma unroll
        for (int ti = 0; ti < 4; ti++) {
            if (ti >= ntiles) break;
            uint32_t a0,a1,a2,a3;
            ldsm4(a0,a1,a2,a3, aaddr[ti] + aoff);
            mma16(acc[ti][0], a0,a1,a2,a3, b0,b1);
            mma16(acc[ti][1], a0,a1,a2,a3, b2,b3);
            mma16(acc[ti][2], a0,a1,a2,a3, c0,c1);
            mma16(acc[ti][3], a0,a1,a2,a3, c2,c3);
        }
    }
    __syncthreads();

    float* res = (float*)smh;          // 12800 floats, aliases act+ws
#pragma unroll
    for (int ti = 0; ti < 4; ti++) {
        if (ti >= ntiles) break;
        int t = wp + 8*ti;
        int p0 = t*16 + gr, p1 = p0 + 8;
#pragma unroll
        for (int nt = 0; nt < 4; nt++) {
            int oc0 = nt*8 + 2*gc;
            res[oc0*400 + p0]     = acc[ti][nt][0];
            res[(oc0+1)*400 + p0] = acc[ti][nt][1];
            res[oc0*400 + p1]     = acc[ti][nt][2];
            res[(oc0+1)*400 + p1] = acc[ti][nt][3];
        }
    }
    __syncthreads();

    for (int item = tid; item < 3200; item += 256) {
        int oc = item / 100, pos = item - oc*100;
        int py = pos / 10, px = pos - py*10;
        float bv = cb[oc];
        const float* xrb = inb + ((size_t)oc*160 + gi*20 + 2*py)*160 + gj*20 + 2*px;
        int p = (2*py)*20 + 2*px;
        float v0 = fmaxf(res[oc*400 + p]      + bv + xrb[0],   0.f);
        float v1 = fmaxf(res[oc*400 + p + 1]  + bv + xrb[1],   0.f);
        float v2 = fmaxf(res[oc*400 + p + 20] + bv + xrb[160], 0.f);
        float v3 = fmaxf(res[oc*400 + p + 21] + bv + xrb[161], 0.f);
        float mx = fmaxf(fmaxf(v0, v1), fmaxf(v2, v3));
        out[(((size_t)b*32 + oc)*80 + gi*10 + py)*80 + gj*10 + px] =
            fmaf(mx, s2[oc], t2[oc]);
    }
}

// =====================================================================
// conv2/conv3 (fp16 mma + ldmatrix): 8x8, COUT=16, 16x16 tile
// =====================================================================
#define C2_KP 520
template<int CIN, int HIN, int WIN, int HOUT, int WOUT>
__global__ void __launch_bounds__(256) conv_tc16h(
    const float* __restrict__ in, const float* __restrict__ w,
    const float* __restrict__ bias, float* __restrict__ out)
{
    extern __shared__ __half smh[];
    __half* xs = smh;                   // 4240
    __half* ws = smh + 4240;            // 16*520
    float* bs = (float*)(ws + 16*C2_KP);

    const int tid = threadIdx.x, lane = tid & 31, wp = tid >> 5;
    const int b = blockIdx.z;
    const int iy0 = blockIdx.y*16, ix0 = blockIdx.x*16;
    const int gr = lane >> 2, gc = lane & 3;

    if (tid < 16) bs[tid] = bias[tid];

    float acc[2][2][4];
#pragma unroll
    for (int m = 0; m < 2; m++)
#pragma unroll
        for (int n = 0; n < 2; n++)
#pragma unroll
            for (int q = 0; q < 4; q++) acc[m][n][q] = 0.f;

    const int arow = lane & 15;
    const int acol = (lane >> 4) * 8;
    const int boc  = (lane & 7) | ((lane >> 4) << 3);
    const int bk   = ((lane >> 3) & 1) * 8;
    uint32_t aaddr[2];
#pragma unroll
    for (int mt = 0; mt < 2; mt++)
        aaddr[mt] = s2u(xs) + (((wp*2 + mt)*23 + arow)*8 + acol)*2;
    const uint32_t baddr = s2u(ws) + (boc*C2_KP + bk)*2;

    for (int cc = 0; cc < CIN; cc += 8) {
        __syncthreads();
        for (int i = tid; i < 4232; i += 256) {
            int p = i >> 3, ic = i & 7;
            int yy = p / 23, xx = p - yy*23;
            int gy = iy0 + yy, gx = ix0 + xx;
            float v = 0.f;
            if (gy < HIN && gx < WIN)
                v = in[(((size_t)b*CIN + cc + ic)*HIN + gy)*WIN + gx];
            xs[i] = __float2half_rn(v);
        }
        for (int i = tid; i < 16*512; i += 256) {
            int oc = i >> 9, kl = i & 511;
            int kh = kl >> 6, kw = (kl >> 3) & 7, ic = kl & 7;
            ws[oc*C2_KP + kl] = __float2half_rn(
                w[((size_t)oc*CIN + cc + ic)*64 + kh*8 + kw]);
        }
        __syncthreads();

        for (int j = 0; j < 32; j++) {
            int kh = j >> 2, kw0 = (j & 3)*2;
            uint32_t aoff = (kh*23 + kw0)*16;
            uint32_t b0,b1,b2,b3;
            ldsm4(b0,b1,b2,b3, baddr + j*32);
#pragma unroll
            for (int mt = 0; mt < 2; mt++) {
                uint32_t a0,a1,a2,a3;
                ldsm4(a0,a1,a2,a3, aaddr[mt] + aoff);
                mma16(acc[mt][0], a0,a1,a2,a3, b0,b1);
                mma16(acc[mt][1], a0,a1,a2,a3, b2,b3);
            }
        }
    }

    const size_t cstride = (size_t)HOUT*WOUT;
#pragma unroll
    for (int mt = 0; mt < 2; mt++) {
        int yp = iy0 + wp*2 + mt;
        int xp = ix0 + gr;
        if (yp < HOUT) {
#pragma unroll
            for (int nt = 0; nt < 2; nt++) {
                int oc = nt*8 + gc*2;
                float* o0 = out + (((size_t)b*16 + oc)*HOUT + yp)*WOUT + xp;
                if (xp < WOUT) {
                    o0[0]       = fmaxf(acc[mt][nt][0] + bs[oc],   0.f);
                    o0[cstride] = fmaxf(acc[mt][nt][1] + bs[oc+1], 0.f);
                }
                if (xp + 8 < WOUT) {
                    o0[8]         = fmaxf(acc[mt][nt][2] + bs[oc],   0.f);
                    o0[cstride+8] = fmaxf(acc[mt][nt][3] + bs[oc+1], 0.f);
                }
            }
        }
    }
}

// =====================================================================
// conv4/conv5 (tf32) — unchanged
// =====================================================================
template<int CIN, int KS, int STRIDE, int HIN, int WIN, int HOUT, int WOUT>
__global__ void __launch_bounds__(256) conv_tcS(
    const float* __restrict__ in, const float* __restrict__ w,
    const float* __restrict__ bias, float* __restrict__ out)
{
    constexpr int TIW = 15*STRIDE + KS;
    constexpr int KCH = 8*KS*KS;
    constexpr int KP  = KCH + 4;
    extern __shared__ uint32_t sm_u[];
    uint32_t* xs = sm_u;
    uint32_t* ws = xs + 8*TIW*TIW;
    int* lut = (int*)(ws + 16*KP);
    float* bs = (float*)(lut + KCH);

    const int tid = threadIdx.x, lane = tid & 31, wp = tid >> 5;
    const int b = blockIdx.z;
    const int iy0in = blockIdx.y*16*STRIDE, ix0in = blockIdx.x*16*STRIDE;

    for (int i = tid; i < KCH; i += 256) {
        int cl = i / (KS*KS), r = i - cl*(KS*KS);
        lut[i] = cl*(TIW*TIW) + (r/KS)*TIW + (r%KS);
    }
    if (tid < 16) bs[tid] = bias[tid];

    float acc[2][2][4];
#pragma unroll
    for (int m = 0; m < 2; m++)
#pragma unroll
        for (int n = 0; n < 2; n++)
#pragma unroll
            for (int q = 0; q < 4; q++) acc[m][n][q] = 0.f;

    const int gr = lane >> 2, gc = lane & 3;
    int mb[2];
#pragma unroll
    for (int i = 0; i < 2; i++)
        mb[i] = (STRIDE*(wp*2 + i))*TIW + STRIDE*gr;
    const int a1off = 8*STRIDE;

    for (int cc = 0; cc < CIN; cc += 8) {
        __syncthreads();
        for (int i = tid; i < 8*TIW*TIW; i += 256) {
            int cl = i / (TIW*TIW), r = i - cl*(TIW*TIW);
            int yy = r / TIW, xx = r - yy*TIW;
            int gy = iy0in + yy, gx = ix0in + xx;
            float v = 0.f;
            if (gy < HIN && gx < WIN)
                v = in[(((size_t)b*CIN + cc + cl)*HIN + gy)*WIN + gx];
            xs[i] = f2tf(v);
        }
        for (int i = tid; i < 16*KCH; i += 256) {
            int oc = i / KCH, kl = i - oc*KCH;
            int cl = kl / (KS*KS), kk = kl - cl*(KS*KS);
            ws[oc*KP + kl] = f2tf(w[((size_t)oc*CIN + cc + cl)*(KS*KS) + kk]);
        }
        __syncthreads();

        for (int k0 = 0; k0 < KCH; k0 += 8) {
            int o1 = lut[k0 + gc], o2 = lut[k0 + gc + 4];
            uint32_t bf0[2], bf1[2];
#pragma unroll
            for (int nt = 0; nt < 2; nt++) {
                const uint32_t* wp_ = &ws[(nt*8 + gr)*KP + k0];
                bf0[nt] = wp_[gc]; bf1[nt] = wp_[gc + 4];
            }
#pragma unroll
            for (int mt = 0; mt < 2; mt++) {
                uint32_t a0 = xs[mb[mt] + o1], a1 = xs[mb[mt] + a1off + o1];
                uint32_t a2 = xs[mb[mt] + o2], a3 = xs[mb[mt] + a1off + o2];
#pragma unroll
                for (int nt = 0; nt < 2; nt++)
                    mma8(acc[mt][nt], a0, a1, a2, a3, bf0[nt], bf1[nt]);
            }
        }
    }

    const size_t cstride = (size_t)HOUT*WOUT;
#pragma unroll
    for (int mt = 0; mt < 2; mt++) {
        int yp = blockIdx.y*16 + wp*2 + mt;
        int xp = blockIdx.x*16 + gr;
        if (yp < HOUT) {
#pragma unroll
            for (int nt = 0; nt < 2; nt++) {
                int oc = nt*8 + gc*2;
                float* o0 = out + (((size_t)b*16 + oc)*HOUT + yp)*WOUT + xp;
                if (xp < WOUT) {
                    o0[0]       = fmaxf(acc[mt][nt][0] + bs[oc],   0.f);
                    o0[cstride] = fmaxf(acc[mt][nt][1] + bs[oc+1], 0.f);
                }
                if (xp + 8 < WOUT) {
                    o0[8]         = fmaxf(acc[mt][nt][2] + bs[oc],   0.f);
                    o0[cstride+8] = fmaxf(acc[mt][nt][3] + bs[oc+1], 0.f);
                }
            }
        }
    }
}

// =====================================================================
// fc (tf32) — unchanged
// =====================================================================
__global__ void __launch_bounds__(256) fc_tc(
    const float* __restrict__ x, const float* __restrict__ w,
    float* __restrict__ part, int N, int K, int klen)
{
    __shared__ uint32_t as[32*68];
    __shared__ uint32_t bsm[128*68];

    const int tid = threadIdx.x, lane = tid & 31, wp = tid >> 5;
    const int n0 = blockIdx.x*128;
    const int kstart = blockIdx.y*klen;
    const int gr = lane >> 2, gc = lane & 3;
    const int nb = wp*16;

    float acc[2][2][4];
#pragma unroll
    for (int m = 0; m < 2; m++)
#pragma unroll
        for (int n = 0; n < 2; n++)
#pragma unroll
            for (int q = 0; q < 4; q++) acc[m][n][q] = 0.f;

    for (int kc = 0; kc < klen; kc += 64) {
        int cl = min(64, klen - kc);
        __syncthreads();
        for (int i = tid; i < 2048; i += 256) {
            int m = i >> 6, k = i & 63;
            float v = (k < cl) ? x[(size_t)m*K + kstart + kc + k] : 0.f;
            as[m*68 + k] = f2tf(v);
        }
        for (int i = tid; i < 8192; i += 256) {
            int n = i >> 6, k = i & 63;
            float v = (k < cl) ? w[(size_t)(n0 + n)*K + kstart + kc + k] : 0.f;
            bsm[n*68 + k] = f2tf(v);
        }
        __syncthreads();

#pragma unroll
        for (int k0 = 0; k0 < 64; k0 += 8) {
            uint32_t a0[2], a1[2], a2[2], a3[2];
#pragma unroll
            for (int mt = 0; mt < 2; mt++) {
                const uint32_t* ap = &as[(mt*16 + gr)*68 + k0];
                a0[mt] = ap[gc];        a2[mt] = ap[gc + 4];
                a1[mt] = ap[8*68 + gc]; a3[mt] = ap[8*68 + gc + 4];
            }
#pragma unroll
            for (int nt = 0; nt < 2; nt++) {
                const uint32_t* bp = &bsm[(nb + nt*8 + gr)*68 + k0];
                uint32_t b0 = bp[gc], b1 = bp[gc + 4];
#pragma unroll
                for (int mt = 0; mt < 2; mt++)
                    mma8(acc[mt][nt], a0[mt], a1[mt], a2[mt], a3[mt], b0, b1);
            }
        }
    }

    float* pr = part + (size_t)blockIdx.y*32*N;
#pragma unroll
    for (int mt = 0; mt < 2; mt++) {
#pragma unroll
        for (int nt = 0; nt < 2; nt++) {
            int n = n0 + nb + nt*8 + 2*gc;
            int m0 = mt*16 + gr;
            *(float2*)&pr[(size_t)m0*N + n]     = make_float2(acc[mt][nt][0], acc[mt][nt][1]);
            *(float2*)&pr[(size_t)(m0+8)*N + n] = make_float2(acc[mt][nt][2], acc[mt][nt][3]);
        }
    }
}

__global__ void fc_reduce(const float* __restrict__ part,
                          const float* __restrict__ bias,
                          float* __restrict__ out, int N, int KT, int do_relu)
{
    int i = blockIdx.x*256 + threadIdx.x;
    if (i >= 32*N) return;
    int n = i % N;
    float s = bias[n];
    for (int kt = 0; kt < KT; kt++) s += part[(size_t)kt*32*N + i];
    out[i] = do_relu ? fmaxf(s, 0.f) : s;
}

__global__ void __launch_bounds__(768) fc3_softmax(
    const float* __restrict__ x, const float* __restrict__ w,
    const float* __restrict__ bias, float* __restrict__ out)
{
    __shared__ float lg[24];
    const int b = blockIdx.x;
    const int tid = threadIdx.x;
    const int wo = tid >> 5, lane = tid & 31;

    const float* xr = x + (size_t)b*2048;
    const float* wr = w + (size_t)wo*2048;
    float s = 0.f;
    for (int k = lane; k < 2048; k += 32) s = fmaf(wr[k], xr[k], s);
#pragma unroll
    for (int off = 16; off; off >>= 1) s += __shfl_xor_sync(0xffffffffu, s, off);
    if (lane == 0) lg[wo] = s + bias[wo];
    __syncthreads();

    if (tid < 24) {
        int a = tid % 12;
        float z0 = lg[a], z1 = lg[12 + a];
        float m = fmaxf(z0, z1);
        float lse = m + logf(expf(z0 - m) + expf(z1 - m));
        out[b*24 + tid] = lg[tid] - lse;
    }
}

// =====================================================================
// launch
// =====================================================================
extern "C" void kernel_launch(void* const* d_in, const int* in_sizes, int n_in,
                              void* d_out, int out_size)
{
    const float* x        = (const float*)d_in[0];
    const float* conv1_w  = (const float*)d_in[1];
    const float* conv1_b  = (const float*)d_in[2];
    const float* rl_gamma = (const float*)d_in[3];
    const float* rl_beta  = (const float*)d_in[4];
    const float* rl_mean  = (const float*)d_in[5];
    const float* rl_var   = (const float*)d_in[6];
    const float* rl_cw    = (const float*)d_in[7];
    const float* rl_cb    = (const float*)d_in[8];
    const float* bn_gamma = (const float*)d_in[9];
    const float* bn_beta  = (const float*)d_in[10];
    const float* bn_mean  = (const float*)d_in[11];
    const float* bn_var   = (const float*)d_in[12];
    const float* conv2_w  = (const float*)d_in[13];
    const float* conv2_b  = (const float*)d_in[14];
    const float* conv3_w  = (const float*)d_in[15];
    const float* conv3_b  = (const float*)d_in[16];
    const float* conv4_w  = (const float*)d_in[17];
    const float* conv4_b  = (const float*)d_in[18];
    const float* conv5_w  = (const float*)d_in[19];
    const float* conv5_b  = (const float*)d_in[20];
    const float* fc1_w    = (const float*)d_in[21];
    const float* fc1_b    = (const float*)d_in[22];
    const float* fc2_w    = (const float*)d_in[23];
    const float* fc2_b    = (const float*)d_in[24];
    const float* fc3_w    = (const float*)d_in[25];
    const float* fc3_b    = (const float*)d_in[26];
    float* out = (float*)d_out;

    float *b1,*b2,*b3,*b4,*b5,*b6,*pt,*f1,*f2;
    cudaGetSymbolAddress((void**)&b1, g_buf1);
    cudaGetSymbolAddress((void**)&b2, g_buf2);
    cudaGetSymbolAddress((void**)&b3, g_buf3);
    cudaGetSymbolAddress((void**)&b4, g_buf4);
    cudaGetSymbolAddress((void**)&b5, g_buf5);
    cudaGetSymbolAddress((void**)&b6, g_buf6);
    cudaGetSymbolAddress((void**)&pt, g_part);
    cudaGetSymbolAddress((void**)&f1, g_fc1);
    cudaGetSymbolAddress((void**)&f2, g_fc2);

    // conv1_h: (2*4432 + 32*536)*2 + 128 = 52160 B
    const int c1_smem = (2*C1_XSH + 32*C1_KP)*2 + 32*4;
    cudaFuncSetAttribute(conv1_h,
                         cudaFuncAttributeMaxDynamicSharedMemorySize, c1_smem);
    // region_h: (4*3888 + 32*392)*2 = 56192 B
    const int reg_smem = (4*RG_CH + 32*RG_KP)*2;
    cudaFuncSetAttribute(region_h,
                         cudaFuncAttributeMaxDynamicSharedMemorySize, reg_smem);
    const int c2_smem = (4240 + 16*C2_KP)*2 + 16*4;
    cudaFuncSetAttribute(conv_tc16h<32,80,80,73,73>,
                         cudaFuncAttributeMaxDynamicSharedMemorySize, c2_smem);
    cudaFuncSetAttribute(conv_tc16h<16,73,73,66,66>,
                         cudaFuncAttributeMaxDynamicSharedMemorySize, c2_smem);
    const int c4_smem = (8*36*36 + 16*292 + 288 + 16) * 4;
    cudaFuncSetAttribute(conv_tcS<16,6,2,66,66,31,31>,
                         cudaFuncAttributeMaxDynamicSharedMemorySize, c4_smem);
    const int c5_smem = (8*20*20 + 16*204 + 200 + 16) * 4;
    cudaFuncSetAttribute(conv_tcS<16,5,1,31,31,27,27>,
                         cudaFuncAttributeMaxDynamicSharedMemorySize, c5_smem);

    // 1. conv1 (fp16 + ldmatrix)
    conv1_h<<<dim3(5,10,BATCH), 256, c1_smem>>>(x, conv1_w, conv1_b, b1);

    // 2. region (fp16 + ldmatrix)
    region_h<<<BATCH*64, 256, reg_smem>>>(
        b1, rl_gamma, rl_beta, rl_mean, rl_var, rl_cw, rl_cb,
        bn_gamma, bn_beta, bn_mean, bn_var, b2);

    // 3. conv2 (fp16 + ldmatrix)
    conv_tc16h<32,80,80,73,73><<<dim3(5,5,BATCH), 256, c2_smem>>>(
        b2, conv2_w, conv2_b, b3);

    // 4. conv3 (fp16 + ldmatrix)
    conv_tc16h<16,73,73,66,66><<<dim3(5,5,BATCH), 256, c2_smem>>>(
        b3, conv3_w, conv3_b, b4);

    // 5. conv4 (tf32)
    conv_tcS<16,6,2,66,66,31,31><<<dim3(2,2,BATCH), 256, c4_smem>>>(
        b4, conv4_w, conv4_b, b5);

    // 6. conv5 (tf32)
    conv_tcS<16,5,1,31,31,27,27><<<dim3(2,2,BATCH), 256, c5_smem>>>(
        b5, conv5_w, conv5_b, b6);

    // 7. fc1
    fc_tc<<<dim3(32,24), 256>>>(b6, fc1_w, pt, 4096, 11664, 486);
    fc_reduce<<<512, 256>>>(pt, fc1_b, f1, 4096, 24, 1);

    // 8. fc2
    fc_tc<<<dim3(16,16), 256>>>(f1, fc2_w, pt, 2048, 4096, 256);
    fc_reduce<<<256, 256>>>(pt, fc2_b, f2, 2048, 16, 1);

    // 9. fc3 + log_softmax
    fc3_softmax<<<BATCH, 768>>>(f2, fc3_w, fc3_b, out);
}